// round 2
// baseline (speedup 1.0000x reference)
#include <cuda_runtime.h>
#include <math.h>
#include <stdint.h>
#include <stddef.h>

// ---------------- problem constants ----------------
constexpr int CB  = 2;
constexpr int CS  = 256;
constexpr int CD  = 1024;
constexpr int CH  = 8;
constexpr int CHD = 128;
constexpr int CL  = 16;
constexpr int CFF = 2048;
constexpr int CV  = 50257;
constexpr int CT  = CS * CB;   // 512 tokens, row r = s*CB + b
constexpr float ATT_SCALE = 0.08838834764831845f;  // 128^-0.5

// ---------------- static device scratch ----------------
__device__ float g_LB[(size_t)(CL + 1) * CT * CD];   // slot-major sources; slot0 = live x
__device__ float g_k [(size_t)CL * CT * CD];
__device__ float g_v [(size_t)CL * CT * CD];
__device__ float g_q [CT * CD];
__device__ float g_sc[(size_t)CL * 16 * CS * CS];    // scores [z=slot*16+bh][q][k]
__device__ float g_ob[(size_t)CL * 16 * CS * CHD];   // per-slot attn out
__device__ float g_comb[CT * CD];
__device__ float g_att [CT * CD];
__device__ float g_xa  [CT * CD];                    // x after LN1
__device__ float g_cur [CT * CD];
__device__ float g_sp  [CT * CD];
__device__ float g_ffh [CT * CFF];
__device__ float g_ffo [CT * CD];
__device__ float g_w   [CL + 1];                     // layer-mix softmax weights

// =======================================================================
// Generic SGEMM core: 128x128 block, K-tile 16, 256 threads, 8x8 microtile.
// A is MxK row-major (lda). B: TRANSB ? NxK row-major (ldb) : KxN row-major.
// C = alpha * A*B (+bias) with optional relu and row-permute (logits transpose).
// Requirements: M % 128 == 0, K % 16 == 0, A/B(transb) float4-aligned rows.
// N may be ragged (scalar B path + guarded stores).
// =======================================================================
template<bool TRANSB>
__device__ __forceinline__ void gemm_core(
    const float* __restrict__ A, const float* __restrict__ B,
    const float* __restrict__ bias, float* __restrict__ C,
    int N, int K, int lda, int ldb, int ldc,
    float alpha, int relu, int perm)
{
  __shared__ float As[16][136];
  __shared__ float Bs[16][136];

  const int t  = threadIdx.x;
  const int m0 = blockIdx.y * 128;
  const int n0 = blockIdx.x * 128;
  const int tm = t >> 4, tn = t & 15;

  const int lr = t >> 2;            // 0..63 : row for A / transposed-B loads
  const int lk = (t & 3) << 2;      // 0,4,8,12
  const int kr = t >> 5;            // 0..7  : k-row for normal-B loads
  const int n4 = (t & 31) << 2;     // 0..124

  const bool vecB = (!TRANSB) && ((ldb & 3) == 0) && (n0 + 128 <= N);

  float acc[8][8];
#pragma unroll
  for (int i = 0; i < 8; i++)
#pragma unroll
    for (int j = 0; j < 8; j++) acc[i][j] = 0.f;

  const int ktiles = K >> 4;
  for (int kt = 0; kt < ktiles; kt++) {
    // ---- load A tile (transposed into As[k][m]) ----
    {
      const float* pa = A + (size_t)(m0 + lr) * lda + kt * 16 + lk;
      float4 a0 = *(const float4*)pa;
      float4 a1 = *(const float4*)(pa + (size_t)64 * lda);
      As[lk + 0][lr] = a0.x; As[lk + 1][lr] = a0.y;
      As[lk + 2][lr] = a0.z; As[lk + 3][lr] = a0.w;
      As[lk + 0][lr + 64] = a1.x; As[lk + 1][lr + 64] = a1.y;
      As[lk + 2][lr + 64] = a1.z; As[lk + 3][lr + 64] = a1.w;
    }
    // ---- load B tile into Bs[k][n] ----
    if (TRANSB) {
      const float* pb = B + (size_t)(n0 + lr) * ldb + kt * 16 + lk;
      float4 b0 = *(const float4*)pb;
      float4 b1 = *(const float4*)(pb + (size_t)64 * ldb);
      Bs[lk + 0][lr] = b0.x; Bs[lk + 1][lr] = b0.y;
      Bs[lk + 2][lr] = b0.z; Bs[lk + 3][lr] = b0.w;
      Bs[lk + 0][lr + 64] = b1.x; Bs[lk + 1][lr + 64] = b1.y;
      Bs[lk + 2][lr + 64] = b1.z; Bs[lk + 3][lr + 64] = b1.w;
    } else if (vecB) {
      const float* pb = B + (size_t)(kt * 16 + kr) * ldb + n0 + n4;
      *(float4*)&Bs[kr][n4]     = *(const float4*)pb;
      *(float4*)&Bs[kr + 8][n4] = *(const float4*)(pb + (size_t)8 * ldb);
    } else {
      const float* pb  = B + (size_t)(kt * 16 + kr) * ldb + n0;
      const float* pb2 = pb + (size_t)8 * ldb;
#pragma unroll
      for (int u = 0; u < 4; u++) {
        int col = n4 + u;
        bool ok = (n0 + col) < N;
        Bs[kr][col]     = ok ? pb[col]  : 0.f;
        Bs[kr + 8][col] = ok ? pb2[col] : 0.f;
      }
    }
    __syncthreads();

    // ---- compute ----
#pragma unroll
    for (int k = 0; k < 16; k++) {
      float a[8], b[8];
      float4 t0 = *(const float4*)&As[k][tm * 8];
      float4 t1 = *(const float4*)&As[k][tm * 8 + 4];
      float4 t2 = *(const float4*)&Bs[k][tn * 8];
      float4 t3 = *(const float4*)&Bs[k][tn * 8 + 4];
      a[0]=t0.x; a[1]=t0.y; a[2]=t0.z; a[3]=t0.w;
      a[4]=t1.x; a[5]=t1.y; a[6]=t1.z; a[7]=t1.w;
      b[0]=t2.x; b[1]=t2.y; b[2]=t2.z; b[3]=t2.w;
      b[4]=t3.x; b[5]=t3.y; b[6]=t3.z; b[7]=t3.w;
#pragma unroll
      for (int i = 0; i < 8; i++)
#pragma unroll
        for (int j = 0; j < 8; j++)
          acc[i][j] = fmaf(a[i], b[j], acc[i][j]);
    }
    __syncthreads();
  }

  // ---- epilogue ----
#pragma unroll
  for (int i = 0; i < 8; i++) {
    int m = m0 + tm * 8 + i;
    int crow = perm ? ((m & 1) * CS + (m >> 1)) : m;   // [s,b] -> [b,s]
    float* cp = C + (size_t)crow * ldc + n0 + tn * 8;
#pragma unroll
    for (int j = 0; j < 8; j++) {
      int n = n0 + tn * 8 + j;
      if (n < N) {
        float vv = acc[i][j] * alpha;
        if (bias) vv += bias[n];
        if (relu) vv = fmaxf(vv, 0.f);
        cp[j] = vv;
      }
    }
  }
}

__global__ void __launch_bounds__(256, 2) k_gemm_nn(
    const float* A, const float* B, const float* bias, float* C,
    int N, int K, int lda, int ldb, int ldc, int relu, int perm)
{
  gemm_core<false>(A, B, bias, C, N, K, lda, ldb, ldc, 1.f, relu, perm);
}

// scores[z][q][k] = SCALE * sum_hd q[q][hd] * k[k][hd],  z = slot*16 + b*8 + h
__global__ void __launch_bounds__(256, 2) k_gemm_scores(
    const float* qb, const float* kb, float* sc)
{
  int z = blockIdx.z, bh = z & 15, slot = z >> 4;
  int b = bh >> 3, h = bh & 7;
  const float* A = qb + b * CD + h * CHD;
  const float* B = kb + (size_t)slot * CT * CD + b * CD + h * CHD;
  float* C = sc + (size_t)z * CS * CS;
  gemm_core<true>(A, B, nullptr, C, CS, CHD, CB * CD, CB * CD, CS,
                  ATT_SCALE, 0, 0);
}

// ob[z][q][hd] = sum_k P[z][q][k] * v[slot][k][hd]
__global__ void __launch_bounds__(256, 2) k_gemm_pv(
    const float* sc, const float* vb, float* ob)
{
  int z = blockIdx.z, bh = z & 15, slot = z >> 4;
  int b = bh >> 3, h = bh & 7;
  const float* A = sc + (size_t)z * CS * CS;
  const float* B = vb + (size_t)slot * CT * CD + b * CD + h * CHD;
  float* C = ob + (size_t)z * CS * CHD;
  gemm_core<false>(A, B, nullptr, C, CHD, CS, CS, CB * CD, CHD, 1.f, 0, 0);
}

// ---------------- softmax over last dim (256) of scores, one block per row ----
__global__ void k_softmax(float* sc) {
  float* row = sc + (size_t)blockIdx.x * CS;
  int t = threadIdx.x;
  __shared__ float red[8];
  float v = row[t];
  float m = v;
#pragma unroll
  for (int o = 16; o > 0; o >>= 1) m = fmaxf(m, __shfl_xor_sync(~0u, m, o));
  if ((t & 31) == 0) red[t >> 5] = m;
  __syncthreads();
  float mx = red[0];
#pragma unroll
  for (int i = 1; i < 8; i++) mx = fmaxf(mx, red[i]);
  float e = expf(v - mx);
  __syncthreads();
  float s = e;
#pragma unroll
  for (int o = 16; o > 0; o >>= 1) s += __shfl_xor_sync(~0u, s, o);
  if ((t & 31) == 0) red[t >> 5] = s;
  __syncthreads();
  float tot = 0.f;
#pragma unroll
  for (int i = 0; i < 8; i++) tot += red[i];
  row[t] = e / tot;
}

// ---------------- layer-mix weights: softmax(layer_w[l][:n]) ----------------
__global__ void k_lw(const float* lw, int n, float* w) {
  if (threadIdx.x == 0) {
    float mx = -1e30f;
    for (int i = 0; i < n; i++) mx = fmaxf(mx, lw[i]);
    float s = 0.f, e[CL + 1];
    for (int i = 0; i < n; i++) { e[i] = expf(lw[i] - mx); s += e[i]; }
    for (int i = 0; i < n; i++) w[i] = e[i] / s;
  }
}

// comb[r][c] = sum_slot w[slot] * ob[slot*16 + b*8 + h][s][hd]
__global__ void k_combine(const float* __restrict__ ob,
                          const float* __restrict__ w, int n,
                          float* __restrict__ comb)
{
  int idx = blockIdx.x * 256 + threadIdx.x;
  int r = idx >> 10, c = idx & 1023;
  int s = r >> 1, b = r & 1, h = c >> 7, hd = c & 127;
  float acc = 0.f;
  for (int slot = 0; slot < n; slot++)
    acc += w[slot] * ob[((size_t)(slot * 16 + b * 8 + h) * CS + s) * CHD + hd];
  comb[idx] = acc;
}

// ---------------- fused residual add + layernorm, one block per row ----------
__global__ void k_addln(const float* __restrict__ x, const float* __restrict__ res,
                        const float* __restrict__ g, const float* __restrict__ be,
                        float* __restrict__ out0, float* __restrict__ out1)
{
  int r = blockIdx.x, t = threadIdx.x;   // 256 threads, 4 elems each
  const float4* xr = (const float4*)(x + (size_t)r * CD);
  const float4* rr = (const float4*)(res + (size_t)r * CD);
  float4 a = xr[t], b4 = rr[t];
  float v0 = a.x + b4.x, v1 = a.y + b4.y, v2 = a.z + b4.z, v3 = a.w + b4.w;

  __shared__ float red[8];
  float s = v0 + v1 + v2 + v3;
#pragma unroll
  for (int o = 16; o > 0; o >>= 1) s += __shfl_xor_sync(~0u, s, o);
  if ((t & 31) == 0) red[t >> 5] = s;
  __syncthreads();
  float tot = 0.f;
#pragma unroll
  for (int i = 0; i < 8; i++) tot += red[i];
  float mean = tot * (1.f / CD);

  float d0 = v0 - mean, d1 = v1 - mean, d2 = v2 - mean, d3 = v3 - mean;
  float sq = d0 * d0 + d1 * d1 + d2 * d2 + d3 * d3;
  __syncthreads();
#pragma unroll
  for (int o = 16; o > 0; o >>= 1) sq += __shfl_xor_sync(~0u, sq, o);
  if ((t & 31) == 0) red[t >> 5] = sq;
  __syncthreads();
  float vs = 0.f;
#pragma unroll
  for (int i = 0; i < 8; i++) vs += red[i];
  float rstd = rsqrtf(vs * (1.f / CD) + 1e-5f);

  float4 gg = ((const float4*)g)[t];
  float4 bb = ((const float4*)be)[t];
  float4 ov;
  ov.x = d0 * rstd * gg.x + bb.x;
  ov.y = d1 * rstd * gg.y + bb.y;
  ov.z = d2 * rstd * gg.z + bb.z;
  ov.w = d3 * rstd * gg.w + bb.w;
  ((float4*)(out0 + (size_t)r * CD))[t] = ov;
  if (out1) ((float4*)(out1 + (size_t)r * CD))[t] = ov;
}

// ---------------- embedding * sqrt(D) + positional encoding ------------------
__global__ void k_embed(const int* __restrict__ src, const float* __restrict__ emb,
                        float* __restrict__ x)
{
  int r = blockIdx.x, t = threadIdx.x;     // 256 threads, 4 d each
  int s = r >> 1, b = r & 1;
  int tok = src[b * CS + s];
  const float* er = emb + (size_t)tok * CD;
  float* xr = x + (size_t)r * CD;
  const float SQ = 32.0f;                  // sqrt(1024)
  const float cexp = -9.210340371976184f / (float)CD;  // -ln(10000)/D
#pragma unroll
  for (int i = 0; i < 4; i++) {
    int d = t * 4 + i;
    int pair = d >> 1;
    float ang = (float)s * expf((float)(2 * pair) * cexp);
    float pe = (d & 1) ? cosf(ang) : sinf(ang);
    xr[d] = er[d] * SQ + pe;
  }
}

// ---------------- SNN scan: 1 block per batch, 1024 threads = D --------------
__global__ void k_snn(const float* __restrict__ cur, float* __restrict__ sp) {
  int b = blockIdx.x, t = threadIdx.x;
  __shared__ float red[32];
  __shared__ float ssum;
  float mem = 0.f, thr = 1.0f;
  for (int s = 0; s < CS; s++) {
    float v = mem;
#pragma unroll
    for (int o = 16; o > 0; o >>= 1) v += __shfl_xor_sync(~0u, v, o);
    if ((t & 31) == 0) red[t >> 5] = v;
    __syncthreads();
    if (t < 32) {
      float w = red[t];
#pragma unroll
      for (int o = 16; o > 0; o >>= 1) w += __shfl_xor_sync(~0u, w, o);
      if (t == 0) ssum = w;
    }
    __syncthreads();
    float c = cur[(size_t)(s * CB + b) * CD + t] - 0.1f * ssum;
    mem = 0.9f * mem + c;
    float spk = (mem >= thr) ? 1.f : 0.f;
    mem -= spk * thr;
    thr = 0.9f * thr + 0.1f * spk;
    sp[(size_t)(s * CB + b) * CD + t] = spk;
    __syncthreads();   // protect red/ssum reuse next step
  }
}

// =======================================================================
extern "C" void kernel_launch(void* const* d_in, const int* in_sizes, int n_in,
                              void* d_out, int out_size)
{
  (void)in_sizes; (void)n_in; (void)out_size;
  const int*   src     = (const int*)  d_in[0];
  const float* emb     = (const float*)d_in[1];
  const float* Wq      = (const float*)d_in[2];
  const float* bq      = (const float*)d_in[3];
  const float* Wk      = (const float*)d_in[4];
  const float* bk      = (const float*)d_in[5];
  const float* Wv      = (const float*)d_in[6];
  const float* bv      = (const float*)d_in[7];
  const float* Wo      = (const float*)d_in[8];
  const float* bo      = (const float*)d_in[9];
  const float* layer_w = (const float*)d_in[10];
  const float* Wsnn    = (const float*)d_in[11];
  const float* bsnn    = (const float*)d_in[12];
  const float* W1      = (const float*)d_in[13];
  const float* b1      = (const float*)d_in[14];
  const float* W2      = (const float*)d_in[15];
  const float* b2      = (const float*)d_in[16];
  const float* g1      = (const float*)d_in[17];
  const float* be1     = (const float*)d_in[18];
  const float* g2      = (const float*)d_in[19];
  const float* be2     = (const float*)d_in[20];
  const float* Wout    = (const float*)d_in[21];
  const float* bout    = (const float*)d_in[22];
  float* out = (float*)d_out;

  static bool s_init = false;
  static float *pLB, *pK, *pV, *pQ, *pSC, *pOB, *pCOMB, *pATT, *pXA,
               *pCUR, *pSP, *pFFH, *pFFO, *pW;
  if (!s_init) {
    cudaGetSymbolAddress((void**)&pLB,   g_LB);
    cudaGetSymbolAddress((void**)&pK,    g_k);
    cudaGetSymbolAddress((void**)&pV,    g_v);
    cudaGetSymbolAddress((void**)&pQ,    g_q);
    cudaGetSymbolAddress((void**)&pSC,   g_sc);
    cudaGetSymbolAddress((void**)&pOB,   g_ob);
    cudaGetSymbolAddress((void**)&pCOMB, g_comb);
    cudaGetSymbolAddress((void**)&pATT,  g_att);
    cudaGetSymbolAddress((void**)&pXA,   g_xa);
    cudaGetSymbolAddress((void**)&pCUR,  g_cur);
    cudaGetSymbolAddress((void**)&pSP,   g_sp);
    cudaGetSymbolAddress((void**)&pFFH,  g_ffh);
    cudaGetSymbolAddress((void**)&pFFO,  g_ffo);
    cudaGetSymbolAddress((void**)&pW,    g_w);
    s_init = true;
  }

  // x = emb[src]*sqrt(D) + pe  ->  LB slot 0
  k_embed<<<CT, 256>>>(src, emb, pLB);

  for (int l = 0; l < CL; l++) {
    int n = l + 1;
    k_lw<<<1, 32>>>(layer_w + (size_t)l * (CL + 1), n, pW);

    // Q projection (M=512)
    k_gemm_nn<<<dim3(8, 4), 256>>>(pLB, Wq + (size_t)l * CD * CD, bq + (size_t)l * CD,
                                   pQ, CD, CD, CD, CD, CD, 0, 0);
    // K,V projections batched over all n sources (M = n*512)
    k_gemm_nn<<<dim3(8, n * 4), 256>>>(pLB, Wk + (size_t)l * CD * CD, bk + (size_t)l * CD,
                                       pK, CD, CD, CD, CD, CD, 0, 0);
    k_gemm_nn<<<dim3(8, n * 4), 256>>>(pLB, Wv + (size_t)l * CD * CD, bv + (size_t)l * CD,
                                       pV, CD, CD, CD, CD, CD, 0, 0);

    k_gemm_scores<<<dim3(2, 2, n * 16), 256>>>(pQ, pK, pSC);
    k_softmax<<<n * 16 * CS, 256>>>(pSC);
    k_gemm_pv<<<dim3(1, 2, n * 16), 256>>>(pSC, pV, pOB);
    k_combine<<<(CT * CD) / 256, 256>>>(pOB, pW, n, pCOMB);

    // output projection + residual LN1
    k_gemm_nn<<<dim3(8, 4), 256>>>(pCOMB, Wo + (size_t)l * CD * CD, bo + (size_t)l * CD,
                                   pATT, CD, CD, CD, CD, CD, 0, 0);
    k_addln<<<CT, 256>>>(pLB, pATT, g1 + (size_t)l * CD, be1 + (size_t)l * CD,
                         pXA, nullptr);

    // SNN: input current projection + scan
    k_gemm_nn<<<dim3(8, 4), 256>>>(pXA, Wsnn + (size_t)l * CD * CD, bsnn + (size_t)l * CD,
                                   pCUR, CD, CD, CD, CD, CD, 0, 0);
    k_snn<<<CB, 1024>>>(pCUR, pSP);

    // FF
    k_gemm_nn<<<dim3(16, 4), 256>>>(pSP, W1 + (size_t)l * CD * CFF, b1 + (size_t)l * CFF,
                                    pFFH, CFF, CD, CD, CFF, CFF, 1, 0);
    k_gemm_nn<<<dim3(8, 4), 256>>>(pFFH, W2 + (size_t)l * CFF * CD, b2 + (size_t)l * CD,
                                   pFFO, CD, CFF, CFF, CD, CD, 0, 0);

    // residual LN2 -> new x in slot 0, and archived in slot l+1
    k_addln<<<CT, 256>>>(pXA, pFFO, g2 + (size_t)l * CD, be2 + (size_t)l * CD,
                         pLB, pLB + (size_t)(l + 1) * CT * CD);
  }

  // logits = x @ Wout + bout, written transposed to [B,S,V]
  k_gemm_nn<<<dim3((CV + 127) / 128, 4), 256>>>(pLB, Wout, bout, out,
                                                CV, CD, CD, CV, CV, 0, 1);
}

// round 4
// speedup vs baseline: 1.3545x; 1.3545x over previous
#include <cuda_runtime.h>
#include <math.h>
#include <stdint.h>
#include <stddef.h>

typedef unsigned long long ull;

// ---------------- problem constants ----------------
constexpr int CB  = 2;
constexpr int CS  = 256;
constexpr int CD  = 1024;
constexpr int CH  = 8;
constexpr int CHD = 128;
constexpr int CL  = 16;
constexpr int CFF = 2048;
constexpr int CV  = 50257;
constexpr int CT  = CS * CB;   // 512 tokens, row r = s*CB + b
constexpr float ATT_SCALE = 0.08838834764831845f;  // 128^-0.5

// ---------------- static device scratch ----------------
__device__ float g_LB[(size_t)(CL + 1) * CT * CD];   // slot-major sources; slot0 = live x
__device__ float g_k [(size_t)CL * CT * CD];
__device__ float g_v [(size_t)CL * CT * CD];
__device__ float g_q [CT * CD];
__device__ float g_sc[(size_t)CL * 16 * CS * CS];    // scores [z=slot*16+bh][q][k]
__device__ float g_ob[(size_t)CL * 16 * CS * CHD];   // per-slot attn out
__device__ float g_comb[CT * CD];
__device__ float g_att [CT * CD];
__device__ float g_xa  [CT * CD];                    // x after LN1
__device__ float g_cur [CT * CD];
__device__ float g_sp  [CT * CD];
__device__ float g_ffh [CT * CFF];
__device__ float g_ffo [CT * CD];
__device__ float g_w   [CL + 1];                     // layer-mix softmax weights

// ---------------- packed f32x2 helpers ----------------
__device__ __forceinline__ ull pk2(float x, float y) {
  ull r; asm("mov.b64 %0,{%1,%2};" : "=l"(r) : "f"(x), "f"(y)); return r;
}
__device__ __forceinline__ void upk2(ull v, float& x, float& y) {
  asm("mov.b64 {%0,%1},%2;" : "=f"(x), "=f"(y) : "l"(v));
}
__device__ __forceinline__ ull ffma2(ull a, ull b, ull c) {
  ull d; asm("fma.rn.f32x2 %0,%1,%2,%3;" : "=l"(d) : "l"(a), "l"(b), "l"(c)); return d;
}

// =======================================================================
// SGEMM core: 128x128 tile, K-tile 16, 256 threads, 8x8 microtile,
// double-buffered smem, packed f32x2 FMA. Supports split-K via [kt0,nkt)
// with atomicAdd epilogue (C pre-filled with bias by caller).
// A: MxK row-major (lda). B: TRANSB ? NxK (ldb) : KxN (ldb).
// =======================================================================
template<bool TRANSB>
__device__ __forceinline__ void gemm_core(
    const float* __restrict__ A, const float* __restrict__ B,
    const float* __restrict__ bias, float* __restrict__ C,
    int N, int lda, int ldb, int ldc,
    int kt0, int nkt, float alpha, int relu, int perm, int atomic)
{
  __shared__ float As[2][16][136];
  __shared__ float Bs[2][16][136];

  const int t  = threadIdx.x;
  const int m0 = blockIdx.y * 128;
  const int n0 = blockIdx.x * 128;
  const int tm = t >> 4, tn = t & 15;

  const int lr = t >> 2;            // 0..63
  const int lk = (t & 3) << 2;      // 0,4,8,12
  const int kr = t >> 5;            // 0..7
  const int n4 = (t & 31) << 2;     // 0..124

  const bool vecB = (!TRANSB) && ((ldb & 3) == 0) && (n0 + 128 <= N);

  ull acc2[8][4];
#pragma unroll
  for (int i = 0; i < 8; i++)
#pragma unroll
    for (int j = 0; j < 4; j++) acc2[i][j] = 0ull;

  float4 pa0, pa1, pb0, pb1;
  float  sb[8];

  auto ldA = [&](int kt) {
    const float* p = A + (size_t)(m0 + lr) * lda + kt * 16 + lk;
    pa0 = *(const float4*)p;
    pa1 = *(const float4*)(p + (size_t)64 * lda);
  };
  auto stA = [&](int s) {
    As[s][lk + 0][lr] = pa0.x; As[s][lk + 1][lr] = pa0.y;
    As[s][lk + 2][lr] = pa0.z; As[s][lk + 3][lr] = pa0.w;
    As[s][lk + 0][lr + 64] = pa1.x; As[s][lk + 1][lr + 64] = pa1.y;
    As[s][lk + 2][lr + 64] = pa1.z; As[s][lk + 3][lr + 64] = pa1.w;
  };
  auto ldB = [&](int kt) {
    if (TRANSB) {
      const float* p = B + (size_t)(n0 + lr) * ldb + kt * 16 + lk;
      pb0 = *(const float4*)p;
      pb1 = *(const float4*)(p + (size_t)64 * ldb);
    } else if (vecB) {
      const float* p = B + (size_t)(kt * 16 + kr) * ldb + n0 + n4;
      pb0 = *(const float4*)p;
      pb1 = *(const float4*)(p + (size_t)8 * ldb);
    } else {
      const float* p  = B + (size_t)(kt * 16 + kr) * ldb + n0;
      const float* p2 = p + (size_t)8 * ldb;
#pragma unroll
      for (int u = 0; u < 4; u++) {
        int col = n4 + u;
        bool ok = (n0 + col) < N;
        sb[u]     = ok ? p[col]  : 0.f;
        sb[4 + u] = ok ? p2[col] : 0.f;
      }
    }
  };
  auto stB = [&](int s) {
    if (TRANSB) {
      Bs[s][lk + 0][lr] = pb0.x; Bs[s][lk + 1][lr] = pb0.y;
      Bs[s][lk + 2][lr] = pb0.z; Bs[s][lk + 3][lr] = pb0.w;
      Bs[s][lk + 0][lr + 64] = pb1.x; Bs[s][lk + 1][lr + 64] = pb1.y;
      Bs[s][lk + 2][lr + 64] = pb1.z; Bs[s][lk + 3][lr + 64] = pb1.w;
    } else if (vecB) {
      *(float4*)&Bs[s][kr][n4]     = pb0;
      *(float4*)&Bs[s][kr + 8][n4] = pb1;
    } else {
#pragma unroll
      for (int u = 0; u < 4; u++) {
        Bs[s][kr][n4 + u]     = sb[u];
        Bs[s][kr + 8][n4 + u] = sb[4 + u];
      }
    }
  };

  ldA(kt0); ldB(kt0);
  stA(0);   stB(0);
  __syncthreads();

  for (int it = 0; it < nkt; it++) {
    int cur = it & 1;
    if (it + 1 < nkt) { ldA(kt0 + it + 1); ldB(kt0 + it + 1); }

#pragma unroll
    for (int k = 0; k < 16; k++) {
      float4 a0 = *(const float4*)&As[cur][k][tm * 8];
      float4 a1 = *(const float4*)&As[cur][k][tm * 8 + 4];
      ulonglong2 q0 = *(const ulonglong2*)&Bs[cur][k][tn * 8];
      ulonglong2 q1 = *(const ulonglong2*)&Bs[cur][k][tn * 8 + 4];
      ull bb[4] = { q0.x, q0.y, q1.x, q1.y };
      float av[8] = { a0.x, a0.y, a0.z, a0.w, a1.x, a1.y, a1.z, a1.w };
#pragma unroll
      for (int i = 0; i < 8; i++) {
        ull aa = pk2(av[i], av[i]);
#pragma unroll
        for (int j = 0; j < 4; j++)
          acc2[i][j] = ffma2(aa, bb[j], acc2[i][j]);
      }
    }

    if (it + 1 < nkt) { stA(cur ^ 1); stB(cur ^ 1); }
    __syncthreads();
  }

  // ---- epilogue ----
#pragma unroll
  for (int i = 0; i < 8; i++) {
    int m = m0 + tm * 8 + i;
    int crow = perm ? ((m & 1) * CS + (m >> 1)) : m;   // [s,b] -> [b,s]
    float* cp = C + (size_t)crow * ldc + n0 + tn * 8;
    float vals[8];
#pragma unroll
    for (int j4 = 0; j4 < 4; j4++) upk2(acc2[i][j4], vals[2 * j4], vals[2 * j4 + 1]);
    if (atomic) {
#pragma unroll
      for (int j = 0; j < 8; j++) {
        int n = n0 + tn * 8 + j;
        if (n < N) atomicAdd(cp + j, vals[j] * alpha);
      }
    } else {
#pragma unroll
      for (int j = 0; j < 8; j++) {
        int n = n0 + tn * 8 + j;
        if (n < N) {
          float v = vals[j] * alpha;
          if (bias) v += bias[n];
          if (relu) v = fmaxf(v, 0.f);
          cp[j] = v;
        }
      }
    }
  }
}

__global__ void __launch_bounds__(256) k_gemm_nn(
    const float* A, const float* B, const float* bias, float* C,
    int N, int K, int lda, int ldb, int ldc, int relu, int perm)
{
  int ks = gridDim.z;
  int ktiles = K >> 4;
  int nkt = ktiles / ks;
  int kt0 = blockIdx.z * nkt;
  gemm_core<false>(A, B, bias, C, N, lda, ldb, ldc, kt0, nkt, 1.f, relu, perm, ks > 1);
}

// scores[z][q][k] = SCALE * sum_hd q[q][hd] * k[k][hd],  z = slot*16 + b*8 + h
__global__ void __launch_bounds__(256) k_gemm_scores(
    const float* qb, const float* kb, float* sc)
{
  int z = blockIdx.z, bh = z & 15, slot = z >> 4;
  int b = bh >> 3, h = bh & 7;
  const float* A = qb + b * CD + h * CHD;
  const float* B = kb + (size_t)slot * CT * CD + b * CD + h * CHD;
  float* C = sc + (size_t)z * CS * CS;
  gemm_core<true>(A, B, nullptr, C, CS, CB * CD, CB * CD, CS,
                  0, CHD / 16, ATT_SCALE, 0, 0, 0);
}

// ob[z][q][hd] = sum_k P[z][q][k] * v[slot][k][hd]
__global__ void __launch_bounds__(256) k_gemm_pv(
    const float* sc, const float* vb, float* ob)
{
  int z = blockIdx.z, bh = z & 15, slot = z >> 4;
  int b = bh >> 3, h = bh & 7;
  const float* A = sc + (size_t)z * CS * CS;
  const float* B = vb + (size_t)slot * CT * CD + b * CD + h * CHD;
  float* C = ob + (size_t)z * CS * CHD;
  gemm_core<false>(A, B, nullptr, C, CHD, CS, CB * CD, CHD,
                  0, CS / 16, 1.f, 0, 0, 0);
}

// ---------------- bias prefill / relu ----------------
__global__ void k_fill(float* __restrict__ C, const float* __restrict__ b,
                       int ncols4, int total4) {
  int i = blockIdx.x * 256 + threadIdx.x;
  if (i < total4) ((float4*)C)[i] = ((const float4*)b)[i % ncols4];
}
__global__ void k_relu(float* __restrict__ p, int total4) {
  int i = blockIdx.x * 256 + threadIdx.x;
  if (i < total4) {
    float4 v = ((float4*)p)[i];
    v.x = fmaxf(v.x, 0.f); v.y = fmaxf(v.y, 0.f);
    v.z = fmaxf(v.z, 0.f); v.w = fmaxf(v.w, 0.f);
    ((float4*)p)[i] = v;
  }
}

// ---------------- softmax over last dim (256), one block per row ----------
__global__ void k_softmax(float* sc) {
  float* row = sc + (size_t)blockIdx.x * CS;
  int t = threadIdx.x;
  __shared__ float red[8];
  float v = row[t];
  float m = v;
#pragma unroll
  for (int o = 16; o > 0; o >>= 1) m = fmaxf(m, __shfl_xor_sync(~0u, m, o));
  if ((t & 31) == 0) red[t >> 5] = m;
  __syncthreads();
  float mx = red[0];
#pragma unroll
  for (int i = 1; i < 8; i++) mx = fmaxf(mx, red[i]);
  float e = expf(v - mx);
  __syncthreads();
  float s = e;
#pragma unroll
  for (int o = 16; o > 0; o >>= 1) s += __shfl_xor_sync(~0u, s, o);
  if ((t & 31) == 0) red[t >> 5] = s;
  __syncthreads();
  float tot = 0.f;
#pragma unroll
  for (int i = 0; i < 8; i++) tot += red[i];
  row[t] = e / tot;
}

// ---------------- layer-mix weights ----------------
__global__ void k_lw(const float* lw, int n, float* w) {
  if (threadIdx.x == 0) {
    float mx = -1e30f;
    for (int i = 0; i < n; i++) mx = fmaxf(mx, lw[i]);
    float s = 0.f, e[CL + 1];
    for (int i = 0; i < n; i++) { e[i] = expf(lw[i] - mx); s += e[i]; }
    for (int i = 0; i < n; i++) w[i] = e[i] / s;
  }
}

// comb[r][c] = sum_slot w[slot] * ob[slot*16 + b*8 + h][s][hd]
__global__ void k_combine(const float* __restrict__ ob,
                          const float* __restrict__ w, int n,
                          float* __restrict__ comb)
{
  int idx = blockIdx.x * 256 + threadIdx.x;
  int r = idx >> 10, c = idx & 1023;
  int s = r >> 1, b = r & 1, h = c >> 7, hd = c & 127;
  float acc = 0.f;
  for (int slot = 0; slot < n; slot++)
    acc += w[slot] * ob[((size_t)(slot * 16 + b * 8 + h) * CS + s) * CHD + hd];
  comb[idx] = acc;
}

// ---------------- fused residual add + layernorm ----------
__global__ void k_addln(const float* __restrict__ x, const float* __restrict__ res,
                        const float* __restrict__ g, const float* __restrict__ be,
                        float* __restrict__ out0, float* __restrict__ out1)
{
  int r = blockIdx.x, t = threadIdx.x;
  const float4* xr = (const float4*)(x + (size_t)r * CD);
  const float4* rr = (const float4*)(res + (size_t)r * CD);
  float4 a = xr[t], b4 = rr[t];
  float v0 = a.x + b4.x, v1 = a.y + b4.y, v2 = a.z + b4.z, v3 = a.w + b4.w;

  __shared__ float red[8];
  float s = v0 + v1 + v2 + v3;
#pragma unroll
  for (int o = 16; o > 0; o >>= 1) s += __shfl_xor_sync(~0u, s, o);
  if ((t & 31) == 0) red[t >> 5] = s;
  __syncthreads();
  float tot = 0.f;
#pragma unroll
  for (int i = 0; i < 8; i++) tot += red[i];
  float mean = tot * (1.f / CD);

  float d0 = v0 - mean, d1 = v1 - mean, d2 = v2 - mean, d3 = v3 - mean;
  float sq = d0 * d0 + d1 * d1 + d2 * d2 + d3 * d3;
  __syncthreads();
#pragma unroll
  for (int o = 16; o > 0; o >>= 1) sq += __shfl_xor_sync(~0u, sq, o);
  if ((t & 31) == 0) red[t >> 5] = sq;
  __syncthreads();
  float vs = 0.f;
#pragma unroll
  for (int i = 0; i < 8; i++) vs += red[i];
  float rstd = rsqrtf(vs * (1.f / CD) + 1e-5f);

  float4 gg = ((const float4*)g)[t];
  float4 bb = ((const float4*)be)[t];
  float4 ov;
  ov.x = d0 * rstd * gg.x + bb.x;
  ov.y = d1 * rstd * gg.y + bb.y;
  ov.z = d2 * rstd * gg.z + bb.z;
  ov.w = d3 * rstd * gg.w + bb.w;
  ((float4*)(out0 + (size_t)r * CD))[t] = ov;
  if (out1) ((float4*)(out1 + (size_t)r * CD))[t] = ov;
}

// ---------------- embedding * sqrt(D) + positional encoding ------------------
__global__ void k_embed(const int* __restrict__ src, const float* __restrict__ emb,
                        float* __restrict__ x)
{
  int r = blockIdx.x, t = threadIdx.x;
  int s = r >> 1, b = r & 1;
  int tok = src[b * CS + s];
  const float* er = emb + (size_t)tok * CD;
  float* xr = x + (size_t)r * CD;
  const float SQ = 32.0f;
  const float cexp = -9.210340371976184f / (float)CD;
#pragma unroll
  for (int i = 0; i < 4; i++) {
    int d = t * 4 + i;
    int pair = d >> 1;
    float ang = (float)s * expf((float)(2 * pair) * cexp);
    float pe = (d & 1) ? cosf(ang) : sinf(ang);
    xr[d] = er[d] * SQ + pe;
  }
}

// ---------------- SNN scan ----------------
__global__ void k_snn(const float* __restrict__ cur, float* __restrict__ sp) {
  int b = blockIdx.x, t = threadIdx.x;
  __shared__ float red[32];
  __shared__ float ssum;
  float mem = 0.f, thr = 1.0f;
  for (int s = 0; s < CS; s++) {
    float v = mem;
#pragma unroll
    for (int o = 16; o > 0; o >>= 1) v += __shfl_xor_sync(~0u, v, o);
    if ((t & 31) == 0) red[t >> 5] = v;
    __syncthreads();
    if (t < 32) {
      float w = red[t];
#pragma unroll
      for (int o = 16; o > 0; o >>= 1) w += __shfl_xor_sync(~0u, w, o);
      if (t == 0) ssum = w;
    }
    __syncthreads();
    float c = cur[(size_t)(s * CB + b) * CD + t] - 0.1f * ssum;
    mem = 0.9f * mem + c;
    float spk = (mem >= thr) ? 1.f : 0.f;
    mem -= spk * thr;
    thr = 0.9f * thr + 0.1f * spk;
    sp[(size_t)(s * CB + b) * CD + t] = spk;
    __syncthreads();
  }
}

// =======================================================================
extern "C" void kernel_launch(void* const* d_in, const int* in_sizes, int n_in,
                              void* d_out, int out_size)
{
  (void)in_sizes; (void)n_in; (void)out_size;
  const int*   src     = (const int*)  d_in[0];
  const float* emb     = (const float*)d_in[1];
  const float* Wq      = (const float*)d_in[2];
  const float* bq      = (const float*)d_in[3];
  const float* Wk      = (const float*)d_in[4];
  const float* bk      = (const float*)d_in[5];
  const float* Wv      = (const float*)d_in[6];
  const float* bv      = (const float*)d_in[7];
  const float* Wo      = (const float*)d_in[8];
  const float* bo      = (const float*)d_in[9];
  const float* layer_w = (const float*)d_in[10];
  const float* Wsnn    = (const float*)d_in[11];
  const float* bsnn    = (const float*)d_in[12];
  const float* W1      = (const float*)d_in[13];
  const float* b1      = (const float*)d_in[14];
  const float* W2      = (const float*)d_in[15];
  const float* b2      = (const float*)d_in[16];
  const float* g1      = (const float*)d_in[17];
  const float* be1     = (const float*)d_in[18];
  const float* g2      = (const float*)d_in[19];
  const float* be2     = (const float*)d_in[20];
  const float* Wout    = (const float*)d_in[21];
  const float* bout    = (const float*)d_in[22];
  float* out = (float*)d_out;

  static bool s_init = false;
  static float *pLB, *pK, *pV, *pQ, *pSC, *pOB, *pCOMB, *pATT, *pXA,
               *pCUR, *pSP, *pFFH, *pFFO, *pW;
  if (!s_init) {
    cudaGetSymbolAddress((void**)&pLB,   g_LB);
    cudaGetSymbolAddress((void**)&pK,    g_k);
    cudaGetSymbolAddress((void**)&pV,    g_v);
    cudaGetSymbolAddress((void**)&pQ,    g_q);
    cudaGetSymbolAddress((void**)&pSC,   g_sc);
    cudaGetSymbolAddress((void**)&pOB,   g_ob);
    cudaGetSymbolAddress((void**)&pCOMB, g_comb);
    cudaGetSymbolAddress((void**)&pATT,  g_att);
    cudaGetSymbolAddress((void**)&pXA,   g_xa);
    cudaGetSymbolAddress((void**)&pCUR,  g_cur);
    cudaGetSymbolAddress((void**)&pSP,   g_sp);
    cudaGetSymbolAddress((void**)&pFFH,  g_ffh);
    cudaGetSymbolAddress((void**)&pFFO,  g_ffo);
    cudaGetSymbolAddress((void**)&pW,    g_w);
    s_init = true;
  }

  // split-K GEMM launcher: prefill bias, accumulate atomically
  auto gemm = [](const float* A, const float* W, const float* b, float* C,
                 int M, int N, int K, int lda, int ks, int relu) {
    if (ks > 1) {
      int t4 = (M * N) >> 2;
      k_fill<<<(t4 + 255) / 256, 256>>>(C, b, N >> 2, t4);
      k_gemm_nn<<<dim3(N / 128, M / 128, ks), 256>>>(A, W, nullptr, C,
                                                     N, K, lda, N, N, 0, 0);
      if (relu) k_relu<<<(t4 + 255) / 256, 256>>>(C, t4);
    } else {
      k_gemm_nn<<<dim3(N / 128, M / 128, 1), 256>>>(A, W, b, C,
                                                    N, K, lda, N, N, relu, 0);
    }
  };

  k_embed<<<CT, 256>>>(src, emb, pLB);

  for (int l = 0; l < CL; l++) {
    int n = l + 1;
    k_lw<<<1, 32>>>(layer_w + (size_t)l * (CL + 1), n, pW);

    gemm(pLB, Wq + (size_t)l * CD * CD, bq + (size_t)l * CD, pQ,
         CT, CD, CD, CD, 4, 0);
    int ksv = (n == 1) ? 4 : (n == 2) ? 2 : 1;
    gemm(pLB, Wk + (size_t)l * CD * CD, bk + (size_t)l * CD, pK,
         n * CT, CD, CD, CD, ksv, 0);
    gemm(pLB, Wv + (size_t)l * CD * CD, bv + (size_t)l * CD, pV,
         n * CT, CD, CD, CD, ksv, 0);

    k_gemm_scores<<<dim3(2, 2, n * 16), 256>>>(pQ, pK, pSC);
    k_softmax<<<n * 16 * CS, 256>>>(pSC);
    k_gemm_pv<<<dim3(1, 2, n * 16), 256>>>(pSC, pV, pOB);
    k_combine<<<(CT * CD) / 256, 256>>>(pOB, pW, n, pCOMB);

    gemm(pCOMB, Wo + (size_t)l * CD * CD, bo + (size_t)l * CD, pATT,
         CT, CD, CD, CD, 4, 0);
    k_addln<<<CT, 256>>>(pLB, pATT, g1 + (size_t)l * CD, be1 + (size_t)l * CD,
                         pXA, nullptr);

    gemm(pXA, Wsnn + (size_t)l * CD * CD, bsnn + (size_t)l * CD, pCUR,
         CT, CD, CD, CD, 4, 0);
    k_snn<<<CB, 1024>>>(pCUR, pSP);

    gemm(pSP, W1 + (size_t)l * CD * CFF, b1 + (size_t)l * CFF, pFFH,
         CT, CFF, CD, CD, 2, 1);
    gemm(pFFH, W2 + (size_t)l * CFF * CD, b2 + (size_t)l * CD, pFFO,
         CT, CD, CFF, CFF, 4, 0);

    k_addln<<<CT, 256>>>(pXA, pFFO, g2 + (size_t)l * CD, be2 + (size_t)l * CD,
                         pLB, pLB + (size_t)(l + 1) * CT * CD);
  }

  // logits = x @ Wout + bout, written transposed to [B,S,V]
  k_gemm_nn<<<dim3((CV + 127) / 128, CT / 128, 1), 256>>>(pLB, Wout, bout, out,
                                                          CV, CD, CD, CV, CV, 0, 1);
}

// round 5
// speedup vs baseline: 1.4974x; 1.1055x over previous
#include <cuda_runtime.h>
#include <math.h>
#include <stdint.h>
#include <stddef.h>

typedef unsigned long long ull;

// ---------------- problem constants ----------------
constexpr int CB  = 2;
constexpr int CS  = 256;
constexpr int CD  = 1024;
constexpr int CH  = 8;
constexpr int CHD = 128;
constexpr int CL  = 16;
constexpr int CFF = 2048;
constexpr int CV  = 50257;
constexpr int CT  = CS * CB;   // 512 tokens, row r = s*CB + b
constexpr float ATT_SCALE = 0.08838834764831845f;  // 128^-0.5

// ---------------- static device scratch ----------------
__device__ float g_LB[(size_t)(CL + 1) * CT * CD];   // slot-major sources; slot0 = live x
__device__ float g_k [(size_t)CL * CT * CD];
__device__ float g_v [(size_t)CL * CT * CD];
__device__ float g_q [CT * CD];
__device__ float g_sc[(size_t)CL * 16 * CS * CS];    // scores [z=slot*16+bh][q][k]
__device__ float g_ob[(size_t)CL * 16 * CS * CHD];   // per-slot attn out
__device__ float g_comb[CT * CD];
__device__ float g_att [CT * CD];
__device__ float g_xa  [CT * CD];                    // x after LN1
__device__ float g_cur [CT * CD];
__device__ float g_sp  [CT * CD];
__device__ float g_ffh [CT * CFF];
__device__ float g_ffo [CT * CD];
__device__ float g_w   [CL + 1];                     // layer-mix softmax weights

// ---------------- packed f32x2 helpers ----------------
__device__ __forceinline__ ull pk2(float x, float y) {
  ull r; asm("mov.b64 %0,{%1,%2};" : "=l"(r) : "f"(x), "f"(y)); return r;
}
__device__ __forceinline__ void upk2(ull v, float& x, float& y) {
  asm("mov.b64 {%0,%1},%2;" : "=f"(x), "=f"(y) : "l"(v));
}
__device__ __forceinline__ ull ffma2(ull a, ull b, ull c) {
  ull d; asm("fma.rn.f32x2 %0,%1,%2,%3;" : "=l"(d) : "l"(a), "l"(b), "l"(c)); return d;
}

// =======================================================================
// SGEMM core: 128x128 tile, K-tile 16, 256 threads, 8x8 microtile,
// double-buffered smem, packed f32x2 FMA. Supports split-K via [kt0,nkt)
// with atomicAdd epilogue (C pre-filled with bias by caller).
// A: MxK row-major (lda). B: TRANSB ? NxK (ldb) : KxN (ldb).
// =======================================================================
template<bool TRANSB>
__device__ __forceinline__ void gemm_core(
    const float* __restrict__ A, const float* __restrict__ B,
    const float* __restrict__ bias, float* __restrict__ C,
    int N, int lda, int ldb, int ldc,
    int kt0, int nkt, float alpha, int relu, int perm, int atomic)
{
  __shared__ float As[2][16][136];
  __shared__ float Bs[2][16][136];

  const int t  = threadIdx.x;
  const int m0 = blockIdx.y * 128;
  const int n0 = blockIdx.x * 128;
  const int tm = t >> 4, tn = t & 15;

  const int lr = t >> 2;            // 0..63
  const int lk = (t & 3) << 2;      // 0,4,8,12
  const int kr = t >> 5;            // 0..7
  const int n4 = (t & 31) << 2;     // 0..124

  const bool vecB = (!TRANSB) && ((ldb & 3) == 0) && (n0 + 128 <= N);

  ull acc2[8][4];
#pragma unroll
  for (int i = 0; i < 8; i++)
#pragma unroll
    for (int j = 0; j < 4; j++) acc2[i][j] = 0ull;

  float4 pa0, pa1, pb0, pb1;

  auto ldA = [&](int kt) {
    const float* p = A + (size_t)(m0 + lr) * lda + kt * 16 + lk;
    pa0 = *(const float4*)p;
    pa1 = *(const float4*)(p + (size_t)64 * lda);
  };
  auto stA = [&](int s) {
    As[s][lk + 0][lr] = pa0.x; As[s][lk + 1][lr] = pa0.y;
    As[s][lk + 2][lr] = pa0.z; As[s][lk + 3][lr] = pa0.w;
    As[s][lk + 0][lr + 64] = pa1.x; As[s][lk + 1][lr + 64] = pa1.y;
    As[s][lk + 2][lr + 64] = pa1.z; As[s][lk + 3][lr + 64] = pa1.w;
  };
  auto ldB = [&](int kt) {
    if (TRANSB) {
      const float* p = B + (size_t)(n0 + lr) * ldb + kt * 16 + lk;
      pb0 = *(const float4*)p;
      pb1 = *(const float4*)(p + (size_t)64 * ldb);
    } else if (vecB) {
      const float* p = B + (size_t)(kt * 16 + kr) * ldb + n0 + n4;
      pb0 = *(const float4*)p;
      pb1 = *(const float4*)(p + (size_t)8 * ldb);
    } else {
      const float* p  = B + (size_t)(kt * 16 + kr) * ldb + n0;
      const float* p2 = p + (size_t)8 * ldb;
      float v[8];
#pragma unroll
      for (int u = 0; u < 4; u++) {
        int col = n4 + u;
        bool ok = (n0 + col) < N;
        v[u]     = ok ? p[col]  : 0.f;
        v[4 + u] = ok ? p2[col] : 0.f;
      }
      pb0 = make_float4(v[0], v[1], v[2], v[3]);
      pb1 = make_float4(v[4], v[5], v[6], v[7]);
    }
  };
  auto stB = [&](int s) {
    if (TRANSB) {
      Bs[s][lk + 0][lr] = pb0.x; Bs[s][lk + 1][lr] = pb0.y;
      Bs[s][lk + 2][lr] = pb0.z; Bs[s][lk + 3][lr] = pb0.w;
      Bs[s][lk + 0][lr + 64] = pb1.x; Bs[s][lk + 1][lr + 64] = pb1.y;
      Bs[s][lk + 2][lr + 64] = pb1.z; Bs[s][lk + 3][lr + 64] = pb1.w;
    } else {
      *(float4*)&Bs[s][kr][n4]     = pb0;
      *(float4*)&Bs[s][kr + 8][n4] = pb1;
    }
  };

  ldA(kt0); ldB(kt0);
  stA(0);   stB(0);
  __syncthreads();

  for (int it = 0; it < nkt; it++) {
    int cur = it & 1;
    if (it + 1 < nkt) { ldA(kt0 + it + 1); ldB(kt0 + it + 1); }

#pragma unroll
    for (int k = 0; k < 16; k++) {
      float4 a0 = *(const float4*)&As[cur][k][tm * 8];
      float4 a1 = *(const float4*)&As[cur][k][tm * 8 + 4];
      ulonglong2 q0 = *(const ulonglong2*)&Bs[cur][k][tn * 8];
      ulonglong2 q1 = *(const ulonglong2*)&Bs[cur][k][tn * 8 + 4];
      ull bb[4] = { q0.x, q0.y, q1.x, q1.y };
      float av[8] = { a0.x, a0.y, a0.z, a0.w, a1.x, a1.y, a1.z, a1.w };
#pragma unroll
      for (int i = 0; i < 8; i++) {
        ull aa = pk2(av[i], av[i]);
#pragma unroll
        for (int j = 0; j < 4; j++)
          acc2[i][j] = ffma2(aa, bb[j], acc2[i][j]);
      }
    }

    if (it + 1 < nkt) { stA(cur ^ 1); stB(cur ^ 1); }
    __syncthreads();
  }

  // ---- epilogue ----
#pragma unroll
  for (int i = 0; i < 8; i++) {
    int m = m0 + tm * 8 + i;
    int crow = perm ? ((m & 1) * CS + (m >> 1)) : m;   // [s,b] -> [b,s]
    float* cp = C + (size_t)crow * ldc + n0 + tn * 8;
    float vals[8];
#pragma unroll
    for (int j4 = 0; j4 < 4; j4++) upk2(acc2[i][j4], vals[2 * j4], vals[2 * j4 + 1]);
    if (atomic) {
#pragma unroll
      for (int j = 0; j < 8; j++) {
        int n = n0 + tn * 8 + j;
        if (n < N) atomicAdd(cp + j, vals[j] * alpha);
      }
    } else {
#pragma unroll
      for (int j = 0; j < 8; j++) {
        int n = n0 + tn * 8 + j;
        if (n < N) {
          float v = vals[j] * alpha;
          if (bias) v += bias[n];
          if (relu) v = fmaxf(v, 0.f);
          cp[j] = v;
        }
      }
    }
  }
}

__global__ void __launch_bounds__(256, 2) k_gemm_nn(
    const float* A, const float* B, const float* bias, float* C,
    int N, int K, int lda, int ldb, int ldc, int relu, int perm)
{
  int ks = gridDim.z;
  int ktiles = K >> 4;
  int nkt = ktiles / ks;
  int kt0 = blockIdx.z * nkt;
  gemm_core<false>(A, B, bias, C, N, lda, ldb, ldc, kt0, nkt, 1.f, relu, perm, ks > 1);
}

// scores[z][q][k] = SCALE * sum_hd q[q][hd] * k[k][hd],  z = slot*16 + b*8 + h
__global__ void __launch_bounds__(256, 2) k_gemm_scores(
    const float* qb, const float* kb, float* sc)
{
  int z = blockIdx.z, bh = z & 15, slot = z >> 4;
  int b = bh >> 3, h = bh & 7;
  const float* A = qb + b * CD + h * CHD;
  const float* B = kb + (size_t)slot * CT * CD + b * CD + h * CHD;
  float* C = sc + (size_t)z * CS * CS;
  gemm_core<true>(A, B, nullptr, C, CS, CB * CD, CB * CD, CS,
                  0, CHD / 16, ATT_SCALE, 0, 0, 0);
}

// ob[z][q][hd] = sum_k P[z][q][k] * v[slot][k][hd]
__global__ void __launch_bounds__(256, 2) k_gemm_pv(
    const float* sc, const float* vb, float* ob)
{
  int z = blockIdx.z, bh = z & 15, slot = z >> 4;
  int b = bh >> 3, h = bh & 7;
  const float* A = sc + (size_t)z * CS * CS;
  const float* B = vb + (size_t)slot * CT * CD + b * CD + h * CHD;
  float* C = ob + (size_t)z * CS * CHD;
  gemm_core<false>(A, B, nullptr, C, CHD, CS, CB * CD, CHD,
                  0, CS / 16, 1.f, 0, 0, 0);
}

// ---------------- bias prefill / relu ----------------
__global__ void k_fill(float* __restrict__ C, const float* __restrict__ b,
                       int ncols4, int total4) {
  int i = blockIdx.x * 256 + threadIdx.x;
  if (i < total4) ((float4*)C)[i] = ((const float4*)b)[i % ncols4];
}
__global__ void k_relu(float* __restrict__ p, int total4) {
  int i = blockIdx.x * 256 + threadIdx.x;
  if (i < total4) {
    float4 v = ((float4*)p)[i];
    v.x = fmaxf(v.x, 0.f); v.y = fmaxf(v.y, 0.f);
    v.z = fmaxf(v.z, 0.f); v.w = fmaxf(v.w, 0.f);
    ((float4*)p)[i] = v;
  }
}

// ---------------- softmax over last dim (256), one block per row ----------
__global__ void k_softmax(float* sc) {
  float* row = sc + (size_t)blockIdx.x * CS;
  int t = threadIdx.x;
  __shared__ float red[8];
  float v = row[t];
  float m = v;
#pragma unroll
  for (int o = 16; o > 0; o >>= 1) m = fmaxf(m, __shfl_xor_sync(~0u, m, o));
  if ((t & 31) == 0) red[t >> 5] = m;
  __syncthreads();
  float mx = red[0];
#pragma unroll
  for (int i = 1; i < 8; i++) mx = fmaxf(mx, red[i]);
  float e = expf(v - mx);
  __syncthreads();
  float s = e;
#pragma unroll
  for (int o = 16; o > 0; o >>= 1) s += __shfl_xor_sync(~0u, s, o);
  if ((t & 31) == 0) red[t >> 5] = s;
  __syncthreads();
  float tot = 0.f;
#pragma unroll
  for (int i = 0; i < 8; i++) tot += red[i];
  row[t] = e / tot;
}

// ---------------- layer-mix weights ----------------
__global__ void k_lw(const float* lw, int n, float* w) {
  if (threadIdx.x == 0) {
    float mx = -1e30f;
    for (int i = 0; i < n; i++) mx = fmaxf(mx, lw[i]);
    float s = 0.f, e[CL + 1];
    for (int i = 0; i < n; i++) { e[i] = expf(lw[i] - mx); s += e[i]; }
    for (int i = 0; i < n; i++) w[i] = e[i] / s;
  }
}

// comb[r][c] = sum_slot w[slot] * ob[slot*16 + b*8 + h][s][hd]
__global__ void k_combine(const float* __restrict__ ob,
                          const float* __restrict__ w, int n,
                          float* __restrict__ comb)
{
  int idx = blockIdx.x * 256 + threadIdx.x;
  int r = idx >> 10, c = idx & 1023;
  int s = r >> 1, b = r & 1, h = c >> 7, hd = c & 127;
  float acc = 0.f;
  for (int slot = 0; slot < n; slot++)
    acc += w[slot] * ob[((size_t)(slot * 16 + b * 8 + h) * CS + s) * CHD + hd];
  comb[idx] = acc;
}

// ---------------- fused residual add + layernorm ----------
__global__ void k_addln(const float* __restrict__ x, const float* __restrict__ res,
                        const float* __restrict__ g, const float* __restrict__ be,
                        float* __restrict__ out0, float* __restrict__ out1)
{
  int r = blockIdx.x, t = threadIdx.x;
  const float4* xr = (const float4*)(x + (size_t)r * CD);
  const float4* rr = (const float4*)(res + (size_t)r * CD);
  float4 a = xr[t], b4 = rr[t];
  float v0 = a.x + b4.x, v1 = a.y + b4.y, v2 = a.z + b4.z, v3 = a.w + b4.w;

  __shared__ float red[8];
  float s = v0 + v1 + v2 + v3;
#pragma unroll
  for (int o = 16; o > 0; o >>= 1) s += __shfl_xor_sync(~0u, s, o);
  if ((t & 31) == 0) red[t >> 5] = s;
  __syncthreads();
  float tot = 0.f;
#pragma unroll
  for (int i = 0; i < 8; i++) tot += red[i];
  float mean = tot * (1.f / CD);

  float d0 = v0 - mean, d1 = v1 - mean, d2 = v2 - mean, d3 = v3 - mean;
  float sq = d0 * d0 + d1 * d1 + d2 * d2 + d3 * d3;
  __syncthreads();
#pragma unroll
  for (int o = 16; o > 0; o >>= 1) sq += __shfl_xor_sync(~0u, sq, o);
  if ((t & 31) == 0) red[t >> 5] = sq;
  __syncthreads();
  float vs = 0.f;
#pragma unroll
  for (int i = 0; i < 8; i++) vs += red[i];
  float rstd = rsqrtf(vs * (1.f / CD) + 1e-5f);

  float4 gg = ((const float4*)g)[t];
  float4 bb = ((const float4*)be)[t];
  float4 ov;
  ov.x = d0 * rstd * gg.x + bb.x;
  ov.y = d1 * rstd * gg.y + bb.y;
  ov.z = d2 * rstd * gg.z + bb.z;
  ov.w = d3 * rstd * gg.w + bb.w;
  ((float4*)(out0 + (size_t)r * CD))[t] = ov;
  if (out1) ((float4*)(out1 + (size_t)r * CD))[t] = ov;
}

// ---------------- embedding * sqrt(D) + positional encoding ------------------
__global__ void k_embed(const int* __restrict__ src, const float* __restrict__ emb,
                        float* __restrict__ x)
{
  int r = blockIdx.x, t = threadIdx.x;
  int s = r >> 1, b = r & 1;
  int tok = src[b * CS + s];
  const float* er = emb + (size_t)tok * CD;
  float* xr = x + (size_t)r * CD;
  const float SQ = 32.0f;
  const float cexp = -9.210340371976184f / (float)CD;
#pragma unroll
  for (int i = 0; i < 4; i++) {
    int d = t * 4 + i;
    int pair = d >> 1;
    float ang = (float)s * expf((float)(2 * pair) * cexp);
    float pe = (d & 1) ? cosf(ang) : sinf(ang);
    xr[d] = er[d] * SQ + pe;
  }
}

// ---------------- SNN scan ----------------
__global__ void k_snn(const float* __restrict__ cur, float* __restrict__ sp) {
  int b = blockIdx.x, t = threadIdx.x;
  __shared__ float red[32];
  __shared__ float ssum;
  float mem = 0.f, thr = 1.0f;
  for (int s = 0; s < CS; s++) {
    float v = mem;
#pragma unroll
    for (int o = 16; o > 0; o >>= 1) v += __shfl_xor_sync(~0u, v, o);
    if ((t & 31) == 0) red[t >> 5] = v;
    __syncthreads();
    if (t < 32) {
      float w = red[t];
#pragma unroll
      for (int o = 16; o > 0; o >>= 1) w += __shfl_xor_sync(~0u, w, o);
      if (t == 0) ssum = w;
    }
    __syncthreads();
    float c = cur[(size_t)(s * CB + b) * CD + t] - 0.1f * ssum;
    mem = 0.9f * mem + c;
    float spk = (mem >= thr) ? 1.f : 0.f;
    mem -= spk * thr;
    thr = 0.9f * thr + 0.1f * spk;
    sp[(size_t)(s * CB + b) * CD + t] = spk;
    __syncthreads();
  }
}

// =======================================================================
extern "C" void kernel_launch(void* const* d_in, const int* in_sizes, int n_in,
                              void* d_out, int out_size)
{
  (void)in_sizes; (void)n_in; (void)out_size;
  const int*   src     = (const int*)  d_in[0];
  const float* emb     = (const float*)d_in[1];
  const float* Wq      = (const float*)d_in[2];
  const float* bq      = (const float*)d_in[3];
  const float* Wk      = (const float*)d_in[4];
  const float* bk      = (const float*)d_in[5];
  const float* Wv      = (const float*)d_in[6];
  const float* bv      = (const float*)d_in[7];
  const float* Wo      = (const float*)d_in[8];
  const float* bo      = (const float*)d_in[9];
  const float* layer_w = (const float*)d_in[10];
  const float* Wsnn    = (const float*)d_in[11];
  const float* bsnn    = (const float*)d_in[12];
  const float* W1      = (const float*)d_in[13];
  const float* b1      = (const float*)d_in[14];
  const float* W2      = (const float*)d_in[15];
  const float* b2      = (const float*)d_in[16];
  const float* g1      = (const float*)d_in[17];
  const float* be1     = (const float*)d_in[18];
  const float* g2      = (const float*)d_in[19];
  const float* be2     = (const float*)d_in[20];
  const float* Wout    = (const float*)d_in[21];
  const float* bout    = (const float*)d_in[22];
  float* out = (float*)d_out;

  static bool s_init = false;
  static float *pLB, *pK, *pV, *pQ, *pSC, *pOB, *pCOMB, *pATT, *pXA,
               *pCUR, *pSP, *pFFH, *pFFO, *pW;
  if (!s_init) {
    cudaGetSymbolAddress((void**)&pLB,   g_LB);
    cudaGetSymbolAddress((void**)&pK,    g_k);
    cudaGetSymbolAddress((void**)&pV,    g_v);
    cudaGetSymbolAddress((void**)&pQ,    g_q);
    cudaGetSymbolAddress((void**)&pSC,   g_sc);
    cudaGetSymbolAddress((void**)&pOB,   g_ob);
    cudaGetSymbolAddress((void**)&pCOMB, g_comb);
    cudaGetSymbolAddress((void**)&pATT,  g_att);
    cudaGetSymbolAddress((void**)&pXA,   g_xa);
    cudaGetSymbolAddress((void**)&pCUR,  g_cur);
    cudaGetSymbolAddress((void**)&pSP,   g_sp);
    cudaGetSymbolAddress((void**)&pFFH,  g_ffh);
    cudaGetSymbolAddress((void**)&pFFO,  g_ffo);
    cudaGetSymbolAddress((void**)&pW,    g_w);
    s_init = true;
  }

  // split-K GEMM launcher: prefill bias, accumulate atomically
  auto gemm = [](const float* A, const float* W, const float* b, float* C,
                 int M, int N, int K, int lda, int ks, int relu) {
    if (ks > 1) {
      int t4 = (M * N) >> 2;
      k_fill<<<(t4 + 255) / 256, 256>>>(C, b, N >> 2, t4);
      k_gemm_nn<<<dim3(N / 128, M / 128, ks), 256>>>(A, W, nullptr, C,
                                                     N, K, lda, N, N, 0, 0);
      if (relu) k_relu<<<(t4 + 255) / 256, 256>>>(C, t4);
    } else {
      k_gemm_nn<<<dim3(N / 128, M / 128, 1), 256>>>(A, W, b, C,
                                                    N, K, lda, N, N, relu, 0);
    }
  };

  k_embed<<<CT, 256>>>(src, emb, pLB);

  for (int l = 0; l < CL; l++) {
    int n = l + 1;
    k_lw<<<1, 32>>>(layer_w + (size_t)l * (CL + 1), n, pW);

    gemm(pLB, Wq + (size_t)l * CD * CD, bq + (size_t)l * CD, pQ,
         CT, CD, CD, CD, 8, 0);
    int ksv = (n == 1) ? 8 : (n == 2) ? 4 : (n <= 7) ? 2 : 1;
    gemm(pLB, Wk + (size_t)l * CD * CD, bk + (size_t)l * CD, pK,
         n * CT, CD, CD, CD, ksv, 0);
    gemm(pLB, Wv + (size_t)l * CD * CD, bv + (size_t)l * CD, pV,
         n * CT, CD, CD, CD, ksv, 0);

    k_gemm_scores<<<dim3(2, 2, n * 16), 256>>>(pQ, pK, pSC);
    k_softmax<<<n * 16 * CS, 256>>>(pSC);
    k_gemm_pv<<<dim3(1, 2, n * 16), 256>>>(pSC, pV, pOB);
    k_combine<<<(CT * CD) / 256, 256>>>(pOB, pW, n, pCOMB);

    gemm(pCOMB, Wo + (size_t)l * CD * CD, bo + (size_t)l * CD, pATT,
         CT, CD, CD, CD, 8, 0);
    k_addln<<<CT, 256>>>(pLB, pATT, g1 + (size_t)l * CD, be1 + (size_t)l * CD,
                         pXA, nullptr);

    gemm(pXA, Wsnn + (size_t)l * CD * CD, bsnn + (size_t)l * CD, pCUR,
         CT, CD, CD, CD, 8, 0);
    k_snn<<<CB, 1024>>>(pCUR, pSP);

    gemm(pSP, W1 + (size_t)l * CD * CFF, b1 + (size_t)l * CFF, pFFH,
         CT, CFF, CD, CD, 4, 1);
    gemm(pFFH, W2 + (size_t)l * CFF * CD, b2 + (size_t)l * CD, pFFO,
         CT, CD, CFF, CFF, 8, 0);

    k_addln<<<CT, 256>>>(pXA, pFFO, g2 + (size_t)l * CD, be2 + (size_t)l * CD,
                         pLB, pLB + (size_t)(l + 1) * CT * CD);
  }

  // logits = x @ Wout + bout, written transposed to [B,S,V]
  k_gemm_nn<<<dim3((CV + 127) / 128, CT / 128, 1), 256>>>(pLB, Wout, bout, out,
                                                          CV, CD, CD, CV, CV, 0, 1);
}

// round 10
// speedup vs baseline: 2.1811x; 1.4566x over previous
#include <cuda_runtime.h>
#include <cuda_bf16.h>
#include <math.h>
#include <stdint.h>
#include <stddef.h>

typedef unsigned long long ull;

// ---------------- problem constants ----------------
constexpr int CB  = 2;
constexpr int CS  = 256;
constexpr int CD  = 1024;
constexpr int CH  = 8;
constexpr int CHD = 128;
constexpr int CL  = 16;
constexpr int CFF = 2048;
constexpr int CV  = 50257;
constexpr int CVP = 50304;     // padded to 128
constexpr int CT  = CS * CB;   // 512 tokens, row r = s*CB + b
constexpr float ATT_SCALE = 0.08838834764831845f;  // 128^-0.5
constexpr int HM_SMEM = 2 * 40960;                 // double-buffered A2+B2 tiles (80KB)

// ---------------- static device scratch ----------------
__device__ __align__(16) float g_LB[(size_t)(CL + 1) * CT * CD];
__device__ __align__(16) float g_k [(size_t)CL * CT * CD];
__device__ __align__(16) float g_v [(size_t)CL * CT * CD];
__device__ __align__(16) float g_q [CT * CD];
__device__ __align__(16) float g_sc[(size_t)CL * 16 * CS * CS];
__device__ __align__(16) float g_ob[(size_t)CL * 16 * CS * CHD];
__device__ __align__(16) float g_comb[CT * CD];
__device__ __align__(16) float g_att [CT * CD];
__device__ __align__(16) float g_xa  [CT * CD];
__device__ __align__(16) float g_cur [CT * CD];
__device__ __align__(16) float g_sp  [CT * CD];
__device__ __align__(16) float g_ffh [CT * CFF];
__device__ __align__(16) float g_ffo [CT * CD];
__device__ float g_w [CL + 1];
// bf16 hi/lo split images, plane-major: [split][rows][K]  (16B-aligned for cp.async)
__device__ __align__(16) __nv_bfloat16 g_a2[(size_t)2 * 8192 * 1024];
__device__ __align__(16) __nv_bfloat16 g_b2[(size_t)2 * CVP * 1024];

// ---------------- helpers ----------------
__device__ __forceinline__ uint32_t smem_u32(const void* p) {
  uint32_t a;
  asm("{ .reg .u64 t; cvta.to.shared.u64 t, %1; cvt.u32.u64 %0, t; }" : "=r"(a) : "l"(p));
  return a;
}
__device__ __forceinline__ ull pk2(float x, float y) {
  ull r; asm("mov.b64 %0,{%1,%2};" : "=l"(r) : "f"(x), "f"(y)); return r;
}
__device__ __forceinline__ void upk2(ull v, float& x, float& y) {
  asm("mov.b64 {%0,%1},%2;" : "=f"(x), "=f"(y) : "l"(v));
}
__device__ __forceinline__ ull ffma2(ull a, ull b, ull c) {
  ull d; asm("fma.rn.f32x2 %0,%1,%2,%3;" : "=l"(d) : "l"(a), "l"(b), "l"(c)); return d;
}
__device__ __forceinline__ uint32_t pkbf(float x0, float x1, float& r0, float& r1) {
  __nv_bfloat16 b0 = __float2bfloat16(x0), b1 = __float2bfloat16(x1);
  uint32_t pk;
  asm("mov.b32 %0,{%1,%2};" : "=r"(pk)
      : "h"(*(unsigned short*)&b0), "h"(*(unsigned short*)&b1));
  r0 = x0 - __bfloat162float(b0);
  r1 = x1 - __bfloat162float(b1);
  return pk;
}

#define LDMX4(r, a) \
  asm volatile("ldmatrix.sync.aligned.m8n8.x4.shared.b16 {%0,%1,%2,%3}, [%4];" \
    : "=r"((r)[0]), "=r"((r)[1]), "=r"((r)[2]), "=r"((r)[3]) : "r"(a))

__device__ __forceinline__ void mma16816(float* c, const uint32_t* a, const uint32_t* b) {
  asm volatile("mma.sync.aligned.m16n8k16.row.col.f32.bf16.bf16.f32 "
    "{%0,%1,%2,%3}, {%4,%5,%6,%7}, {%8,%9}, {%0,%1,%2,%3};"
    : "+f"(c[0]), "+f"(c[1]), "+f"(c[2]), "+f"(c[3])
    : "r"(a[0]), "r"(a[1]), "r"(a[2]), "r"(a[3]), "r"(b[0]), "r"(b[1]));
}

// =======================================================================
// hi/lo split-image builders. Plain row-major planes: img[s][row][K].
// =======================================================================
__global__ void k_splitA2(const float* __restrict__ A, __nv_bfloat16* __restrict__ img,
                          int K, int total /* M*K/2 */)
{
  int idx = blockIdx.x * 256 + threadIdx.x;
  if (idx >= total) return;
  size_t planeA = (size_t)total * 2;
  int kh = K >> 1;
  int m = idx / kh, kp = idx - m * kh;
  int k = kp * 2;
  float2 v = *(const float2*)(A + (size_t)m * K + k);
  float r0, r1, d0, d1;
  uint32_t hp = pkbf(v.x, v.y, r0, r1);
  uint32_t lp = pkbf(r0, r1, d0, d1);
  *(uint32_t*)(img + (size_t)m * K + k) = hp;
  *(uint32_t*)(img + planeA + (size_t)m * K + k) = lp;
}

// W is [K][N] row-major; image is [n][k] (transposed) per split plane.
__global__ void k_splitB2(const float* __restrict__ W, __nv_bfloat16* __restrict__ img,
                          int N, int Npad, int K)
{
  __shared__ float sT[64][129];
  int t = threadIdx.x;
  int n0 = blockIdx.x * 128, k0 = blockIdx.y * 64;
  size_t planeB = (size_t)Npad * K;
  for (int i = t; i < 64 * 128; i += 256) {
    int kk = i >> 7, nn = i & 127;
    int n = n0 + nn;
    sT[kk][nn] = (n < N) ? W[(size_t)(k0 + kk) * N + n] : 0.f;
  }
  __syncthreads();
  for (int i = t; i < 128 * 32; i += 256) {
    int r = i >> 5, kp = i & 31;
    float r0, r1, d0, d1;
    uint32_t hp = pkbf(sT[2 * kp][r], sT[2 * kp + 1][r], r0, r1);
    uint32_t lp = pkbf(r0, r1, d0, d1);
    size_t off = (size_t)(n0 + r) * K + k0 + 2 * kp;
    *(uint32_t*)(img + off) = hp;
    *(uint32_t*)(img + planeB + off) = lp;
  }
}

// =======================================================================
// HMMA bf16-split GEMM: 128x128 tile, k-chunk 32, cp.async double buffer.
// 8 warps as 2(m)x4(n); warp tile 64x32 = 4x4 m16n8 mma tiles.
// ASPL=2: products hi*hi + hi*lo + lo*hi.  ASPL=1 (exact A): hi*hi + hi*lo.
// Split-K via blockIdx.z with atomicAdd epilogue (C pre-filled with bias).
// =======================================================================
template<int ASPL>
__global__ void __launch_bounds__(256, 1) k_hmma(
    const __nv_bfloat16* __restrict__ Aimg, const __nv_bfloat16* __restrict__ Bimg,
    const float* __restrict__ bias, float* __restrict__ C,
    int Mimg, int N, int Npad, int K, int nck, int ldc,
    int relu, int perm, int atomic)
{
  extern __shared__ char sm[];
  const int t = threadIdx.x, l = t & 31, wid = t >> 5;
  const int wm = wid >> 2, wn = wid & 3;
  const int m0 = blockIdx.y * 128, n0 = blockIdx.x * 128;
  const int ck0 = blockIdx.z * nck;
  const size_t planeA = (size_t)Mimg * K, planeB = (size_t)Npad * K;
  uint32_t sbase = smem_u32(sm);

  float acc[4][4][4];
#pragma unroll
  for (int a = 0; a < 4; a++)
#pragma unroll
    for (int b = 0; b < 4; b++)
#pragma unroll
      for (int c = 0; c < 4; c++) acc[a][b][c] = 0.f;

  auto load_chunk = [&](int buf, int ck) {
    int kc = ck * 32;
#pragma unroll
    for (int j = 0; j < 8; j++) {
      int cid = t + j * 256;
      int mat = cid >> 10;           // 0 = A, 1 = B
      int s   = (cid >> 9) & 1;
      int row = (cid >> 2) & 127;
      int c16 = cid & 3;
      const __nv_bfloat16* src = (mat == 0)
        ? Aimg + (size_t)s * planeA + (size_t)(m0 + row) * K + kc + c16 * 8
        : Bimg + (size_t)s * planeB + (size_t)(n0 + row) * K + kc + c16 * 8;
      uint32_t dst = sbase + buf * 40960 + mat * 20480 + s * 10240 + row * 80 + c16 * 16;
      asm volatile("cp.async.cg.shared.global [%0], [%1], 16;" :: "r"(dst), "l"(src));
    }
    asm volatile("cp.async.commit_group;" ::: "memory");
  };

  load_chunk(0, ck0);
  const int krow = l & 15, khalf = l >> 4;

  for (int ic = 0; ic < nck; ic++) {
    int buf = ic & 1;
    if (ic + 1 < nck) {
      load_chunk(buf ^ 1, ck0 + ic + 1);
      asm volatile("cp.async.wait_group 1;" ::: "memory");
    } else {
      asm volatile("cp.async.wait_group 0;" ::: "memory");
    }
    __syncthreads();

    uint32_t abase = sbase + buf * 40960;
    uint32_t bbase = abase + 20480;
#pragma unroll
    for (int ks = 0; ks < 2; ks++) {
      uint32_t koff = (uint32_t)(ks * 16 + khalf * 8) * 2;
      uint32_t af[ASPL][4][4];
#pragma unroll
      for (int s = 0; s < ASPL; s++)
#pragma unroll
        for (int mt = 0; mt < 4; mt++) {
          uint32_t addr = abase + s * 10240 + (uint32_t)(wm * 64 + mt * 16 + krow) * 80 + koff;
          LDMX4(af[s][mt], addr);
        }
#pragma unroll
      for (int sb = 0; sb < 2; sb++) {
        uint32_t bfr[4][2];
#pragma unroll
        for (int nt = 0; nt < 2; nt++) {
          uint32_t r[4];
          uint32_t addr = bbase + sb * 10240 + (uint32_t)(wn * 32 + nt * 16 + krow) * 80 + koff;
          LDMX4(r, addr);
          bfr[2 * nt][0]     = r[0]; bfr[2 * nt][1]     = r[2];
          bfr[2 * nt + 1][0] = r[1]; bfr[2 * nt + 1][1] = r[3];
        }
#pragma unroll
        for (int sa = 0; sa < ASPL; sa++) {
          if (sa + sb > 1) continue;   // drop lo*lo class terms
#pragma unroll
          for (int mt = 0; mt < 4; mt++)
#pragma unroll
            for (int g = 0; g < 4; g++)
              mma16816(acc[mt][g], af[sa][mt], bfr[g]);
        }
      }
    }
    __syncthreads();
  }

  // ---- epilogue ----
  const int gid = l >> 2, q = l & 3;
#pragma unroll
  for (int mt = 0; mt < 4; mt++) {
#pragma unroll
    for (int g = 0; g < 4; g++) {
      int mr = m0 + wm * 64 + mt * 16 + gid;
      int nc = n0 + wn * 32 + g * 8 + q * 2;
      const float* a = acc[mt][g];
#pragma unroll
      for (int h = 0; h < 2; h++) {
        int m = mr + h * 8;
        int crow = perm ? ((m & 1) * CS + (m >> 1)) : m;
        float* cp = C + (size_t)crow * ldc;
        float v0 = a[2 * h + 0], v1 = a[2 * h + 1];
        if (atomic) {
          if (nc < N)     atomicAdd(cp + nc, v0);
          if (nc + 1 < N) atomicAdd(cp + nc + 1, v1);
        } else {
          if (nc < N)     { float x = v0 + bias[nc];     if (relu) x = fmaxf(x, 0.f); cp[nc] = x; }
          if (nc + 1 < N) { float x = v1 + bias[nc + 1]; if (relu) x = fmaxf(x, 0.f); cp[nc + 1] = x; }
        }
      }
    }
  }
}

// =======================================================================
// SIMT fp32 SGEMM (exact) — used for SNN current projection + attention.
// =======================================================================
template<bool TRANSB>
__device__ __forceinline__ void gemm_core(
    const float* __restrict__ A, const float* __restrict__ B,
    const float* __restrict__ bias, float* __restrict__ C,
    int N, int lda, int ldb, int ldc,
    int kt0, int nkt, float alpha, int relu, int perm, int atomic)
{
  __shared__ float As[2][16][136];
  __shared__ float Bs[2][16][136];

  const int t  = threadIdx.x;
  const int m0 = blockIdx.y * 128;
  const int n0 = blockIdx.x * 128;
  const int tm = t >> 4, tn = t & 15;
  const int lr = t >> 2;
  const int lk = (t & 3) << 2;
  const int kr = t >> 5;
  const int n4 = (t & 31) << 2;

  ull acc2[8][4];
#pragma unroll
  for (int i = 0; i < 8; i++)
#pragma unroll
    for (int j = 0; j < 4; j++) acc2[i][j] = 0ull;

  float4 pa0, pa1, pb0, pb1;
  auto ldA = [&](int kt) {
    const float* p = A + (size_t)(m0 + lr) * lda + kt * 16 + lk;
    pa0 = *(const float4*)p;
    pa1 = *(const float4*)(p + (size_t)64 * lda);
  };
  auto stA = [&](int s) {
    As[s][lk + 0][lr] = pa0.x; As[s][lk + 1][lr] = pa0.y;
    As[s][lk + 2][lr] = pa0.z; As[s][lk + 3][lr] = pa0.w;
    As[s][lk + 0][lr + 64] = pa1.x; As[s][lk + 1][lr + 64] = pa1.y;
    As[s][lk + 2][lr + 64] = pa1.z; As[s][lk + 3][lr + 64] = pa1.w;
  };
  auto ldB = [&](int kt) {
    if (TRANSB) {
      const float* p = B + (size_t)(n0 + lr) * ldb + kt * 16 + lk;
      pb0 = *(const float4*)p;
      pb1 = *(const float4*)(p + (size_t)64 * ldb);
    } else {
      const float* p = B + (size_t)(kt * 16 + kr) * ldb + n0 + n4;
      pb0 = *(const float4*)p;
      pb1 = *(const float4*)(p + (size_t)8 * ldb);
    }
  };
  auto stB = [&](int s) {
    if (TRANSB) {
      Bs[s][lk + 0][lr] = pb0.x; Bs[s][lk + 1][lr] = pb0.y;
      Bs[s][lk + 2][lr] = pb0.z; Bs[s][lk + 3][lr] = pb0.w;
      Bs[s][lk + 0][lr + 64] = pb1.x; Bs[s][lk + 1][lr + 64] = pb1.y;
      Bs[s][lk + 2][lr + 64] = pb1.z; Bs[s][lk + 3][lr + 64] = pb1.w;
    } else {
      *(float4*)&Bs[s][kr][n4]     = pb0;
      *(float4*)&Bs[s][kr + 8][n4] = pb1;
    }
  };

  ldA(kt0); ldB(kt0); stA(0); stB(0);
  __syncthreads();

  for (int it = 0; it < nkt; it++) {
    int cur = it & 1;
    if (it + 1 < nkt) { ldA(kt0 + it + 1); ldB(kt0 + it + 1); }
#pragma unroll
    for (int k = 0; k < 16; k++) {
      float4 a0 = *(const float4*)&As[cur][k][tm * 8];
      float4 a1 = *(const float4*)&As[cur][k][tm * 8 + 4];
      ulonglong2 q0 = *(const ulonglong2*)&Bs[cur][k][tn * 8];
      ulonglong2 q1 = *(const ulonglong2*)&Bs[cur][k][tn * 8 + 4];
      ull bb[4] = { q0.x, q0.y, q1.x, q1.y };
      float av[8] = { a0.x, a0.y, a0.z, a0.w, a1.x, a1.y, a1.z, a1.w };
#pragma unroll
      for (int i = 0; i < 8; i++) {
        ull aa = pk2(av[i], av[i]);
#pragma unroll
        for (int j = 0; j < 4; j++)
          acc2[i][j] = ffma2(aa, bb[j], acc2[i][j]);
      }
    }
    if (it + 1 < nkt) { stA(cur ^ 1); stB(cur ^ 1); }
    __syncthreads();
  }

#pragma unroll
  for (int i = 0; i < 8; i++) {
    int m = m0 + tm * 8 + i;
    int crow = perm ? ((m & 1) * CS + (m >> 1)) : m;
    float* cp = C + (size_t)crow * ldc + n0 + tn * 8;
    float vals[8];
#pragma unroll
    for (int j4 = 0; j4 < 4; j4++) upk2(acc2[i][j4], vals[2 * j4], vals[2 * j4 + 1]);
    if (atomic) {
#pragma unroll
      for (int j = 0; j < 8; j++) atomicAdd(cp + j, vals[j] * alpha);
    } else {
#pragma unroll
      for (int j = 0; j < 8; j++) {
        float v = vals[j] * alpha;
        if (bias) v += bias[n0 + tn * 8 + j];
        if (relu) v = fmaxf(v, 0.f);
        cp[j] = v;
      }
    }
  }
}

__global__ void __launch_bounds__(256, 2) k_gemm_nn(
    const float* A, const float* B, const float* bias, float* C,
    int N, int K, int lda, int ldb, int ldc, int relu, int perm)
{
  int ks = gridDim.z;
  int nkt = (K >> 4) / ks;
  int kt0 = blockIdx.z * nkt;
  gemm_core<false>(A, B, bias, C, N, lda, ldb, ldc, kt0, nkt, 1.f, relu, perm, ks > 1);
}

__global__ void __launch_bounds__(256, 2) k_gemm_scores(
    const float* qb, const float* kb, float* sc)
{
  int z = blockIdx.z, bh = z & 15, slot = z >> 4;
  int b = bh >> 3, h = bh & 7;
  const float* A = qb + b * CD + h * CHD;
  const float* B = kb + (size_t)slot * CT * CD + b * CD + h * CHD;
  float* C = sc + (size_t)z * CS * CS;
  gemm_core<true>(A, B, nullptr, C, CS, CB * CD, CB * CD, CS,
                  0, CHD / 16, ATT_SCALE, 0, 0, 0);
}

__global__ void __launch_bounds__(256, 2) k_gemm_pv(
    const float* sc, const float* vb, float* ob)
{
  int z = blockIdx.z, bh = z & 15, slot = z >> 4;
  int b = bh >> 3, h = bh & 7;
  const float* A = sc + (size_t)z * CS * CS;
  const float* B = vb + (size_t)slot * CT * CD + b * CD + h * CHD;
  float* C = ob + (size_t)z * CS * CHD;
  gemm_core<false>(A, B, nullptr, C, CHD, CS, CB * CD, CHD,
                  0, CS / 16, 1.f, 0, 0, 0);
}

// ---------------- small helper kernels ----------------
__global__ void k_fill(float* __restrict__ C, const float* __restrict__ b,
                       int ncols4, int total4) {
  int i = blockIdx.x * 256 + threadIdx.x;
  if (i < total4) ((float4*)C)[i] = ((const float4*)b)[i % ncols4];
}
__global__ void k_relu(float* __restrict__ p, int total4) {
  int i = blockIdx.x * 256 + threadIdx.x;
  if (i < total4) {
    float4 v = ((float4*)p)[i];
    v.x = fmaxf(v.x, 0.f); v.y = fmaxf(v.y, 0.f);
    v.z = fmaxf(v.z, 0.f); v.w = fmaxf(v.w, 0.f);
    ((float4*)p)[i] = v;
  }
}

__global__ void k_softmax(float* sc) {
  float* row = sc + (size_t)blockIdx.x * CS;
  int t = threadIdx.x;
  __shared__ float red[8];
  float v = row[t];
  float m = v;
#pragma unroll
  for (int o = 16; o > 0; o >>= 1) m = fmaxf(m, __shfl_xor_sync(~0u, m, o));
  if ((t & 31) == 0) red[t >> 5] = m;
  __syncthreads();
  float mx = red[0];
#pragma unroll
  for (int i = 1; i < 8; i++) mx = fmaxf(mx, red[i]);
  float e = expf(v - mx);
  __syncthreads();
  float s = e;
#pragma unroll
  for (int o = 16; o > 0; o >>= 1) s += __shfl_xor_sync(~0u, s, o);
  if ((t & 31) == 0) red[t >> 5] = s;
  __syncthreads();
  float tot = 0.f;
#pragma unroll
  for (int i = 0; i < 8; i++) tot += red[i];
  row[t] = e / tot;
}

__global__ void k_lw(const float* lw, int n, float* w) {
  if (threadIdx.x == 0) {
    float mx = -1e30f;
    for (int i = 0; i < n; i++) mx = fmaxf(mx, lw[i]);
    float s = 0.f, e[CL + 1];
    for (int i = 0; i < n; i++) { e[i] = expf(lw[i] - mx); s += e[i]; }
    for (int i = 0; i < n; i++) w[i] = e[i] / s;
  }
}

__global__ void k_combine(const float* __restrict__ ob,
                          const float* __restrict__ w, int n,
                          float* __restrict__ comb)
{
  int idx = blockIdx.x * 256 + threadIdx.x;
  int r = idx >> 10, c = idx & 1023;
  int s = r >> 1, b = r & 1, h = c >> 7, hd = c & 127;
  float acc = 0.f;
  for (int slot = 0; slot < n; slot++)
    acc += w[slot] * ob[((size_t)(slot * 16 + b * 8 + h) * CS + s) * CHD + hd];
  comb[idx] = acc;
}

__global__ void k_addln(const float* __restrict__ x, const float* __restrict__ res,
                        const float* __restrict__ g, const float* __restrict__ be,
                        float* __restrict__ out0, float* __restrict__ out1)
{
  int r = blockIdx.x, t = threadIdx.x;
  const float4* xr = (const float4*)(x + (size_t)r * CD);
  const float4* rr = (const float4*)(res + (size_t)r * CD);
  float4 a = xr[t], b4 = rr[t];
  float v0 = a.x + b4.x, v1 = a.y + b4.y, v2 = a.z + b4.z, v3 = a.w + b4.w;

  __shared__ float red[8];
  float s = v0 + v1 + v2 + v3;
#pragma unroll
  for (int o = 16; o > 0; o >>= 1) s += __shfl_xor_sync(~0u, s, o);
  if ((t & 31) == 0) red[t >> 5] = s;
  __syncthreads();
  float tot = 0.f;
#pragma unroll
  for (int i = 0; i < 8; i++) tot += red[i];
  float mean = tot * (1.f / CD);

  float d0 = v0 - mean, d1 = v1 - mean, d2 = v2 - mean, d3 = v3 - mean;
  float sq = d0 * d0 + d1 * d1 + d2 * d2 + d3 * d3;
  __syncthreads();
#pragma unroll
  for (int o = 16; o > 0; o >>= 1) sq += __shfl_xor_sync(~0u, sq, o);
  if ((t & 31) == 0) red[t >> 5] = sq;
  __syncthreads();
  float vs = 0.f;
#pragma unroll
  for (int i = 0; i < 8; i++) vs += red[i];
  float rstd = rsqrtf(vs * (1.f / CD) + 1e-5f);

  float4 gg = ((const float4*)g)[t];
  float4 bb = ((const float4*)be)[t];
  float4 ov;
  ov.x = d0 * rstd * gg.x + bb.x;
  ov.y = d1 * rstd * gg.y + bb.y;
  ov.z = d2 * rstd * gg.z + bb.z;
  ov.w = d3 * rstd * gg.w + bb.w;
  ((float4*)(out0 + (size_t)r * CD))[t] = ov;
  if (out1) ((float4*)(out1 + (size_t)r * CD))[t] = ov;
}

__global__ void k_embed(const int* __restrict__ src, const float* __restrict__ emb,
                        float* __restrict__ x)
{
  int r = blockIdx.x, t = threadIdx.x;
  int s = r >> 1, b = r & 1;
  int tok = src[b * CS + s];
  const float* er = emb + (size_t)tok * CD;
  float* xr = x + (size_t)r * CD;
  const float SQ = 32.0f;
  const float cexp = -9.210340371976184f / (float)CD;
#pragma unroll
  for (int i = 0; i < 4; i++) {
    int d = t * 4 + i;
    int pair = d >> 1;
    float ang = (float)s * expf((float)(2 * pair) * cexp);
    float pe = (d & 1) ? cosf(ang) : sinf(ang);
    xr[d] = er[d] * SQ + pe;
  }
}

__global__ void k_snn(const float* __restrict__ cur, float* __restrict__ sp) {
  int b = blockIdx.x, t = threadIdx.x;
  __shared__ float red[32];
  __shared__ float ssum;
  float mem = 0.f, thr = 1.0f;
  for (int s = 0; s < CS; s++) {
    float v = mem;
#pragma unroll
    for (int o = 16; o > 0; o >>= 1) v += __shfl_xor_sync(~0u, v, o);
    if ((t & 31) == 0) red[t >> 5] = v;
    __syncthreads();
    if (t < 32) {
      float w = red[t];
#pragma unroll
      for (int o = 16; o > 0; o >>= 1) w += __shfl_xor_sync(~0u, w, o);
      if (t == 0) ssum = w;
    }
    __syncthreads();
    float c = cur[(size_t)(s * CB + b) * CD + t] - 0.1f * ssum;
    mem = 0.9f * mem + c;
    float spk = (mem >= thr) ? 1.f : 0.f;
    mem -= spk * thr;
    thr = 0.9f * thr + 0.1f * spk;
    sp[(size_t)(s * CB + b) * CD + t] = spk;
    __syncthreads();
  }
}

// =======================================================================
extern "C" void kernel_launch(void* const* d_in, const int* in_sizes, int n_in,
                              void* d_out, int out_size)
{
  (void)in_sizes; (void)n_in; (void)out_size;
  const int*   src     = (const int*)  d_in[0];
  const float* emb     = (const float*)d_in[1];
  const float* Wq      = (const float*)d_in[2];
  const float* bq      = (const float*)d_in[3];
  const float* Wk      = (const float*)d_in[4];
  const float* bk      = (const float*)d_in[5];
  const float* Wv      = (const float*)d_in[6];
  const float* bv      = (const float*)d_in[7];
  const float* Wo      = (const float*)d_in[8];
  const float* bo      = (const float*)d_in[9];
  const float* layer_w = (const float*)d_in[10];
  const float* Wsnn    = (const float*)d_in[11];
  const float* bsnn    = (const float*)d_in[12];
  const float* W1      = (const float*)d_in[13];
  const float* b1      = (const float*)d_in[14];
  const float* W2      = (const float*)d_in[15];
  const float* b2      = (const float*)d_in[16];
  const float* g1      = (const float*)d_in[17];
  const float* be1     = (const float*)d_in[18];
  const float* g2      = (const float*)d_in[19];
  const float* be2     = (const float*)d_in[20];
  const float* Wout    = (const float*)d_in[21];
  const float* bout    = (const float*)d_in[22];
  float* out = (float*)d_out;

  static bool s_init = false;
  static float *pLB, *pK, *pV, *pQ, *pSC, *pOB, *pCOMB, *pATT, *pXA,
               *pCUR, *pSP, *pFFH, *pFFO, *pW;
  static __nv_bfloat16 *pA2, *pB2;
  if (!s_init) {
    cudaGetSymbolAddress((void**)&pLB,   g_LB);
    cudaGetSymbolAddress((void**)&pK,    g_k);
    cudaGetSymbolAddress((void**)&pV,    g_v);
    cudaGetSymbolAddress((void**)&pQ,    g_q);
    cudaGetSymbolAddress((void**)&pSC,   g_sc);
    cudaGetSymbolAddress((void**)&pOB,   g_ob);
    cudaGetSymbolAddress((void**)&pCOMB, g_comb);
    cudaGetSymbolAddress((void**)&pATT,  g_att);
    cudaGetSymbolAddress((void**)&pXA,   g_xa);
    cudaGetSymbolAddress((void**)&pCUR,  g_cur);
    cudaGetSymbolAddress((void**)&pSP,   g_sp);
    cudaGetSymbolAddress((void**)&pFFH,  g_ffh);
    cudaGetSymbolAddress((void**)&pFFO,  g_ffo);
    cudaGetSymbolAddress((void**)&pW,    g_w);
    cudaGetSymbolAddress((void**)&pA2,   g_a2);
    cudaGetSymbolAddress((void**)&pB2,   g_b2);
    cudaFuncSetAttribute(k_hmma<2>, cudaFuncAttributeMaxDynamicSharedMemorySize, HM_SMEM);
    cudaFuncSetAttribute(k_hmma<1>, cudaFuncAttributeMaxDynamicSharedMemorySize, HM_SMEM);
    s_init = true;
  }

  auto splitA = [&](const float* A, int M, int K) {
    int tot = M * K / 2;
    k_splitA2<<<(tot + 255) / 256, 256>>>(A, pA2, K, tot);
  };
  auto hgemm = [&](const float* W, const float* bias, float* C,
                   int M, int Mimg, int Nact, int Npad, int K,
                   int ks, int relu, int perm, int aspl) {
    k_splitB2<<<dim3(Npad / 128, K / 64), 256>>>(W, pB2, Nact, Npad, K);
    int chunks = K >> 5;
    if (ks > 1) {
      int t4 = (M * Nact) >> 2;
      k_fill<<<(t4 + 255) / 256, 256>>>(C, bias, Nact >> 2, t4);
      if (aspl == 1)
        k_hmma<1><<<dim3(Npad / 128, M / 128, ks), 256, HM_SMEM>>>(
            pA2, pB2, nullptr, C, Mimg, Nact, Npad, K, chunks / ks, Nact, 0, 0, 1);
      else
        k_hmma<2><<<dim3(Npad / 128, M / 128, ks), 256, HM_SMEM>>>(
            pA2, pB2, nullptr, C, Mimg, Nact, Npad, K, chunks / ks, Nact, 0, 0, 1);
      if (relu) k_relu<<<(t4 + 255) / 256, 256>>>(C, t4);
    } else {
      if (aspl == 1)
        k_hmma<1><<<dim3(Npad / 128, M / 128, 1), 256, HM_SMEM>>>(
            pA2, pB2, bias, C, Mimg, Nact, Npad, K, chunks, Nact, relu, perm, 0);
      else
        k_hmma<2><<<dim3(Npad / 128, M / 128, 1), 256, HM_SMEM>>>(
            pA2, pB2, bias, C, Mimg, Nact, Npad, K, chunks, Nact, relu, perm, 0);
    }
  };

  k_embed<<<CT, 256>>>(src, emb, pLB);

  for (int l = 0; l < CL; l++) {
    int n = l + 1;
    k_lw<<<1, 32>>>(layer_w + (size_t)l * (CL + 1), n, pW);

    // one A image over all n source slots serves Q (prefix rows) and K/V
    splitA(pLB, n * CT, CD);
    hgemm(Wq + (size_t)l * CD * CD, bq + (size_t)l * CD, pQ,
          CT, n * CT, CD, CD, CD, 4, 0, 0, 2);
    int ksv = (n == 1) ? 4 : (n == 2) ? 2 : 1;
    hgemm(Wk + (size_t)l * CD * CD, bk + (size_t)l * CD, pK,
          n * CT, n * CT, CD, CD, CD, ksv, 0, 0, 2);
    hgemm(Wv + (size_t)l * CD * CD, bv + (size_t)l * CD, pV,
          n * CT, n * CT, CD, CD, CD, ksv, 0, 0, 2);

    k_gemm_scores<<<dim3(2, 2, n * 16), 256>>>(pQ, pK, pSC);
    k_softmax<<<n * 16 * CS, 256>>>(pSC);
    k_gemm_pv<<<dim3(1, 2, n * 16), 256>>>(pSC, pV, pOB);
    k_combine<<<(CT * CD) / 256, 256>>>(pOB, pW, n, pCOMB);

    splitA(pCOMB, CT, CD);
    hgemm(Wo + (size_t)l * CD * CD, bo + (size_t)l * CD, pATT,
          CT, CT, CD, CD, CD, 4, 0, 0, 2);
    k_addln<<<CT, 256>>>(pLB, pATT, g1 + (size_t)l * CD, be1 + (size_t)l * CD,
                         pXA, nullptr);

    // SNN current projection: exact fp32 SIMT (feeds hard spike threshold)
    {
      int t4 = (CT * CD) >> 2;
      k_fill<<<(t4 + 255) / 256, 256>>>(pCUR, bsnn + (size_t)l * CD, CD >> 2, t4);
      k_gemm_nn<<<dim3(8, 4, 8), 256>>>(pXA, Wsnn + (size_t)l * CD * CD, nullptr, pCUR,
                                        CD, CD, CD, CD, CD, 0, 0);
    }
    k_snn<<<CB, 1024>>>(pCUR, pSP);

    splitA(pSP, CT, CD);   // spikes are 0/1 -> exactly bf16: aspl=1
    hgemm(W1 + (size_t)l * CD * CFF, b1 + (size_t)l * CFF, pFFH,
          CT, CT, CFF, CFF, CD, 2, 1, 0, 1);
    splitA(pFFH, CT, CFF);
    hgemm(W2 + (size_t)l * CFF * CD, b2 + (size_t)l * CD, pFFO,
          CT, CT, CD, CD, CFF, 4, 0, 0, 2);

    k_addln<<<CT, 256>>>(pXA, pFFO, g2 + (size_t)l * CD, be2 + (size_t)l * CD,
                         pLB, pLB + (size_t)(l + 1) * CT * CD);
  }

  // logits = x @ Wout + bout -> [B,S,V] (perm)
  splitA(pLB, CT, CD);
  hgemm(Wout, bout, out, CT, CT, CV, CVP, CD, 1, 0, 1, 2);
}

// round 14
// speedup vs baseline: 2.3820x; 1.0921x over previous
#include <cuda_runtime.h>
#include <cuda_bf16.h>
#include <math.h>
#include <stdint.h>
#include <stddef.h>

typedef unsigned long long ull;

// ---------------- problem constants ----------------
constexpr int CB  = 2;
constexpr int CS  = 256;
constexpr int CD  = 1024;
constexpr int CH  = 8;
constexpr int CHD = 128;
constexpr int CL  = 16;
constexpr int CFF = 2048;
constexpr int CV  = 50257;
constexpr int CVP = 50304;     // padded to 128
constexpr int CT  = CS * CB;   // 512 tokens, row r = s*CB + b
constexpr float ATT_SCALE = 0.08838834764831845f;  // 128^-0.5
constexpr int HM_SMEM = 2 * 40960;                 // double-buffered A2+B2 tiles (80KB)

// weight-image layout (bf16 elements)
constexpr size_t W_CDCD   = (size_t)2 * CD * CD;            // 2M per CDxCD weight
constexpr size_t W_BASE1  = (size_t)64 * W_CDCD;            // after Wq/Wk/Wv/Wo x16
constexpr size_t W_FFSZ   = (size_t)2 * CFF * CD;           // 4M per FF weight
constexpr size_t W_BASE2  = W_BASE1 + (size_t)CL * W_FFSZ;
constexpr size_t W_BASEO  = W_BASE2 + (size_t)CL * W_FFSZ;
constexpr size_t W_TOTAL  = W_BASEO + (size_t)2 * CVP * CD;

// ---------------- static device scratch ----------------
__device__ __align__(16) float g_LB[(size_t)(CL + 1) * CT * CD];
__device__ __align__(16) float g_k [(size_t)CL * CT * CD];
__device__ __align__(16) float g_v [(size_t)CL * CT * CD];
__device__ __align__(16) float g_q [CT * CD];
__device__ __align__(16) float g_sc[(size_t)CL * 16 * CS * CS];
__device__ __align__(16) float g_ob[(size_t)CL * 16 * CS * CHD];
__device__ __align__(16) float g_comb[CT * CD];
__device__ __align__(16) float g_att [CT * CD];
__device__ __align__(16) float g_xa  [CT * CD];
__device__ __align__(16) float g_cur [CT * CD];
__device__ __align__(16) float g_sp  [CT * CD];
__device__ __align__(16) float g_ffh [CT * CFF];
__device__ __align__(16) float g_ffo [CT * CD];
__device__ float g_w [CL + 1];
// bf16 hi/lo split images (16B-aligned for cp.async)
__device__ __align__(16) __nv_bfloat16 g_a2[(size_t)2 * 8192 * 1024];
__device__ __align__(16) __nv_bfloat16 g_wimg[W_TOTAL];     // all weights, pre-split

// ---------------- helpers ----------------
__device__ __forceinline__ uint32_t smem_u32(const void* p) {
  uint32_t a;
  asm("{ .reg .u64 t; cvta.to.shared.u64 t, %1; cvt.u32.u64 %0, t; }" : "=r"(a) : "l"(p));
  return a;
}
__device__ __forceinline__ ull pk2(float x, float y) {
  ull r; asm("mov.b64 %0,{%1,%2};" : "=l"(r) : "f"(x), "f"(y)); return r;
}
__device__ __forceinline__ void upk2(ull v, float& x, float& y) {
  asm("mov.b64 {%0,%1},%2;" : "=f"(x), "=f"(y) : "l"(v));
}
__device__ __forceinline__ ull ffma2(ull a, ull b, ull c) {
  ull d; asm("fma.rn.f32x2 %0,%1,%2,%3;" : "=l"(d) : "l"(a), "l"(b), "l"(c)); return d;
}
__device__ __forceinline__ uint32_t pkbf(float x0, float x1, float& r0, float& r1) {
  __nv_bfloat16 b0 = __float2bfloat16(x0), b1 = __float2bfloat16(x1);
  uint32_t pk;
  asm("mov.b32 %0,{%1,%2};" : "=r"(pk)
      : "h"(*(unsigned short*)&b0), "h"(*(unsigned short*)&b1));
  r0 = x0 - __bfloat162float(b0);
  r1 = x1 - __bfloat162float(b1);
  return pk;
}

#define LDMX4(r, a) \
  asm volatile("ldmatrix.sync.aligned.m8n8.x4.shared.b16 {%0,%1,%2,%3}, [%4];" \
    : "=r"((r)[0]), "=r"((r)[1]), "=r"((r)[2]), "=r"((r)[3]) : "r"(a))

__device__ __forceinline__ void mma16816(float* c, const uint32_t* a, const uint32_t* b) {
  asm volatile("mma.sync.aligned.m16n8k16.row.col.f32.bf16.bf16.f32 "
    "{%0,%1,%2,%3}, {%4,%5,%6,%7}, {%8,%9}, {%0,%1,%2,%3};"
    : "+f"(c[0]), "+f"(c[1]), "+f"(c[2]), "+f"(c[3])
    : "r"(a[0]), "r"(a[1]), "r"(a[2]), "r"(a[3]), "r"(b[0]), "r"(b[1]));
}

// =======================================================================
// hi/lo split-image builders. Plain row-major planes: img[s][row][K].
// =======================================================================
__global__ void k_splitA2(const float* __restrict__ A, __nv_bfloat16* __restrict__ img,
                          int K, int total /* M*K/2 */)
{
  int idx = blockIdx.x * 256 + threadIdx.x;
  if (idx >= total) return;
  size_t planeA = (size_t)total * 2;
  int kh = K >> 1;
  int m = idx / kh, kp = idx - m * kh;
  int k = kp * 2;
  float2 v = *(const float2*)(A + (size_t)m * K + k);
  float r0, r1, d0, d1;
  uint32_t hp = pkbf(v.x, v.y, r0, r1);
  uint32_t lp = pkbf(r0, r1, d0, d1);
  *(uint32_t*)(img + (size_t)m * K + k) = hp;
  *(uint32_t*)(img + planeA + (size_t)m * K + k) = lp;
}

// W is [K][N] row-major; image is [n][k] (transposed) per split plane.
// Batched over layers via blockIdx.z with strides.
__global__ void k_splitB2b(const float* __restrict__ W0, __nv_bfloat16* __restrict__ img0,
                           int N, int Npad, int K, size_t wstride, size_t istride)
{
  __shared__ float sT[64][129];
  const float* W = W0 + (size_t)blockIdx.z * wstride;
  __nv_bfloat16* img = img0 + (size_t)blockIdx.z * istride;
  int t = threadIdx.x;
  int n0 = blockIdx.x * 128, k0 = blockIdx.y * 64;
  size_t planeB = (size_t)Npad * K;
  for (int i = t; i < 64 * 128; i += 256) {
    int kk = i >> 7, nn = i & 127;
    int n = n0 + nn;
    sT[kk][nn] = (n < N) ? W[(size_t)(k0 + kk) * N + n] : 0.f;
  }
  __syncthreads();
  for (int i = t; i < 128 * 32; i += 256) {
    int r = i >> 5, kp = i & 31;
    float r0, r1, d0, d1;
    uint32_t hp = pkbf(sT[2 * kp][r], sT[2 * kp + 1][r], r0, r1);
    uint32_t lp = pkbf(r0, r1, d0, d1);
    size_t off = (size_t)(n0 + r) * K + k0 + 2 * kp;
    *(uint32_t*)(img + off) = hp;
    *(uint32_t*)(img + planeB + off) = lp;
  }
}

// =======================================================================
// HMMA bf16-split GEMM: 128x128 tile, k-chunk 32, cp.async double buffer.
// 8 warps as 2(m)x4(n); warp tile 64x32 = 4x4 m16n8 mma tiles.
// ASPL=2: products hi*hi + hi*lo + lo*hi.  ASPL=1 (exact A): hi*hi + hi*lo.
// Split-K via blockIdx.z with atomicAdd epilogue (C pre-filled with bias).
// =======================================================================
template<int ASPL>
__global__ void __launch_bounds__(256, 2) k_hmma(
    const __nv_bfloat16* __restrict__ Aimg, const __nv_bfloat16* __restrict__ Bimg,
    const float* __restrict__ bias, float* __restrict__ C,
    int Mimg, int N, int Npad, int K, int nck, int ldc,
    int relu, int perm, int atomic)
{
  extern __shared__ char sm[];
  const int t = threadIdx.x, l = t & 31, wid = t >> 5;
  const int wm = wid >> 2, wn = wid & 3;
  const int m0 = blockIdx.y * 128, n0 = blockIdx.x * 128;
  const int ck0 = blockIdx.z * nck;
  const size_t planeA = (size_t)Mimg * K, planeB = (size_t)Npad * K;
  uint32_t sbase = smem_u32(sm);

  float acc[4][4][4];
#pragma unroll
  for (int a = 0; a < 4; a++)
#pragma unroll
    for (int b = 0; b < 4; b++)
#pragma unroll
      for (int c = 0; c < 4; c++) acc[a][b][c] = 0.f;

  auto load_chunk = [&](int buf, int ck) {
    int kc = ck * 32;
#pragma unroll
    for (int j = 0; j < 8; j++) {
      int cid = t + j * 256;
      int mat = cid >> 10;           // 0 = A, 1 = B
      int s   = (cid >> 9) & 1;
      int row = (cid >> 2) & 127;
      int c16 = cid & 3;
      const __nv_bfloat16* src = (mat == 0)
        ? Aimg + (size_t)s * planeA + (size_t)(m0 + row) * K + kc + c16 * 8
        : Bimg + (size_t)s * planeB + (size_t)(n0 + row) * K + kc + c16 * 8;
      uint32_t dst = sbase + buf * 40960 + mat * 20480 + s * 10240 + row * 80 + c16 * 16;
      asm volatile("cp.async.cg.shared.global [%0], [%1], 16;" :: "r"(dst), "l"(src));
    }
    asm volatile("cp.async.commit_group;" ::: "memory");
  };

  load_chunk(0, ck0);
  const int krow = l & 15, khalf = l >> 4;

  for (int ic = 0; ic < nck; ic++) {
    int buf = ic & 1;
    if (ic + 1 < nck) {
      load_chunk(buf ^ 1, ck0 + ic + 1);
      asm volatile("cp.async.wait_group 1;" ::: "memory");
    } else {
      asm volatile("cp.async.wait_group 0;" ::: "memory");
    }
    __syncthreads();

    uint32_t abase = sbase + buf * 40960;
    uint32_t bbase = abase + 20480;
#pragma unroll
    for (int ks = 0; ks < 2; ks++) {
      uint32_t koff = (uint32_t)(ks * 16 + khalf * 8) * 2;
      uint32_t af[ASPL][4][4];
#pragma unroll
      for (int s = 0; s < ASPL; s++)
#pragma unroll
        for (int mt = 0; mt < 4; mt++) {
          uint32_t addr = abase + s * 10240 + (uint32_t)(wm * 64 + mt * 16 + krow) * 80 + koff;
          LDMX4(af[s][mt], addr);
        }
#pragma unroll
      for (int sb = 0; sb < 2; sb++) {
        uint32_t bfr[4][2];
#pragma unroll
        for (int nt = 0; nt < 2; nt++) {
          uint32_t r[4];
          uint32_t addr = bbase + sb * 10240 + (uint32_t)(wn * 32 + nt * 16 + krow) * 80 + koff;
          LDMX4(r, addr);
          bfr[2 * nt][0]     = r[0]; bfr[2 * nt][1]     = r[2];
          bfr[2 * nt + 1][0] = r[1]; bfr[2 * nt + 1][1] = r[3];
        }
#pragma unroll
        for (int sa = 0; sa < ASPL; sa++) {
          if (sa + sb > 1) continue;   // drop lo*lo class terms
#pragma unroll
          for (int mt = 0; mt < 4; mt++)
#pragma unroll
            for (int g = 0; g < 4; g++)
              mma16816(acc[mt][g], af[sa][mt], bfr[g]);
        }
      }
    }
    __syncthreads();
  }

  // ---- epilogue ----
  const int gid = l >> 2, q = l & 3;
#pragma unroll
  for (int mt = 0; mt < 4; mt++) {
#pragma unroll
    for (int g = 0; g < 4; g++) {
      int mr = m0 + wm * 64 + mt * 16 + gid;
      int nc = n0 + wn * 32 + g * 8 + q * 2;
      const float* a = acc[mt][g];
#pragma unroll
      for (int h = 0; h < 2; h++) {
        int m = mr + h * 8;
        int crow = perm ? ((m & 1) * CS + (m >> 1)) : m;
        float* cp = C + (size_t)crow * ldc;
        float v0 = a[2 * h + 0], v1 = a[2 * h + 1];
        if (atomic) {
          if (nc < N)     atomicAdd(cp + nc, v0);
          if (nc + 1 < N) atomicAdd(cp + nc + 1, v1);
        } else {
          if (nc < N)     { float x = v0 + bias[nc];     if (relu) x = fmaxf(x, 0.f); cp[nc] = x; }
          if (nc + 1 < N) { float x = v1 + bias[nc + 1]; if (relu) x = fmaxf(x, 0.f); cp[nc + 1] = x; }
        }
      }
    }
  }
}

// =======================================================================
// SIMT fp32 SGEMM (exact) — used for SNN current projection + attention.
// =======================================================================
template<bool TRANSB>
__device__ __forceinline__ void gemm_core(
    const float* __restrict__ A, const float* __restrict__ B,
    const float* __restrict__ bias, float* __restrict__ C,
    int N, int lda, int ldb, int ldc,
    int kt0, int nkt, float alpha, int relu, int perm, int atomic)
{
  __shared__ float As[2][16][136];
  __shared__ float Bs[2][16][136];

  const int t  = threadIdx.x;
  const int m0 = blockIdx.y * 128;
  const int n0 = blockIdx.x * 128;
  const int tm = t >> 4, tn = t & 15;
  const int lr = t >> 2;
  const int lk = (t & 3) << 2;
  const int kr = t >> 5;
  const int n4 = (t & 31) << 2;

  ull acc2[8][4];
#pragma unroll
  for (int i = 0; i < 8; i++)
#pragma unroll
    for (int j = 0; j < 4; j++) acc2[i][j] = 0ull;

  float4 pa0, pa1, pb0, pb1;
  auto ldA = [&](int kt) {
    const float* p = A + (size_t)(m0 + lr) * lda + kt * 16 + lk;
    pa0 = *(const float4*)p;
    pa1 = *(const float4*)(p + (size_t)64 * lda);
  };
  auto stA = [&](int s) {
    As[s][lk + 0][lr] = pa0.x; As[s][lk + 1][lr] = pa0.y;
    As[s][lk + 2][lr] = pa0.z; As[s][lk + 3][lr] = pa0.w;
    As[s][lk + 0][lr + 64] = pa1.x; As[s][lk + 1][lr + 64] = pa1.y;
    As[s][lk + 2][lr + 64] = pa1.z; As[s][lk + 3][lr + 64] = pa1.w;
  };
  auto ldB = [&](int kt) {
    if (TRANSB) {
      const float* p = B + (size_t)(n0 + lr) * ldb + kt * 16 + lk;
      pb0 = *(const float4*)p;
      pb1 = *(const float4*)(p + (size_t)64 * ldb);
    } else {
      const float* p = B + (size_t)(kt * 16 + kr) * ldb + n0 + n4;
      pb0 = *(const float4*)p;
      pb1 = *(const float4*)(p + (size_t)8 * ldb);
    }
  };
  auto stB = [&](int s) {
    if (TRANSB) {
      Bs[s][lk + 0][lr] = pb0.x; Bs[s][lk + 1][lr] = pb0.y;
      Bs[s][lk + 2][lr] = pb0.z; Bs[s][lk + 3][lr] = pb0.w;
      Bs[s][lk + 0][lr + 64] = pb1.x; Bs[s][lk + 1][lr + 64] = pb1.y;
      Bs[s][lk + 2][lr + 64] = pb1.z; Bs[s][lk + 3][lr + 64] = pb1.w;
    } else {
      *(float4*)&Bs[s][kr][n4]     = pb0;
      *(float4*)&Bs[s][kr + 8][n4] = pb1;
    }
  };

  ldA(kt0); ldB(kt0); stA(0); stB(0);
  __syncthreads();

  for (int it = 0; it < nkt; it++) {
    int cur = it & 1;
    if (it + 1 < nkt) { ldA(kt0 + it + 1); ldB(kt0 + it + 1); }
#pragma unroll
    for (int k = 0; k < 16; k++) {
      float4 a0 = *(const float4*)&As[cur][k][tm * 8];
      float4 a1 = *(const float4*)&As[cur][k][tm * 8 + 4];
      ulonglong2 q0 = *(const ulonglong2*)&Bs[cur][k][tn * 8];
      ulonglong2 q1 = *(const ulonglong2*)&Bs[cur][k][tn * 8 + 4];
      ull bb[4] = { q0.x, q0.y, q1.x, q1.y };
      float av[8] = { a0.x, a0.y, a0.z, a0.w, a1.x, a1.y, a1.z, a1.w };
#pragma unroll
      for (int i = 0; i < 8; i++) {
        ull aa = pk2(av[i], av[i]);
#pragma unroll
        for (int j = 0; j < 4; j++)
          acc2[i][j] = ffma2(aa, bb[j], acc2[i][j]);
      }
    }
    if (it + 1 < nkt) { stA(cur ^ 1); stB(cur ^ 1); }
    __syncthreads();
  }

#pragma unroll
  for (int i = 0; i < 8; i++) {
    int m = m0 + tm * 8 + i;
    int crow = perm ? ((m & 1) * CS + (m >> 1)) : m;
    float* cp = C + (size_t)crow * ldc + n0 + tn * 8;
    float vals[8];
#pragma unroll
    for (int j4 = 0; j4 < 4; j4++) upk2(acc2[i][j4], vals[2 * j4], vals[2 * j4 + 1]);
    if (atomic) {
#pragma unroll
      for (int j = 0; j < 8; j++) atomicAdd(cp + j, vals[j] * alpha);
    } else {
#pragma unroll
      for (int j = 0; j < 8; j++) {
        float v = vals[j] * alpha;
        if (bias) v += bias[n0 + tn * 8 + j];
        if (relu) v = fmaxf(v, 0.f);
        cp[j] = v;
      }
    }
  }
}

__global__ void __launch_bounds__(256, 2) k_gemm_nn(
    const float* A, const float* B, const float* bias, float* C,
    int N, int K, int lda, int ldb, int ldc, int relu, int perm)
{
  int ks = gridDim.z;
  int nkt = (K >> 4) / ks;
  int kt0 = blockIdx.z * nkt;
  gemm_core<false>(A, B, bias, C, N, lda, ldb, ldc, kt0, nkt, 1.f, relu, perm, ks > 1);
}

__global__ void __launch_bounds__(256, 2) k_gemm_scores(
    const float* qb, const float* kb, float* sc)
{
  int z = blockIdx.z, bh = z & 15, slot = z >> 4;
  int b = bh >> 3, h = bh & 7;
  const float* A = qb + b * CD + h * CHD;
  const float* B = kb + (size_t)slot * CT * CD + b * CD + h * CHD;
  float* C = sc + (size_t)z * CS * CS;
  gemm_core<true>(A, B, nullptr, C, CS, CB * CD, CB * CD, CS,
                  0, CHD / 16, ATT_SCALE, 0, 0, 0);
}

__global__ void __launch_bounds__(256, 2) k_gemm_pv(
    const float* sc, const float* vb, float* ob)
{
  int z = blockIdx.z, bh = z & 15, slot = z >> 4;
  int b = bh >> 3, h = bh & 7;
  const float* A = sc + (size_t)z * CS * CS;
  const float* B = vb + (size_t)slot * CT * CD + b * CD + h * CHD;
  float* C = ob + (size_t)z * CS * CHD;
  gemm_core<false>(A, B, nullptr, C, CHD, CS, CB * CD, CHD,
                  0, CS / 16, 1.f, 0, 0, 0);
}

// ---------------- small helper kernels ----------------
__global__ void k_fill(float* __restrict__ C, const float* __restrict__ b,
                       int ncols4, int total4) {
  int i = blockIdx.x * 256 + threadIdx.x;
  if (i < total4) ((float4*)C)[i] = ((const float4*)b)[i % ncols4];
}
__global__ void k_relu(float* __restrict__ p, int total4) {
  int i = blockIdx.x * 256 + threadIdx.x;
  if (i < total4) {
    float4 v = ((float4*)p)[i];
    v.x = fmaxf(v.x, 0.f); v.y = fmaxf(v.y, 0.f);
    v.z = fmaxf(v.z, 0.f); v.w = fmaxf(v.w, 0.f);
    ((float4*)p)[i] = v;
  }
}

__global__ void k_softmax(float* sc) {
  float* row = sc + (size_t)blockIdx.x * CS;
  int t = threadIdx.x;
  __shared__ float red[8];
  float v = row[t];
  float m = v;
#pragma unroll
  for (int o = 16; o > 0; o >>= 1) m = fmaxf(m, __shfl_xor_sync(~0u, m, o));
  if ((t & 31) == 0) red[t >> 5] = m;
  __syncthreads();
  float mx = red[0];
#pragma unroll
  for (int i = 1; i < 8; i++) mx = fmaxf(mx, red[i]);
  float e = expf(v - mx);
  __syncthreads();
  float s = e;
#pragma unroll
  for (int o = 16; o > 0; o >>= 1) s += __shfl_xor_sync(~0u, s, o);
  if ((t & 31) == 0) red[t >> 5] = s;
  __syncthreads();
  float tot = 0.f;
#pragma unroll
  for (int i = 0; i < 8; i++) tot += red[i];
  row[t] = e / tot;
}

__global__ void k_lw(const float* lw, int n, float* w) {
  if (threadIdx.x == 0) {
    float mx = -1e30f;
    for (int i = 0; i < n; i++) mx = fmaxf(mx, lw[i]);
    float s = 0.f, e[CL + 1];
    for (int i = 0; i < n; i++) { e[i] = expf(lw[i] - mx); s += e[i]; }
    for (int i = 0; i < n; i++) w[i] = e[i] / s;
  }
}

__global__ void k_combine(const float* __restrict__ ob,
                          const float* __restrict__ w, int n,
                          float* __restrict__ comb)
{
  int idx = blockIdx.x * 256 + threadIdx.x;
  int r = idx >> 10, c = idx & 1023;
  int s = r >> 1, b = r & 1, h = c >> 7, hd = c & 127;
  float acc = 0.f;
  for (int slot = 0; slot < n; slot++)
    acc += w[slot] * ob[((size_t)(slot * 16 + b * 8 + h) * CS + s) * CHD + hd];
  comb[idx] = acc;
}

__global__ void k_addln(const float* __restrict__ x, const float* __restrict__ res,
                        const float* __restrict__ g, const float* __restrict__ be,
                        float* __restrict__ out0, float* __restrict__ out1)
{
  int r = blockIdx.x, t = threadIdx.x;
  const float4* xr = (const float4*)(x + (size_t)r * CD);
  const float4* rr = (const float4*)(res + (size_t)r * CD);
  float4 a = xr[t], b4 = rr[t];
  float v0 = a.x + b4.x, v1 = a.y + b4.y, v2 = a.z + b4.z, v3 = a.w + b4.w;

  __shared__ float red[8];
  float s = v0 + v1 + v2 + v3;
#pragma unroll
  for (int o = 16; o > 0; o >>= 1) s += __shfl_xor_sync(~0u, s, o);
  if ((t & 31) == 0) red[t >> 5] = s;
  __syncthreads();
  float tot = 0.f;
#pragma unroll
  for (int i = 0; i < 8; i++) tot += red[i];
  float mean = tot * (1.f / CD);

  float d0 = v0 - mean, d1 = v1 - mean, d2 = v2 - mean, d3 = v3 - mean;
  float sq = d0 * d0 + d1 * d1 + d2 * d2 + d3 * d3;
  __syncthreads();
#pragma unroll
  for (int o = 16; o > 0; o >>= 1) sq += __shfl_xor_sync(~0u, sq, o);
  if ((t & 31) == 0) red[t >> 5] = sq;
  __syncthreads();
  float vs = 0.f;
#pragma unroll
  for (int i = 0; i < 8; i++) vs += red[i];
  float rstd = rsqrtf(vs * (1.f / CD) + 1e-5f);

  float4 gg = ((const float4*)g)[t];
  float4 bb = ((const float4*)be)[t];
  float4 ov;
  ov.x = d0 * rstd * gg.x + bb.x;
  ov.y = d1 * rstd * gg.y + bb.y;
  ov.z = d2 * rstd * gg.z + bb.z;
  ov.w = d3 * rstd * gg.w + bb.w;
  ((float4*)(out0 + (size_t)r * CD))[t] = ov;
  if (out1) ((float4*)(out1 + (size_t)r * CD))[t] = ov;
}

__global__ void k_embed(const int* __restrict__ src, const float* __restrict__ emb,
                        float* __restrict__ x)
{
  int r = blockIdx.x, t = threadIdx.x;
  int s = r >> 1, b = r & 1;
  int tok = src[b * CS + s];
  const float* er = emb + (size_t)tok * CD;
  float* xr = x + (size_t)r * CD;
  const float SQ = 32.0f;
  const float cexp = -9.210340371976184f / (float)CD;
#pragma unroll
  for (int i = 0; i < 4; i++) {
    int d = t * 4 + i;
    int pair = d >> 1;
    float ang = (float)s * expf((float)(2 * pair) * cexp);
    float pe = (d & 1) ? cosf(ang) : sinf(ang);
    xr[d] = er[d] * SQ + pe;
  }
}

__global__ void k_snn(const float* __restrict__ cur, float* __restrict__ sp) {
  int b = blockIdx.x, t = threadIdx.x;
  __shared__ float red[32];
  __shared__ float ssum;
  float mem = 0.f, thr = 1.0f;
  for (int s = 0; s < CS; s++) {
    float v = mem;
#pragma unroll
    for (int o = 16; o > 0; o >>= 1) v += __shfl_xor_sync(~0u, v, o);
    if ((t & 31) == 0) red[t >> 5] = v;
    __syncthreads();
    if (t < 32) {
      float w = red[t];
#pragma unroll
      for (int o = 16; o > 0; o >>= 1) w += __shfl_xor_sync(~0u, w, o);
      if (t == 0) ssum = w;
    }
    __syncthreads();
    float c = cur[(size_t)(s * CB + b) * CD + t] - 0.1f * ssum;
    mem = 0.9f * mem + c;
    float spk = (mem >= thr) ? 1.f : 0.f;
    mem -= spk * thr;
    thr = 0.9f * thr + 0.1f * spk;
    sp[(size_t)(s * CB + b) * CD + t] = spk;
    __syncthreads();
  }
}

// =======================================================================
extern "C" void kernel_launch(void* const* d_in, const int* in_sizes, int n_in,
                              void* d_out, int out_size)
{
  (void)in_sizes; (void)n_in; (void)out_size;
  const int*   src     = (const int*)  d_in[0];
  const float* emb     = (const float*)d_in[1];
  const float* Wq      = (const float*)d_in[2];
  const float* bq      = (const float*)d_in[3];
  const float* Wk      = (const float*)d_in[4];
  const float* bk      = (const float*)d_in[5];
  const float* Wv      = (const float*)d_in[6];
  const float* bv      = (const float*)d_in[7];
  const float* Wo      = (const float*)d_in[8];
  const float* bo      = (const float*)d_in[9];
  const float* layer_w = (const float*)d_in[10];
  const float* Wsnn    = (const float*)d_in[11];
  const float* bsnn    = (const float*)d_in[12];
  const float* W1      = (const float*)d_in[13];
  const float* b1      = (const float*)d_in[14];
  const float* W2      = (const float*)d_in[15];
  const float* b2      = (const float*)d_in[16];
  const float* g1      = (const float*)d_in[17];
  const float* be1     = (const float*)d_in[18];
  const float* g2      = (const float*)d_in[19];
  const float* be2     = (const float*)d_in[20];
  const float* Wout    = (const float*)d_in[21];
  const float* bout    = (const float*)d_in[22];
  float* out = (float*)d_out;

  static bool s_init = false;
  static float *pLB, *pK, *pV, *pQ, *pSC, *pOB, *pCOMB, *pATT, *pXA,
               *pCUR, *pSP, *pFFH, *pFFO, *pW;
  static __nv_bfloat16 *pA2, *pWI;
  if (!s_init) {
    cudaGetSymbolAddress((void**)&pLB,   g_LB);
    cudaGetSymbolAddress((void**)&pK,    g_k);
    cudaGetSymbolAddress((void**)&pV,    g_v);
    cudaGetSymbolAddress((void**)&pQ,    g_q);
    cudaGetSymbolAddress((void**)&pSC,   g_sc);
    cudaGetSymbolAddress((void**)&pOB,   g_ob);
    cudaGetSymbolAddress((void**)&pCOMB, g_comb);
    cudaGetSymbolAddress((void**)&pATT,  g_att);
    cudaGetSymbolAddress((void**)&pXA,   g_xa);
    cudaGetSymbolAddress((void**)&pCUR,  g_cur);
    cudaGetSymbolAddress((void**)&pSP,   g_sp);
    cudaGetSymbolAddress((void**)&pFFH,  g_ffh);
    cudaGetSymbolAddress((void**)&pFFO,  g_ffo);
    cudaGetSymbolAddress((void**)&pW,    g_w);
    cudaGetSymbolAddress((void**)&pA2,   g_a2);
    cudaGetSymbolAddress((void**)&pWI,   g_wimg);
    cudaFuncSetAttribute(k_hmma<2>, cudaFuncAttributeMaxDynamicSharedMemorySize, HM_SMEM);
    cudaFuncSetAttribute(k_hmma<1>, cudaFuncAttributeMaxDynamicSharedMemorySize, HM_SMEM);
    s_init = true;
  }

  // ---- pre-split all weights (batched over layers) ----
  k_splitB2b<<<dim3(CD / 128, CD / 64, CL), 256>>>(Wq, pWI + 0 * CL * W_CDCD,
      CD, CD, CD, (size_t)CD * CD, W_CDCD);
  k_splitB2b<<<dim3(CD / 128, CD / 64, CL), 256>>>(Wk, pWI + 1 * CL * W_CDCD,
      CD, CD, CD, (size_t)CD * CD, W_CDCD);
  k_splitB2b<<<dim3(CD / 128, CD / 64, CL), 256>>>(Wv, pWI + 2 * CL * W_CDCD,
      CD, CD, CD, (size_t)CD * CD, W_CDCD);
  k_splitB2b<<<dim3(CD / 128, CD / 64, CL), 256>>>(Wo, pWI + 3 * CL * W_CDCD,
      CD, CD, CD, (size_t)CD * CD, W_CDCD);
  k_splitB2b<<<dim3(CFF / 128, CD / 64, CL), 256>>>(W1, pWI + W_BASE1,
      CFF, CFF, CD, (size_t)CD * CFF, W_FFSZ);
  k_splitB2b<<<dim3(CD / 128, CFF / 64, CL), 256>>>(W2, pWI + W_BASE2,
      CD, CD, CFF, (size_t)CFF * CD, W_FFSZ);
  k_splitB2b<<<dim3(CVP / 128, CD / 64, 1), 256>>>(Wout, pWI + W_BASEO,
      CV, CVP, CD, 0, 0);

  auto splitA = [&](const float* A, int M, int K) {
    int tot = M * K / 2;
    k_splitA2<<<(tot + 255) / 256, 256>>>(A, pA2, K, tot);
  };
  auto hgemm = [&](const __nv_bfloat16* Wimg, const float* bias, float* C,
                   int M, int Mimg, int Nact, int Npad, int K,
                   int ks, int relu, int perm, int aspl) {
    int chunks = K >> 5;
    if (ks > 1) {
      int t4 = (M * Nact) >> 2;
      k_fill<<<(t4 + 255) / 256, 256>>>(C, bias, Nact >> 2, t4);
      if (aspl == 1)
        k_hmma<1><<<dim3(Npad / 128, M / 128, ks), 256, HM_SMEM>>>(
            pA2, Wimg, nullptr, C, Mimg, Nact, Npad, K, chunks / ks, Nact, 0, 0, 1);
      else
        k_hmma<2><<<dim3(Npad / 128, M / 128, ks), 256, HM_SMEM>>>(
            pA2, Wimg, nullptr, C, Mimg, Nact, Npad, K, chunks / ks, Nact, 0, 0, 1);
      if (relu) k_relu<<<(t4 + 255) / 256, 256>>>(C, t4);
    } else {
      if (aspl == 1)
        k_hmma<1><<<dim3(Npad / 128, M / 128, 1), 256, HM_SMEM>>>(
            pA2, Wimg, bias, C, Mimg, Nact, Npad, K, chunks, Nact, relu, perm, 0);
      else
        k_hmma<2><<<dim3(Npad / 128, M / 128, 1), 256, HM_SMEM>>>(
            pA2, Wimg, bias, C, Mimg, Nact, Npad, K, chunks, Nact, relu, perm, 0);
    }
  };

  k_embed<<<CT, 256>>>(src, emb, pLB);

  for (int l = 0; l < CL; l++) {
    int n = l + 1;
    k_lw<<<1, 32>>>(layer_w + (size_t)l * (CL + 1), n, pW);

    // one A image over all n source slots serves Q (prefix rows) and K/V
    splitA(pLB, n * CT, CD);
    hgemm(pWI + (0 * CL + l) * W_CDCD, bq + (size_t)l * CD, pQ,
          CT, n * CT, CD, CD, CD, 8, 0, 0, 2);
    int ksv = (n == 1) ? 8 : (n == 2) ? 4 : (n <= 7) ? 2 : 1;
    hgemm(pWI + (1 * CL + l) * W_CDCD, bk + (size_t)l * CD, pK,
          n * CT, n * CT, CD, CD, CD, ksv, 0, 0, 2);
    hgemm(pWI + (2 * CL + l) * W_CDCD, bv + (size_t)l * CD, pV,
          n * CT, n * CT, CD, CD, CD, ksv, 0, 0, 2);

    k_gemm_scores<<<dim3(2, 2, n * 16), 256>>>(pQ, pK, pSC);
    k_softmax<<<n * 16 * CS, 256>>>(pSC);
    k_gemm_pv<<<dim3(1, 2, n * 16), 256>>>(pSC, pV, pOB);
    k_combine<<<(CT * CD) / 256, 256>>>(pOB, pW, n, pCOMB);

    splitA(pCOMB, CT, CD);
    hgemm(pWI + (3 * CL + l) * W_CDCD, bo + (size_t)l * CD, pATT,
          CT, CT, CD, CD, CD, 8, 0, 0, 2);
    k_addln<<<CT, 256>>>(pLB, pATT, g1 + (size_t)l * CD, be1 + (size_t)l * CD,
                         pXA, nullptr);

    // SNN current projection: exact fp32 SIMT (feeds hard spike threshold)
    {
      int t4 = (CT * CD) >> 2;
      k_fill<<<(t4 + 255) / 256, 256>>>(pCUR, bsnn + (size_t)l * CD, CD >> 2, t4);
      k_gemm_nn<<<dim3(8, 4, 8), 256>>>(pXA, Wsnn + (size_t)l * CD * CD, nullptr, pCUR,
                                        CD, CD, CD, CD, CD, 0, 0);
    }
    k_snn<<<CB, 1024>>>(pCUR, pSP);

    splitA(pSP, CT, CD);   // spikes are 0/1 -> exactly bf16: aspl=1
    hgemm(pWI + W_BASE1 + (size_t)l * W_FFSZ, b1 + (size_t)l * CFF, pFFH,
          CT, CT, CFF, CFF, CD, 4, 1, 0, 1);
    splitA(pFFH, CT, CFF);
    hgemm(pWI + W_BASE2 + (size_t)l * W_FFSZ, b2 + (size_t)l * CD, pFFO,
          CT, CT, CD, CD, CFF, 8, 0, 0, 2);

    k_addln<<<CT, 256>>>(pXA, pFFO, g2 + (size_t)l * CD, be2 + (size_t)l * CD,
                         pLB, pLB + (size_t)(l + 1) * CT * CD);
  }

  // logits = x @ Wout + bout -> [B,S,V] (perm)
  splitA(pLB, CT, CD);
  hgemm(pWI + W_BASEO, bout, out, CT, CT, CV, CVP, CD, 1, 0, 1, 2);
}

// round 15
// speedup vs baseline: 2.7111x; 1.1382x over previous
#include <cuda_runtime.h>
#include <cuda_bf16.h>
#include <math.h>
#include <stdint.h>
#include <stddef.h>

typedef unsigned long long ull;
typedef __nv_bfloat16 bf16;

// ---------------- problem constants ----------------
constexpr int CB  = 2;
constexpr int CS  = 256;
constexpr int CD  = 1024;
constexpr int CH  = 8;
constexpr int CHD = 128;
constexpr int CL  = 16;
constexpr int CFF = 2048;
constexpr int CV  = 50257;
constexpr int CVP = 50304;
constexpr int CT  = CS * CB;   // 512 tokens, row r = s*CB + b
constexpr float ATT_SCALE = 0.08838834764831845f;
constexpr int HM_SMEM = 2 * 40960;   // double-buffered A2+B2 tiles (80KB)

// weight-image layout (bf16 elements)
constexpr size_t W_CDCD   = (size_t)2 * CD * CD;
constexpr size_t W_BASE1  = (size_t)64 * W_CDCD;
constexpr size_t W_FFSZ   = (size_t)2 * CFF * CD;
constexpr size_t W_BASE2  = W_BASE1 + (size_t)CL * W_FFSZ;
constexpr size_t W_BASEO  = W_BASE2 + (size_t)CL * W_FFSZ;
constexpr size_t W_TOTAL  = W_BASEO + (size_t)2 * CVP * CD;

// activation image planes
constexpr size_t PLANE_LB  = (size_t)(CL + 1) * CT * CD;       // 17 slots x 512 x 1024
constexpr size_t PLANE_TMP = (size_t)512 * 2048;
constexpr size_t QPLANE    = (size_t)16 * CS * CHD;            // 524288
constexpr size_t KPLANE    = (size_t)CL * 16 * CS * CHD;       // 8.39M
constexpr size_t PPLANE    = (size_t)CL * 16 * CS * CS;        // 16.78M

// ---------------- static device scratch ----------------
__device__ __align__(16) float g_LB[(size_t)(CL + 1) * CT * CD];
__device__ __align__(16) float g_k [(size_t)CL * CT * CD];
__device__ __align__(16) float g_v [(size_t)CL * CT * CD];
__device__ __align__(16) float g_q [CT * CD];
__device__ __align__(16) float g_sc[(size_t)CL * 16 * CS * CS];
__device__ __align__(16) float g_ob[(size_t)CL * 16 * CS * CHD];
__device__ __align__(16) float g_att [CT * CD];
__device__ __align__(16) float g_xa  [CT * CD];
__device__ __align__(16) float g_cur [CT * CD];
__device__ __align__(16) float g_ffh [CT * CFF];
__device__ __align__(16) float g_ffo [CT * CD];
__device__ float g_w [CL + 1];
// bf16 hi/lo split images (16B-aligned for cp.async)
__device__ __align__(16) bf16 g_aLB [2 * PLANE_LB];
__device__ __align__(16) bf16 g_atmp[2 * PLANE_TMP];
__device__ __align__(16) bf16 g_qi  [2 * QPLANE];
__device__ __align__(16) bf16 g_ki  [2 * KPLANE];
__device__ __align__(16) bf16 g_vi  [2 * KPLANE];
__device__ __align__(16) bf16 g_pi  [2 * PPLANE];
__device__ __align__(16) bf16 g_wimg[W_TOTAL];

// ---------------- helpers ----------------
__device__ __forceinline__ uint32_t smem_u32(const void* p) {
  uint32_t a;
  asm("{ .reg .u64 t; cvta.to.shared.u64 t, %1; cvt.u32.u64 %0, t; }" : "=r"(a) : "l"(p));
  return a;
}
__device__ __forceinline__ ull pk2(float x, float y) {
  ull r; asm("mov.b64 %0,{%1,%2};" : "=l"(r) : "f"(x), "f"(y)); return r;
}
__device__ __forceinline__ void upk2(ull v, float& x, float& y) {
  asm("mov.b64 {%0,%1},%2;" : "=f"(x), "=f"(y) : "l"(v));
}
__device__ __forceinline__ ull ffma2(ull a, ull b, ull c) {
  ull d; asm("fma.rn.f32x2 %0,%1,%2,%3;" : "=l"(d) : "l"(a), "l"(b), "l"(c)); return d;
}
__device__ __forceinline__ uint32_t pkbf(float x0, float x1, float& r0, float& r1) {
  bf16 b0 = __float2bfloat16(x0), b1 = __float2bfloat16(x1);
  uint32_t pk;
  asm("mov.b32 %0,{%1,%2};" : "=r"(pk)
      : "h"(*(unsigned short*)&b0), "h"(*(unsigned short*)&b1));
  r0 = x0 - __bfloat162float(b0);
  r1 = x1 - __bfloat162float(b1);
  return pk;
}

#define LDMX4(r, a) \
  asm volatile("ldmatrix.sync.aligned.m8n8.x4.shared.b16 {%0,%1,%2,%3}, [%4];" \
    : "=r"((r)[0]), "=r"((r)[1]), "=r"((r)[2]), "=r"((r)[3]) : "r"(a))

__device__ __forceinline__ void mma16816(float* c, const uint32_t* a, const uint32_t* b) {
  asm volatile("mma.sync.aligned.m16n8k16.row.col.f32.bf16.bf16.f32 "
    "{%0,%1,%2,%3}, {%4,%5,%6,%7}, {%8,%9}, {%0,%1,%2,%3};"
    : "+f"(c[0]), "+f"(c[1]), "+f"(c[2]), "+f"(c[3])
    : "r"(a[0]), "r"(a[1]), "r"(a[2]), "r"(a[3]), "r"(b[0]), "r"(b[1]));
}

// =======================================================================
// split-image builders
// =======================================================================
__global__ void k_splitA2(const float* __restrict__ A, bf16* __restrict__ img,
                          int K, int pairs, int rowOff, size_t plane)
{
  int idx = blockIdx.x * 256 + threadIdx.x;
  if (idx >= pairs) return;
  int kh = K >> 1;
  int m = idx / kh, kp = idx - m * kh;
  int k = kp * 2;
  float2 v = *(const float2*)(A + (size_t)m * K + k);
  float r0, r1, d0, d1;
  uint32_t hp = pkbf(v.x, v.y, r0, r1);
  uint32_t lp = pkbf(r0, r1, d0, d1);
  size_t off = (size_t)(rowOff + m) * K + k;
  *(uint32_t*)(img + off) = hp;
  *(uint32_t*)(img + plane + off) = lp;
}

__global__ void k_relusplit(const float* __restrict__ A, bf16* __restrict__ img,
                            int K, int pairs, size_t plane)
{
  int idx = blockIdx.x * 256 + threadIdx.x;
  if (idx >= pairs) return;
  int kh = K >> 1;
  int m = idx / kh, kp = idx - m * kh;
  int k = kp * 2;
  float2 v = *(const float2*)(A + (size_t)m * K + k);
  v.x = fmaxf(v.x, 0.f); v.y = fmaxf(v.y, 0.f);
  float r0, r1, d0, d1;
  uint32_t hp = pkbf(v.x, v.y, r0, r1);
  uint32_t lp = pkbf(r0, r1, d0, d1);
  size_t off = (size_t)m * K + k;
  *(uint32_t*)(img + off) = hp;
  *(uint32_t*)(img + plane + off) = lp;
}

// W [K][N] row-major -> image [n][k] per split plane, batched over layers.
__global__ void k_splitB2b(const float* __restrict__ W0, bf16* __restrict__ img0,
                           int N, int Npad, int K, size_t wstride, size_t istride)
{
  __shared__ float sT[64][129];
  const float* W = W0 + (size_t)blockIdx.z * wstride;
  bf16* img = img0 + (size_t)blockIdx.z * istride;
  int t = threadIdx.x;
  int n0 = blockIdx.x * 128, k0 = blockIdx.y * 64;
  size_t planeB = (size_t)Npad * K;
  for (int i = t; i < 64 * 128; i += 256) {
    int kk = i >> 7, nn = i & 127;
    int n = n0 + nn;
    sT[kk][nn] = (n < N) ? W[(size_t)(k0 + kk) * N + n] : 0.f;
  }
  __syncthreads();
  for (int i = t; i < 128 * 32; i += 256) {
    int r = i >> 5, kp = i & 31;
    float r0, r1, d0, d1;
    uint32_t hp = pkbf(sT[2 * kp][r], sT[2 * kp + 1][r], r0, r1);
    uint32_t lp = pkbf(r0, r1, d0, d1);
    size_t off = (size_t)(n0 + r) * K + k0 + 2 * kp;
    *(uint32_t*)(img + off) = hp;
    *(uint32_t*)(img + planeB + off) = lp;
  }
}

// per-head reorder+split: in[(slot*CT)+(s*CB+b)][h*CHD+hd] -> out[z][s][hd]
__global__ void k_splitHead(const float* __restrict__ in, bf16* __restrict__ out,
                            size_t plane, int total /* nz*16384 */)
{
  int idx = blockIdx.x * 256 + threadIdx.x;
  if (idx >= total) return;
  int z2 = idx >> 14;            // 256*64 pairs per z
  int rem = idx & 16383;
  int s = rem >> 6, hd = (rem & 63) * 2;
  int slot = z2 >> 4, bh = z2 & 15, b = bh >> 3, h = bh & 7;
  float2 v = *(const float2*)(in + ((size_t)(slot * CT + s * CB + b)) * CD + h * CHD + hd);
  float r0, r1, d0, d1;
  uint32_t hp = pkbf(v.x, v.y, r0, r1);
  uint32_t lp = pkbf(r0, r1, d0, d1);
  size_t off = (size_t)z2 * (CS * CHD) + (size_t)s * CHD + hd;
  *(uint32_t*)(out + off) = hp;
  *(uint32_t*)(out + plane + off) = lp;
}

// V transpose+split: in v-layout -> out[z][hd][s]
__global__ void k_splitVT(const float* __restrict__ in, bf16* __restrict__ out,
                          size_t plane)
{
  __shared__ float sT[64][129];
  int t = threadIdx.x;
  int z2 = blockIdx.x, s0 = blockIdx.y * 64;
  int slot = z2 >> 4, bh = z2 & 15, b = bh >> 3, h = bh & 7;
  for (int i = t; i < 64 * 128; i += 256) {
    int sl = i >> 7, hd = i & 127;
    sT[sl][hd] = in[((size_t)(slot * CT + (s0 + sl) * CB + b)) * CD + h * CHD + hd];
  }
  __syncthreads();
  for (int i = t; i < 128 * 32; i += 256) {
    int hd = i >> 5, sp = i & 31, sl = sp * 2;
    float r0, r1, d0, d1;
    uint32_t hp = pkbf(sT[sl][hd], sT[sl + 1][hd], r0, r1);
    uint32_t lp = pkbf(r0, r1, d0, d1);
    size_t off = (size_t)z2 * (CHD * CS) + (size_t)hd * CS + s0 + sl;
    *(uint32_t*)(out + off) = hp;
    *(uint32_t*)(out + plane + off) = lp;
  }
}

// =======================================================================
// HMMA bf16-split mainloop (shared by all HMMA kernels).
// 128x128 tile, k-chunk 32, cp.async double buffer, 8 warps 2(m)x4(n).
// =======================================================================
template<int ASPL>
__device__ __forceinline__ void hmma_loop(
    const bf16* __restrict__ Aimg, const bf16* __restrict__ Bimg,
    size_t planeA, size_t planeB, int K,
    int m0, int n0, int ck0, int nck, float (&acc)[4][4][4])
{
  extern __shared__ char sm[];
  const int t = threadIdx.x, l = t & 31, wid = t >> 5;
  const int wm = wid >> 2, wn = wid & 3;
  uint32_t sbase = smem_u32(sm);

  auto load_chunk = [&](int buf, int ck) {
    int kc = ck * 32;
#pragma unroll
    for (int j = 0; j < 8; j++) {
      int cid = t + j * 256;
      int mat = cid >> 10;
      int s   = (cid >> 9) & 1;
      int row = (cid >> 2) & 127;
      int c16 = cid & 3;
      const bf16* src = (mat == 0)
        ? Aimg + (size_t)s * planeA + (size_t)(m0 + row) * K + kc + c16 * 8
        : Bimg + (size_t)s * planeB + (size_t)(n0 + row) * K + kc + c16 * 8;
      uint32_t dst = sbase + buf * 40960 + mat * 20480 + s * 10240 + row * 80 + c16 * 16;
      asm volatile("cp.async.cg.shared.global [%0], [%1], 16;" :: "r"(dst), "l"(src));
    }
    asm volatile("cp.async.commit_group;" ::: "memory");
  };

  load_chunk(0, ck0);
  const int krow = l & 15, khalf = l >> 4;

  for (int ic = 0; ic < nck; ic++) {
    int buf = ic & 1;
    if (ic + 1 < nck) {
      load_chunk(buf ^ 1, ck0 + ic + 1);
      asm volatile("cp.async.wait_group 1;" ::: "memory");
    } else {
      asm volatile("cp.async.wait_group 0;" ::: "memory");
    }
    __syncthreads();

    uint32_t abase = sbase + buf * 40960;
    uint32_t bbase = abase + 20480;
#pragma unroll
    for (int ks = 0; ks < 2; ks++) {
      uint32_t koff = (uint32_t)(ks * 16 + khalf * 8) * 2;
      uint32_t af[ASPL][4][4];
#pragma unroll
      for (int s = 0; s < ASPL; s++)
#pragma unroll
        for (int mt = 0; mt < 4; mt++) {
          uint32_t addr = abase + s * 10240 + (uint32_t)(wm * 64 + mt * 16 + krow) * 80 + koff;
          LDMX4(af[s][mt], addr);
        }
#pragma unroll
      for (int sb = 0; sb < 2; sb++) {
        uint32_t bfr[4][2];
#pragma unroll
        for (int nt = 0; nt < 2; nt++) {
          uint32_t r[4];
          uint32_t addr = bbase + sb * 10240 + (uint32_t)(wn * 32 + nt * 16 + krow) * 80 + koff;
          LDMX4(r, addr);
          bfr[2 * nt][0]     = r[0]; bfr[2 * nt][1]     = r[2];
          bfr[2 * nt + 1][0] = r[1]; bfr[2 * nt + 1][1] = r[3];
        }
#pragma unroll
        for (int sa = 0; sa < ASPL; sa++) {
          if (sa + sb > 1) continue;
#pragma unroll
          for (int mt = 0; mt < 4; mt++)
#pragma unroll
            for (int g = 0; g < 4; g++)
              mma16816(acc[mt][g], af[sa][mt], bfr[g]);
        }
      }
    }
    __syncthreads();
  }
}

// generic projection GEMM (bias/relu/perm/atomic epilogue)
template<int ASPL>
__global__ void __launch_bounds__(256, 2) k_hmma(
    const bf16* __restrict__ Aimg, const bf16* __restrict__ Bimg,
    const float* __restrict__ bias, float* __restrict__ C,
    int Mimg, int N, int Npad, int K, int nck, int ldc,
    int relu, int perm, int atomic)
{
  float acc[4][4][4];
#pragma unroll
  for (int a = 0; a < 4; a++)
#pragma unroll
    for (int b = 0; b < 4; b++)
#pragma unroll
      for (int c = 0; c < 4; c++) acc[a][b][c] = 0.f;

  const int m0 = blockIdx.y * 128, n0 = blockIdx.x * 128;
  hmma_loop<ASPL>(Aimg, Bimg, (size_t)Mimg * K, (size_t)Npad * K, K,
                  m0, n0, blockIdx.z * nck, nck, acc);

  const int t = threadIdx.x, l = t & 31, wid = t >> 5;
  const int wm = wid >> 2, wn = wid & 3;
  const int gid = l >> 2, q = l & 3;
#pragma unroll
  for (int mt = 0; mt < 4; mt++) {
#pragma unroll
    for (int g = 0; g < 4; g++) {
      int mr = m0 + wm * 64 + mt * 16 + gid;
      int nc = n0 + wn * 32 + g * 8 + q * 2;
      const float* a = acc[mt][g];
#pragma unroll
      for (int h = 0; h < 2; h++) {
        int m = mr + h * 8;
        int crow = perm ? ((m & 1) * CS + (m >> 1)) : m;
        float* cp = C + (size_t)crow * ldc;
        float v0 = a[2 * h + 0], v1 = a[2 * h + 1];
        if (atomic) {
          if (nc < N)     atomicAdd(cp + nc, v0);
          if (nc + 1 < N) atomicAdd(cp + nc + 1, v1);
        } else {
          if (nc < N)     { float x = v0 + bias[nc];     if (relu) x = fmaxf(x, 0.f); cp[nc] = x; }
          if (nc + 1 < N) { float x = v1 + bias[nc + 1]; if (relu) x = fmaxf(x, 0.f); cp[nc + 1] = x; }
        }
      }
    }
  }
}

// scores: C[z][q][k] = SCALE * sum_hd Q[bh][q][hd]*K[z][k][hd]
__global__ void __launch_bounds__(256, 2) k_hmma_sc(
    const bf16* __restrict__ qi, const bf16* __restrict__ ki, float* __restrict__ sc)
{
  int z = blockIdx.z, bh = z & 15;
  float acc[4][4][4];
#pragma unroll
  for (int a = 0; a < 4; a++)
#pragma unroll
    for (int b = 0; b < 4; b++)
#pragma unroll
      for (int c = 0; c < 4; c++) acc[a][b][c] = 0.f;

  const int m0 = blockIdx.y * 128, n0 = blockIdx.x * 128;
  hmma_loop<2>(qi + (size_t)bh * (CS * CHD), ki + (size_t)z * (CS * CHD),
               QPLANE, KPLANE, CHD, m0, n0, 0, 4, acc);

  const int t = threadIdx.x, l = t & 31, wid = t >> 5;
  const int wm = wid >> 2, wn = wid & 3;
  const int gid = l >> 2, q4 = l & 3;
  float* C = sc + (size_t)z * (CS * CS);
#pragma unroll
  for (int mt = 0; mt < 4; mt++)
#pragma unroll
    for (int g = 0; g < 4; g++) {
      int mr = m0 + wm * 64 + mt * 16 + gid;
      int nc = n0 + wn * 32 + g * 8 + q4 * 2;
      const float* a = acc[mt][g];
#pragma unroll
      for (int h = 0; h < 2; h++) {
        int m = mr + h * 8;
        C[(size_t)m * CS + nc]     = a[2 * h + 0] * ATT_SCALE;
        C[(size_t)m * CS + nc + 1] = a[2 * h + 1] * ATT_SCALE;
      }
    }
}

// PV: ob[z][q][hd] = sum_k P[z][q][k]*V[z][k][hd]   (vi is [z][hd][k])
__global__ void __launch_bounds__(256, 2) k_hmma_pv(
    const bf16* __restrict__ pi, const bf16* __restrict__ vi, float* __restrict__ ob)
{
  int z = blockIdx.z;
  float acc[4][4][4];
#pragma unroll
  for (int a = 0; a < 4; a++)
#pragma unroll
    for (int b = 0; b < 4; b++)
#pragma unroll
      for (int c = 0; c < 4; c++) acc[a][b][c] = 0.f;

  const int m0 = blockIdx.y * 128;
  hmma_loop<2>(pi + (size_t)z * (CS * CS), vi + (size_t)z * (CHD * CS),
               PPLANE, KPLANE, CS, m0, 0, 0, 8, acc);

  const int t = threadIdx.x, l = t & 31, wid = t >> 5;
  const int wm = wid >> 2, wn = wid & 3;
  const int gid = l >> 2, q4 = l & 3;
  float* C = ob + (size_t)z * (CS * CHD);
#pragma unroll
  for (int mt = 0; mt < 4; mt++)
#pragma unroll
    for (int g = 0; g < 4; g++) {
      int mr = m0 + wm * 64 + mt * 16 + gid;
      int nc = wn * 32 + g * 8 + q4 * 2;
      const float* a = acc[mt][g];
#pragma unroll
      for (int h = 0; h < 2; h++) {
        int m = mr + h * 8;
        C[(size_t)m * CHD + nc]     = a[2 * h + 0];
        C[(size_t)m * CHD + nc + 1] = a[2 * h + 1];
      }
    }
}

// =======================================================================
// SIMT fp32 SGEMM (exact) — SNN current projection only.
// =======================================================================
__global__ void __launch_bounds__(256, 2) k_gemm_nn(
    const float* __restrict__ A, const float* __restrict__ B,
    float* __restrict__ C, int K, int ld)
{
  __shared__ float As[2][16][136];
  __shared__ float Bs[2][16][136];
  const int t  = threadIdx.x;
  const int m0 = blockIdx.y * 128, n0 = blockIdx.x * 128;
  const int tm = t >> 4, tn = t & 15;
  const int lr = t >> 2, lk = (t & 3) << 2;
  const int kr = t >> 5, n4 = (t & 31) << 2;
  int nkt = (K >> 4) / gridDim.z;
  int kt0 = blockIdx.z * nkt;

  ull acc2[8][4];
#pragma unroll
  for (int i = 0; i < 8; i++)
#pragma unroll
    for (int j = 0; j < 4; j++) acc2[i][j] = 0ull;

  float4 pa0, pa1, pb0, pb1;
  auto ldA = [&](int kt) {
    const float* p = A + (size_t)(m0 + lr) * ld + kt * 16 + lk;
    pa0 = *(const float4*)p;
    pa1 = *(const float4*)(p + (size_t)64 * ld);
  };
  auto stA = [&](int s) {
    As[s][lk + 0][lr] = pa0.x; As[s][lk + 1][lr] = pa0.y;
    As[s][lk + 2][lr] = pa0.z; As[s][lk + 3][lr] = pa0.w;
    As[s][lk + 0][lr + 64] = pa1.x; As[s][lk + 1][lr + 64] = pa1.y;
    As[s][lk + 2][lr + 64] = pa1.z; As[s][lk + 3][lr + 64] = pa1.w;
  };
  auto ldB = [&](int kt) {
    const float* p = B + (size_t)(kt * 16 + kr) * ld + n0 + n4;
    pb0 = *(const float4*)p;
    pb1 = *(const float4*)(p + (size_t)8 * ld);
  };
  auto stB = [&](int s) {
    *(float4*)&Bs[s][kr][n4]     = pb0;
    *(float4*)&Bs[s][kr + 8][n4] = pb1;
  };

  ldA(kt0); ldB(kt0); stA(0); stB(0);
  __syncthreads();
  for (int it = 0; it < nkt; it++) {
    int cur = it & 1;
    if (it + 1 < nkt) { ldA(kt0 + it + 1); ldB(kt0 + it + 1); }
#pragma unroll
    for (int k = 0; k < 16; k++) {
      float4 a0 = *(const float4*)&As[cur][k][tm * 8];
      float4 a1 = *(const float4*)&As[cur][k][tm * 8 + 4];
      ulonglong2 q0 = *(const ulonglong2*)&Bs[cur][k][tn * 8];
      ulonglong2 q1 = *(const ulonglong2*)&Bs[cur][k][tn * 8 + 4];
      ull bb[4] = { q0.x, q0.y, q1.x, q1.y };
      float av[8] = { a0.x, a0.y, a0.z, a0.w, a1.x, a1.y, a1.z, a1.w };
#pragma unroll
      for (int i = 0; i < 8; i++) {
        ull aa = pk2(av[i], av[i]);
#pragma unroll
        for (int j = 0; j < 4; j++)
          acc2[i][j] = ffma2(aa, bb[j], acc2[i][j]);
      }
    }
    if (it + 1 < nkt) { stA(cur ^ 1); stB(cur ^ 1); }
    __syncthreads();
  }
#pragma unroll
  for (int i = 0; i < 8; i++) {
    float* cp = C + (size_t)(m0 + tm * 8 + i) * ld + n0 + tn * 8;
    float vals[8];
#pragma unroll
    for (int j4 = 0; j4 < 4; j4++) upk2(acc2[i][j4], vals[2 * j4], vals[2 * j4 + 1]);
#pragma unroll
    for (int j = 0; j < 8; j++) atomicAdd(cp + j, vals[j]);
  }
}

// ---------------- small helper kernels ----------------
__global__ void k_fill(float* __restrict__ C, const float* __restrict__ b,
                       int ncols4, int total4) {
  int i = blockIdx.x * 256 + threadIdx.x;
  if (i < total4) ((float4*)C)[i] = ((const float4*)b)[i % ncols4];
}

__global__ void k_softmax(const float* __restrict__ sc, bf16* __restrict__ pi,
                          size_t plane) {
  const float* row = sc + (size_t)blockIdx.x * CS;
  int t = threadIdx.x;
  __shared__ float red[8];
  float v = row[t];
  float m = v;
#pragma unroll
  for (int o = 16; o > 0; o >>= 1) m = fmaxf(m, __shfl_xor_sync(~0u, m, o));
  if ((t & 31) == 0) red[t >> 5] = m;
  __syncthreads();
  float mx = red[0];
#pragma unroll
  for (int i = 1; i < 8; i++) mx = fmaxf(mx, red[i]);
  float e = expf(v - mx);
  __syncthreads();
  float s = e;
#pragma unroll
  for (int o = 16; o > 0; o >>= 1) s += __shfl_xor_sync(~0u, s, o);
  if ((t & 31) == 0) red[t >> 5] = s;
  __syncthreads();
  float tot = 0.f;
#pragma unroll
  for (int i = 0; i < 8; i++) tot += red[i];
  float p = e / tot;
  bf16 hi = __float2bfloat16(p);
  bf16 lo = __float2bfloat16(p - __bfloat162float(hi));
  size_t off = (size_t)blockIdx.x * CS + t;
  pi[off] = hi;
  pi[plane + off] = lo;
}

__global__ void k_lw(const float* lw, int n, float* w) {
  if (threadIdx.x == 0) {
    float mx = -1e30f;
    for (int i = 0; i < n; i++) mx = fmaxf(mx, lw[i]);
    float s = 0.f, e[CL + 1];
    for (int i = 0; i < n; i++) { e[i] = expf(lw[i] - mx); s += e[i]; }
    for (int i = 0; i < n; i++) w[i] = e[i] / s;
  }
}

// combine + split emit (feeds O projection image)
__global__ void k_combine(const float* __restrict__ ob, const float* __restrict__ w,
                          int n, bf16* __restrict__ out, size_t plane)
{
  int idx = blockIdx.x * 256 + threadIdx.x;
  int r = idx >> 10, c = idx & 1023;
  int s = r >> 1, b = r & 1, h = c >> 7, hd = c & 127;
  float acc = 0.f;
  for (int slot = 0; slot < n; slot++)
    acc += w[slot] * ob[((size_t)(slot * 16 + b * 8 + h) * CS + s) * CHD + hd];
  bf16 hi = __float2bfloat16(acc);
  bf16 lo = __float2bfloat16(acc - __bfloat162float(hi));
  out[(size_t)r * CD + c] = hi;
  out[plane + (size_t)r * CD + c] = lo;
}

__global__ void k_addln(const float* __restrict__ x, const float* __restrict__ res,
                        const float* __restrict__ g, const float* __restrict__ be,
                        float* __restrict__ out0, float* __restrict__ out1)
{
  int r = blockIdx.x, t = threadIdx.x;
  const float4* xr = (const float4*)(x + (size_t)r * CD);
  const float4* rr = (const float4*)(res + (size_t)r * CD);
  float4 a = xr[t], b4 = rr[t];
  float v0 = a.x + b4.x, v1 = a.y + b4.y, v2 = a.z + b4.z, v3 = a.w + b4.w;

  __shared__ float red[8];
  float s = v0 + v1 + v2 + v3;
#pragma unroll
  for (int o = 16; o > 0; o >>= 1) s += __shfl_xor_sync(~0u, s, o);
  if ((t & 31) == 0) red[t >> 5] = s;
  __syncthreads();
  float tot = 0.f;
#pragma unroll
  for (int i = 0; i < 8; i++) tot += red[i];
  float mean = tot * (1.f / CD);

  float d0 = v0 - mean, d1 = v1 - mean, d2 = v2 - mean, d3 = v3 - mean;
  float sq = d0 * d0 + d1 * d1 + d2 * d2 + d3 * d3;
  __syncthreads();
#pragma unroll
  for (int o = 16; o > 0; o >>= 1) sq += __shfl_xor_sync(~0u, sq, o);
  if ((t & 31) == 0) red[t >> 5] = sq;
  __syncthreads();
  float vs = 0.f;
#pragma unroll
  for (int i = 0; i < 8; i++) vs += red[i];
  float rstd = rsqrtf(vs * (1.f / CD) + 1e-5f);

  float4 gg = ((const float4*)g)[t];
  float4 bb = ((const float4*)be)[t];
  float4 ov;
  ov.x = d0 * rstd * gg.x + bb.x;
  ov.y = d1 * rstd * gg.y + bb.y;
  ov.z = d2 * rstd * gg.z + bb.z;
  ov.w = d3 * rstd * gg.w + bb.w;
  ((float4*)(out0 + (size_t)r * CD))[t] = ov;
  if (out1) ((float4*)(out1 + (size_t)r * CD))[t] = ov;
}

__global__ void k_embed(const int* __restrict__ src, const float* __restrict__ emb,
                        float* __restrict__ x)
{
  int r = blockIdx.x, t = threadIdx.x;
  int s = r >> 1, b = r & 1;
  int tok = src[b * CS + s];
  const float* er = emb + (size_t)tok * CD;
  float* xr = x + (size_t)r * CD;
  const float SQ = 32.0f;
  const float cexp = -9.210340371976184f / (float)CD;
#pragma unroll
  for (int i = 0; i < 4; i++) {
    int d = t * 4 + i;
    int pair = d >> 1;
    float ang = (float)s * expf((float)(2 * pair) * cexp);
    float pe = (d & 1) ? cosf(ang) : sinf(ang);
    xr[d] = er[d] * SQ + pe;
  }
}

// SNN scan: emits spike split image directly (hi = spike, lo = 0)
__global__ void k_snn(const float* __restrict__ cur, bf16* __restrict__ spimg,
                      size_t plane) {
  int b = blockIdx.x, t = threadIdx.x;
  __shared__ float red[32];
  __shared__ float ssum;
  const bf16 z16 = __float2bfloat16(0.f);
  float mem = 0.f, thr = 1.0f;
  for (int s = 0; s < CS; s++) {
    float v = mem;
#pragma unroll
    for (int o = 16; o > 0; o >>= 1) v += __shfl_xor_sync(~0u, v, o);
    if ((t & 31) == 0) red[t >> 5] = v;
    __syncthreads();
    if (t < 32) {
      float w = red[t];
#pragma unroll
      for (int o = 16; o > 0; o >>= 1) w += __shfl_xor_sync(~0u, w, o);
      if (t == 0) ssum = w;
    }
    __syncthreads();
    float c = cur[(size_t)(s * CB + b) * CD + t] - 0.1f * ssum;
    mem = 0.9f * mem + c;
    float spk = (mem >= thr) ? 1.f : 0.f;
    mem -= spk * thr;
    thr = 0.9f * thr + 0.1f * spk;
    size_t off = (size_t)(s * CB + b) * CD + t;
    spimg[off] = __float2bfloat16(spk);
    spimg[plane + off] = z16;
    __syncthreads();
  }
}

// =======================================================================
extern "C" void kernel_launch(void* const* d_in, const int* in_sizes, int n_in,
                              void* d_out, int out_size)
{
  (void)in_sizes; (void)n_in; (void)out_size;
  const int*   src     = (const int*)  d_in[0];
  const float* emb     = (const float*)d_in[1];
  const float* Wq      = (const float*)d_in[2];
  const float* bq      = (const float*)d_in[3];
  const float* Wk      = (const float*)d_in[4];
  const float* bk      = (const float*)d_in[5];
  const float* Wv      = (const float*)d_in[6];
  const float* bv      = (const float*)d_in[7];
  const float* Wo      = (const float*)d_in[8];
  const float* bo      = (const float*)d_in[9];
  const float* layer_w = (const float*)d_in[10];
  const float* Wsnn    = (const float*)d_in[11];
  const float* bsnn    = (const float*)d_in[12];
  const float* W1      = (const float*)d_in[13];
  const float* b1      = (const float*)d_in[14];
  const float* W2      = (const float*)d_in[15];
  const float* b2      = (const float*)d_in[16];
  const float* g1      = (const float*)d_in[17];
  const float* be1     = (const float*)d_in[18];
  const float* g2      = (const float*)d_in[19];
  const float* be2     = (const float*)d_in[20];
  const float* Wout    = (const float*)d_in[21];
  const float* bout    = (const float*)d_in[22];
  float* out = (float*)d_out;

  static bool s_init = false;
  static float *pLB, *pK, *pV, *pQ, *pSC, *pOB, *pATT, *pXA, *pCUR,
               *pFFH, *pFFO, *pW;
  static bf16 *pALB, *pATMP, *pQI, *pKI, *pVI, *pPI, *pWI;
  if (!s_init) {
    cudaGetSymbolAddress((void**)&pLB,   g_LB);
    cudaGetSymbolAddress((void**)&pK,    g_k);
    cudaGetSymbolAddress((void**)&pV,    g_v);
    cudaGetSymbolAddress((void**)&pQ,    g_q);
    cudaGetSymbolAddress((void**)&pSC,   g_sc);
    cudaGetSymbolAddress((void**)&pOB,   g_ob);
    cudaGetSymbolAddress((void**)&pATT,  g_att);
    cudaGetSymbolAddress((void**)&pXA,   g_xa);
    cudaGetSymbolAddress((void**)&pCUR,  g_cur);
    cudaGetSymbolAddress((void**)&pFFH,  g_ffh);
    cudaGetSymbolAddress((void**)&pFFO,  g_ffo);
    cudaGetSymbolAddress((void**)&pW,    g_w);
    cudaGetSymbolAddress((void**)&pALB,  g_aLB);
    cudaGetSymbolAddress((void**)&pATMP, g_atmp);
    cudaGetSymbolAddress((void**)&pQI,   g_qi);
    cudaGetSymbolAddress((void**)&pKI,   g_ki);
    cudaGetSymbolAddress((void**)&pVI,   g_vi);
    cudaGetSymbolAddress((void**)&pPI,   g_pi);
    cudaGetSymbolAddress((void**)&pWI,   g_wimg);
    cudaFuncSetAttribute(k_hmma<2>,  cudaFuncAttributeMaxDynamicSharedMemorySize, HM_SMEM);
    cudaFuncSetAttribute(k_hmma<1>,  cudaFuncAttributeMaxDynamicSharedMemorySize, HM_SMEM);
    cudaFuncSetAttribute(k_hmma_sc,  cudaFuncAttributeMaxDynamicSharedMemorySize, HM_SMEM);
    cudaFuncSetAttribute(k_hmma_pv,  cudaFuncAttributeMaxDynamicSharedMemorySize, HM_SMEM);
    s_init = true;
  }

  // ---- pre-split all weights (batched over layers) ----
  k_splitB2b<<<dim3(CD / 128, CD / 64, CL), 256>>>(Wq, pWI + 0 * CL * W_CDCD,
      CD, CD, CD, (size_t)CD * CD, W_CDCD);
  k_splitB2b<<<dim3(CD / 128, CD / 64, CL), 256>>>(Wk, pWI + 1 * CL * W_CDCD,
      CD, CD, CD, (size_t)CD * CD, W_CDCD);
  k_splitB2b<<<dim3(CD / 128, CD / 64, CL), 256>>>(Wv, pWI + 2 * CL * W_CDCD,
      CD, CD, CD, (size_t)CD * CD, W_CDCD);
  k_splitB2b<<<dim3(CD / 128, CD / 64, CL), 256>>>(Wo, pWI + 3 * CL * W_CDCD,
      CD, CD, CD, (size_t)CD * CD, W_CDCD);
  k_splitB2b<<<dim3(CFF / 128, CD / 64, CL), 256>>>(W1, pWI + W_BASE1,
      CFF, CFF, CD, (size_t)CD * CFF, W_FFSZ);
  k_splitB2b<<<dim3(CD / 128, CFF / 64, CL), 256>>>(W2, pWI + W_BASE2,
      CD, CD, CFF, (size_t)CFF * CD, W_FFSZ);
  k_splitB2b<<<dim3(CVP / 128, CD / 64, 1), 256>>>(Wout, pWI + W_BASEO,
      CV, CVP, CD, 0, 0);

  auto hgemm = [&](const bf16* Aimg, int Mimg, const bf16* Wimg,
                   const float* bias, float* C,
                   int M, int Nact, int Npad, int K,
                   int ks, int relu, int perm, int aspl) {
    int chunks = K >> 5;
    if (ks > 1) {
      int t4 = (M * Nact) >> 2;
      k_fill<<<(t4 + 255) / 256, 256>>>(C, bias, Nact >> 2, t4);
      if (aspl == 1)
        k_hmma<1><<<dim3(Npad / 128, M / 128, ks), 256, HM_SMEM>>>(
            Aimg, Wimg, nullptr, C, Mimg, Nact, Npad, K, chunks / ks, Nact, 0, 0, 1);
      else
        k_hmma<2><<<dim3(Npad / 128, M / 128, ks), 256, HM_SMEM>>>(
            Aimg, Wimg, nullptr, C, Mimg, Nact, Npad, K, chunks / ks, Nact, 0, 0, 1);
    } else {
      if (aspl == 1)
        k_hmma<1><<<dim3(Npad / 128, M / 128, 1), 256, HM_SMEM>>>(
            Aimg, Wimg, bias, C, Mimg, Nact, Npad, K, chunks, Nact, relu, perm, 0);
      else
        k_hmma<2><<<dim3(Npad / 128, M / 128, 1), 256, HM_SMEM>>>(
            Aimg, Wimg, bias, C, Mimg, Nact, Npad, K, chunks, Nact, relu, perm, 0);
    }
  };
  const int MIMG_LB = (CL + 1) * CT;   // 8704

  k_embed<<<CT, 256>>>(src, emb, pLB);
  // initial slot-0 split into persistent LB image
  k_splitA2<<<(CT * CD / 2 + 255) / 256, 256>>>(pLB, pALB, CD, CT * CD / 2, 0, PLANE_LB);

  for (int l = 0; l < CL; l++) {
    int n = l + 1;
    k_lw<<<1, 32>>>(layer_w + (size_t)l * (CL + 1), n, pW);

    hgemm(pALB, MIMG_LB, pWI + (0 * CL + l) * W_CDCD, bq + (size_t)l * CD, pQ,
          CT, CD, CD, CD, 8, 0, 0, 2);
    int ksv = (n == 1) ? 8 : (n == 2) ? 4 : (n <= 7) ? 2 : 1;
    hgemm(pALB, MIMG_LB, pWI + (1 * CL + l) * W_CDCD, bk + (size_t)l * CD, pK,
          n * CT, CD, CD, CD, ksv, 0, 0, 2);
    hgemm(pALB, MIMG_LB, pWI + (2 * CL + l) * W_CDCD, bv + (size_t)l * CD, pV,
          n * CT, CD, CD, CD, ksv, 0, 0, 2);

    // attention via HMMA
    k_splitHead<<<(16 * 16384) / 256, 256>>>(pQ, pQI, QPLANE, 16 * 16384);
    k_splitHead<<<(n * 16 * 16384) / 256, 256>>>(pK, pKI, KPLANE, n * 16 * 16384);
    k_splitVT<<<dim3(n * 16, 4), 256>>>(pV, pVI, KPLANE);
    k_hmma_sc<<<dim3(2, 2, n * 16), 256, HM_SMEM>>>(pQI, pKI, pSC);
    k_softmax<<<n * 16 * CS, 256>>>(pSC, pPI, PPLANE);
    k_hmma_pv<<<dim3(1, 2, n * 16), 256, HM_SMEM>>>(pPI, pVI, pOB);
    k_combine<<<(CT * CD) / 256, 256>>>(pOB, pW, n, pATMP, (size_t)512 * CD);

    hgemm(pATMP, 512, pWI + (3 * CL + l) * W_CDCD, bo + (size_t)l * CD, pATT,
          CT, CD, CD, CD, 8, 0, 0, 2);
    k_addln<<<CT, 256>>>(pLB, pATT, g1 + (size_t)l * CD, be1 + (size_t)l * CD,
                         pXA, nullptr);

    // SNN current projection: exact fp32 SIMT
    {
      int t4 = (CT * CD) >> 2;
      k_fill<<<(t4 + 255) / 256, 256>>>(pCUR, bsnn + (size_t)l * CD, CD >> 2, t4);
      k_gemm_nn<<<dim3(8, 4, 8), 256>>>(pXA, Wsnn + (size_t)l * CD * CD, pCUR, CD, CD);
    }
    k_snn<<<CB, 1024>>>(pCUR, pATMP, (size_t)512 * CD);

    hgemm(pATMP, 512, pWI + W_BASE1 + (size_t)l * W_FFSZ, b1 + (size_t)l * CFF, pFFH,
          CT, CFF, CFF, CD, 4, 1, 0, 1);
    k_relusplit<<<(CT * CFF / 2 + 255) / 256, 256>>>(pFFH, pATMP, CFF, CT * CFF / 2,
                                                     (size_t)512 * CFF);
    hgemm(pATMP, 512, pWI + W_BASE2 + (size_t)l * W_FFSZ, b2 + (size_t)l * CD, pFFO,
          CT, CD, CD, CFF, 8, 0, 0, 2);

    k_addln<<<CT, 256>>>(pXA, pFFO, g2 + (size_t)l * CD, be2 + (size_t)l * CD,
                         pLB, pLB + (size_t)(l + 1) * CT * CD);
    // incremental LB-image update: new x -> slot 0 and slot l+1
    k_splitA2<<<(CT * CD / 2 + 255) / 256, 256>>>(pLB, pALB, CD, CT * CD / 2, 0, PLANE_LB);
    k_splitA2<<<(CT * CD / 2 + 255) / 256, 256>>>(pLB, pALB, CD, CT * CD / 2,
                                                  (l + 1) * CT, PLANE_LB);
  }

  // logits = x @ Wout + bout -> [B,S,V] (perm)
  hgemm(pALB, MIMG_LB, pWI + W_BASEO, bout, out, CT, CV, CVP, CD, 1, 0, 1, 2);
}

// round 16
// speedup vs baseline: 2.8599x; 1.0549x over previous
#include <cuda_runtime.h>
#include <cuda_bf16.h>
#include <math.h>
#include <stdint.h>
#include <stddef.h>

typedef unsigned long long ull;
typedef __nv_bfloat16 bf16;

// ---------------- problem constants ----------------
constexpr int CB  = 2;
constexpr int CS  = 256;
constexpr int CD  = 1024;
constexpr int CH  = 8;
constexpr int CHD = 128;
constexpr int CL  = 16;
constexpr int CFF = 2048;
constexpr int CV  = 50257;
constexpr int CVP = 50304;
constexpr int CT  = CS * CB;   // 512 tokens, row r = s*CB + b
constexpr float ATT_SCALE = 0.08838834764831845f;
constexpr int HM_SMEM = 2 * 40960;   // double-buffered A2+B2 tiles (80KB)

// weight-image layout (bf16 elements)
constexpr size_t W_CDCD   = (size_t)2 * CD * CD;
constexpr size_t W_BASE1  = (size_t)64 * W_CDCD;
constexpr size_t W_FFSZ   = (size_t)2 * CFF * CD;
constexpr size_t W_BASE2  = W_BASE1 + (size_t)CL * W_FFSZ;
constexpr size_t W_BASEO  = W_BASE2 + (size_t)CL * W_FFSZ;
constexpr size_t W_BASES  = W_BASEO + (size_t)2 * CVP * CD;   // Wsnn images
constexpr size_t W_TOTAL  = W_BASES + (size_t)CL * W_CDCD;

// activation image planes
constexpr size_t PLANE_LB  = (size_t)(CL + 1) * CT * CD;
constexpr size_t PLANE_TMP = (size_t)512 * 2048;
constexpr size_t PLANE_CD  = (size_t)512 * CD;
constexpr size_t QPLANE    = (size_t)16 * CS * CHD;
constexpr size_t KPLANE    = (size_t)CL * 16 * CS * CHD;
constexpr size_t PPLANE    = (size_t)CL * 16 * CS * CS;

// ---------------- static device scratch ----------------
__device__ __align__(16) float g_LB[(size_t)(CL + 1) * CT * CD];
__device__ __align__(16) float g_k [(size_t)CL * CT * CD];
__device__ __align__(16) float g_v [(size_t)CL * CT * CD];
__device__ __align__(16) float g_q [CT * CD];
__device__ __align__(16) float g_sc[(size_t)CL * 16 * CS * CS];
__device__ __align__(16) float g_ob[(size_t)CL * 16 * CS * CHD];
__device__ __align__(16) float g_att [CT * CD];
__device__ __align__(16) float g_xa  [CT * CD];
__device__ __align__(16) float g_cur [CT * CD];
__device__ __align__(16) float g_ffh [CT * CFF];
__device__ __align__(16) float g_ffo [CT * CD];
// bf16 hi/lo split images (16B-aligned for cp.async)
__device__ __align__(16) bf16 g_aLB [2 * PLANE_LB];
__device__ __align__(16) bf16 g_atmp[2 * PLANE_TMP];
__device__ __align__(16) bf16 g_qi  [2 * QPLANE];
__device__ __align__(16) bf16 g_ki  [2 * KPLANE];
__device__ __align__(16) bf16 g_vi  [2 * KPLANE];
__device__ __align__(16) bf16 g_pi  [2 * PPLANE];
__device__ __align__(16) bf16 g_wimg[W_TOTAL];

// ---------------- helpers ----------------
__device__ __forceinline__ uint32_t smem_u32(const void* p) {
  uint32_t a;
  asm("{ .reg .u64 t; cvta.to.shared.u64 t, %1; cvt.u32.u64 %0, t; }" : "=r"(a) : "l"(p));
  return a;
}
__device__ __forceinline__ uint32_t pkbf(float x0, float x1, float& r0, float& r1) {
  bf16 b0 = __float2bfloat16(x0), b1 = __float2bfloat16(x1);
  uint32_t pk;
  asm("mov.b32 %0,{%1,%2};" : "=r"(pk)
      : "h"(*(unsigned short*)&b0), "h"(*(unsigned short*)&b1));
  r0 = x0 - __bfloat162float(b0);
  r1 = x1 - __bfloat162float(b1);
  return pk;
}
__device__ __forceinline__ uint32_t pkbf2(float x0, float x1, float& r0, float& r1) {
  return pkbf(x0, x1, r0, r1);
}

#define LDMX4(r, a) \
  asm volatile("ldmatrix.sync.aligned.m8n8.x4.shared.b16 {%0,%1,%2,%3}, [%4];" \
    : "=r"((r)[0]), "=r"((r)[1]), "=r"((r)[2]), "=r"((r)[3]) : "r"(a))

__device__ __forceinline__ void mma16816(float* c, const uint32_t* a, const uint32_t* b) {
  asm volatile("mma.sync.aligned.m16n8k16.row.col.f32.bf16.bf16.f32 "
    "{%0,%1,%2,%3}, {%4,%5,%6,%7}, {%8,%9}, {%0,%1,%2,%3};"
    : "+f"(c[0]), "+f"(c[1]), "+f"(c[2]), "+f"(c[3])
    : "r"(a[0]), "r"(a[1]), "r"(a[2]), "r"(a[3]), "r"(b[0]), "r"(b[1]));
}

// =======================================================================
// split-image builders
// =======================================================================
__global__ void k_splitA2(const float* __restrict__ A, bf16* __restrict__ img,
                          int K, int pairs, int rowOff, size_t plane)
{
  int idx = blockIdx.x * 256 + threadIdx.x;
  if (idx >= pairs) return;
  int kh = K >> 1;
  int m = idx / kh, kp = idx - m * kh;
  int k = kp * 2;
  float2 v = *(const float2*)(A + (size_t)m * K + k);
  float r0, r1, d0, d1;
  uint32_t hp = pkbf(v.x, v.y, r0, r1);
  uint32_t lp = pkbf(r0, r1, d0, d1);
  size_t off = (size_t)(rowOff + m) * K + k;
  *(uint32_t*)(img + off) = hp;
  *(uint32_t*)(img + plane + off) = lp;
}

__global__ void k_relusplit(const float* __restrict__ A, bf16* __restrict__ img,
                            int K, int pairs, size_t plane)
{
  int idx = blockIdx.x * 256 + threadIdx.x;
  if (idx >= pairs) return;
  int kh = K >> 1;
  int m = idx / kh, kp = idx - m * kh;
  int k = kp * 2;
  float2 v = *(const float2*)(A + (size_t)m * K + k);
  v.x = fmaxf(v.x, 0.f); v.y = fmaxf(v.y, 0.f);
  float r0, r1, d0, d1;
  uint32_t hp = pkbf(v.x, v.y, r0, r1);
  uint32_t lp = pkbf(r0, r1, d0, d1);
  size_t off = (size_t)m * K + k;
  *(uint32_t*)(img + off) = hp;
  *(uint32_t*)(img + plane + off) = lp;
}

// W [K][N] row-major -> image [n][k] per split plane, batched over layers.
__global__ void k_splitB2b(const float* __restrict__ W0, bf16* __restrict__ img0,
                           int N, int Npad, int K, size_t wstride, size_t istride)
{
  __shared__ float sT[64][129];
  const float* W = W0 + (size_t)blockIdx.z * wstride;
  bf16* img = img0 + (size_t)blockIdx.z * istride;
  int t = threadIdx.x;
  int n0 = blockIdx.x * 128, k0 = blockIdx.y * 64;
  size_t planeB = (size_t)Npad * K;
  for (int i = t; i < 64 * 128; i += 256) {
    int kk = i >> 7, nn = i & 127;
    int n = n0 + nn;
    sT[kk][nn] = (n < N) ? W[(size_t)(k0 + kk) * N + n] : 0.f;
  }
  __syncthreads();
  for (int i = t; i < 128 * 32; i += 256) {
    int r = i >> 5, kp = i & 31;
    float r0, r1, d0, d1;
    uint32_t hp = pkbf(sT[2 * kp][r], sT[2 * kp + 1][r], r0, r1);
    uint32_t lp = pkbf(r0, r1, d0, d1);
    size_t off = (size_t)(n0 + r) * K + k0 + 2 * kp;
    *(uint32_t*)(img + off) = hp;
    *(uint32_t*)(img + planeB + off) = lp;
  }
}

// per-head reorder+split: in[(slot*CT)+(s*CB+b)][h*CHD+hd] -> out[z][s][hd]
__global__ void k_splitHead(const float* __restrict__ in, bf16* __restrict__ out,
                            size_t plane, int total)
{
  int idx = blockIdx.x * 256 + threadIdx.x;
  if (idx >= total) return;
  int z2 = idx >> 14;
  int rem = idx & 16383;
  int s = rem >> 6, hd = (rem & 63) * 2;
  int slot = z2 >> 4, bh = z2 & 15, b = bh >> 3, h = bh & 7;
  float2 v = *(const float2*)(in + ((size_t)(slot * CT + s * CB + b)) * CD + h * CHD + hd);
  float r0, r1, d0, d1;
  uint32_t hp = pkbf(v.x, v.y, r0, r1);
  uint32_t lp = pkbf(r0, r1, d0, d1);
  size_t off = (size_t)z2 * (CS * CHD) + (size_t)s * CHD + hd;
  *(uint32_t*)(out + off) = hp;
  *(uint32_t*)(out + plane + off) = lp;
}

// V transpose+split: in v-layout -> out[z][hd][s]
__global__ void k_splitVT(const float* __restrict__ in, bf16* __restrict__ out,
                          size_t plane)
{
  __shared__ float sT[64][129];
  int t = threadIdx.x;
  int z2 = blockIdx.x, s0 = blockIdx.y * 64;
  int slot = z2 >> 4, bh = z2 & 15, b = bh >> 3, h = bh & 7;
  for (int i = t; i < 64 * 128; i += 256) {
    int sl = i >> 7, hd = i & 127;
    sT[sl][hd] = in[((size_t)(slot * CT + (s0 + sl) * CB + b)) * CD + h * CHD + hd];
  }
  __syncthreads();
  for (int i = t; i < 128 * 32; i += 256) {
    int hd = i >> 5, sp = i & 31, sl = sp * 2;
    float r0, r1, d0, d1;
    uint32_t hp = pkbf(sT[sl][hd], sT[sl + 1][hd], r0, r1);
    uint32_t lp = pkbf(r0, r1, d0, d1);
    size_t off = (size_t)z2 * (CHD * CS) + (size_t)hd * CS + s0 + sl;
    *(uint32_t*)(out + off) = hp;
    *(uint32_t*)(out + plane + off) = lp;
  }
}

// =======================================================================
// HMMA bf16-split mainloop (shared by all HMMA kernels).
// =======================================================================
template<int ASPL>
__device__ __forceinline__ void hmma_loop(
    const bf16* __restrict__ Aimg, const bf16* __restrict__ Bimg,
    size_t planeA, size_t planeB, int K,
    int m0, int n0, int ck0, int nck, float (&acc)[4][4][4])
{
  extern __shared__ char sm[];
  const int t = threadIdx.x, l = t & 31, wid = t >> 5;
  const int wm = wid >> 2, wn = wid & 3;
  uint32_t sbase = smem_u32(sm);

  auto load_chunk = [&](int buf, int ck) {
    int kc = ck * 32;
#pragma unroll
    for (int j = 0; j < 8; j++) {
      int cid = t + j * 256;
      int mat = cid >> 10;
      int s   = (cid >> 9) & 1;
      int row = (cid >> 2) & 127;
      int c16 = cid & 3;
      const bf16* src = (mat == 0)
        ? Aimg + (size_t)s * planeA + (size_t)(m0 + row) * K + kc + c16 * 8
        : Bimg + (size_t)s * planeB + (size_t)(n0 + row) * K + kc + c16 * 8;
      uint32_t dst = sbase + buf * 40960 + mat * 20480 + s * 10240 + row * 80 + c16 * 16;
      asm volatile("cp.async.cg.shared.global [%0], [%1], 16;" :: "r"(dst), "l"(src));
    }
    asm volatile("cp.async.commit_group;" ::: "memory");
  };

  load_chunk(0, ck0);
  const int krow = l & 15, khalf = l >> 4;

  for (int ic = 0; ic < nck; ic++) {
    int buf = ic & 1;
    if (ic + 1 < nck) {
      load_chunk(buf ^ 1, ck0 + ic + 1);
      asm volatile("cp.async.wait_group 1;" ::: "memory");
    } else {
      asm volatile("cp.async.wait_group 0;" ::: "memory");
    }
    __syncthreads();

    uint32_t abase = sbase + buf * 40960;
    uint32_t bbase = abase + 20480;
#pragma unroll
    for (int ks = 0; ks < 2; ks++) {
      uint32_t koff = (uint32_t)(ks * 16 + khalf * 8) * 2;
      uint32_t af[ASPL][4][4];
#pragma unroll
      for (int s = 0; s < ASPL; s++)
#pragma unroll
        for (int mt = 0; mt < 4; mt++) {
          uint32_t addr = abase + s * 10240 + (uint32_t)(wm * 64 + mt * 16 + krow) * 80 + koff;
          LDMX4(af[s][mt], addr);
        }
#pragma unroll
      for (int sb = 0; sb < 2; sb++) {
        uint32_t bfr[4][2];
#pragma unroll
        for (int nt = 0; nt < 2; nt++) {
          uint32_t r[4];
          uint32_t addr = bbase + sb * 10240 + (uint32_t)(wn * 32 + nt * 16 + krow) * 80 + koff;
          LDMX4(r, addr);
          bfr[2 * nt][0]     = r[0]; bfr[2 * nt][1]     = r[2];
          bfr[2 * nt + 1][0] = r[1]; bfr[2 * nt + 1][1] = r[3];
        }
#pragma unroll
        for (int sa = 0; sa < ASPL; sa++) {
          if (sa + sb > 1) continue;
#pragma unroll
          for (int mt = 0; mt < 4; mt++)
#pragma unroll
            for (int g = 0; g < 4; g++)
              mma16816(acc[mt][g], af[sa][mt], bfr[g]);
        }
      }
    }
    __syncthreads();
  }
}

// generic projection GEMM. himg != null: write bf16 split head-layout instead of C.
template<int ASPL>
__global__ void __launch_bounds__(256, 2) k_hmma(
    const bf16* __restrict__ Aimg, const bf16* __restrict__ Bimg,
    const float* __restrict__ bias, float* __restrict__ C,
    int Mimg, int N, int Npad, int K, int nck, int ldc,
    int relu, int perm, int atomic, bf16* __restrict__ himg, size_t hplane)
{
  float acc[4][4][4];
#pragma unroll
  for (int a = 0; a < 4; a++)
#pragma unroll
    for (int b = 0; b < 4; b++)
#pragma unroll
      for (int c = 0; c < 4; c++) acc[a][b][c] = 0.f;

  const int m0 = blockIdx.y * 128, n0 = blockIdx.x * 128;
  hmma_loop<ASPL>(Aimg, Bimg, (size_t)Mimg * K, (size_t)Npad * K, K,
                  m0, n0, blockIdx.z * nck, nck, acc);

  const int t = threadIdx.x, l = t & 31, wid = t >> 5;
  const int wm = wid >> 2, wn = wid & 3;
  const int gid = l >> 2, q = l & 3;
#pragma unroll
  for (int mt = 0; mt < 4; mt++) {
#pragma unroll
    for (int g = 0; g < 4; g++) {
      int mr = m0 + wm * 64 + mt * 16 + gid;
      int nc = n0 + wn * 32 + g * 8 + q * 2;
      const float* a = acc[mt][g];
#pragma unroll
      for (int h = 0; h < 2; h++) {
        int m = mr + h * 8;
        float v0 = a[2 * h + 0], v1 = a[2 * h + 1];
        if (himg) {
          // head-layout split emit: m = slot*CT + s*CB + b ; n = hh*CHD + hd
          int slot = m >> 9, r = m & 511, s = r >> 1, b = r & 1;
          int hh = nc >> 7, hd = nc & 127;
          int z2 = slot * 16 + b * 8 + hh;
          size_t off = (size_t)z2 * (CS * CHD) + (size_t)s * CHD + hd;
          float x0 = v0 + bias[nc], x1 = v1 + bias[nc + 1];
          float r0, r1, d0, d1;
          uint32_t hp = pkbf(x0, x1, r0, r1);
          uint32_t lp = pkbf(r0, r1, d0, d1);
          *(uint32_t*)(himg + off) = hp;
          *(uint32_t*)(himg + hplane + off) = lp;
        } else {
          int crow = perm ? ((m & 1) * CS + (m >> 1)) : m;
          float* cp = C + (size_t)crow * ldc;
          if (atomic) {
            if (nc < N)     atomicAdd(cp + nc, v0);
            if (nc + 1 < N) atomicAdd(cp + nc + 1, v1);
          } else {
            if (nc < N)     { float x = v0 + bias[nc];     if (relu) x = fmaxf(x, 0.f); cp[nc] = x; }
            if (nc + 1 < N) { float x = v1 + bias[nc + 1]; if (relu) x = fmaxf(x, 0.f); cp[nc + 1] = x; }
          }
        }
      }
    }
  }
}

// scores: C[z][q][k] = SCALE * sum_hd Q[bh][q][hd]*K[z][k][hd]
__global__ void __launch_bounds__(256, 2) k_hmma_sc(
    const bf16* __restrict__ qi, const bf16* __restrict__ ki, float* __restrict__ sc)
{
  int z = blockIdx.z, bh = z & 15;
  float acc[4][4][4];
#pragma unroll
  for (int a = 0; a < 4; a++)
#pragma unroll
    for (int b = 0; b < 4; b++)
#pragma unroll
      for (int c = 0; c < 4; c++) acc[a][b][c] = 0.f;

  const int m0 = blockIdx.y * 128, n0 = blockIdx.x * 128;
  hmma_loop<2>(qi + (size_t)bh * (CS * CHD), ki + (size_t)z * (CS * CHD),
               QPLANE, KPLANE, CHD, m0, n0, 0, 4, acc);

  const int t = threadIdx.x, l = t & 31, wid = t >> 5;
  const int wm = wid >> 2, wn = wid & 3;
  const int gid = l >> 2, q4 = l & 3;
  float* C = sc + (size_t)z * (CS * CS);
#pragma unroll
  for (int mt = 0; mt < 4; mt++)
#pragma unroll
    for (int g = 0; g < 4; g++) {
      int mr = m0 + wm * 64 + mt * 16 + gid;
      int nc = n0 + wn * 32 + g * 8 + q4 * 2;
      const float* a = acc[mt][g];
#pragma unroll
      for (int h = 0; h < 2; h++) {
        int m = mr + h * 8;
        C[(size_t)m * CS + nc]     = a[2 * h + 0] * ATT_SCALE;
        C[(size_t)m * CS + nc + 1] = a[2 * h + 1] * ATT_SCALE;
      }
    }
}

// PV: ob[z][q][hd] = sum_k P[z][q][k]*V[z][k][hd]   (vi is [z][hd][k])
__global__ void __launch_bounds__(256, 2) k_hmma_pv(
    const bf16* __restrict__ pi, const bf16* __restrict__ vi, float* __restrict__ ob)
{
  int z = blockIdx.z;
  float acc[4][4][4];
#pragma unroll
  for (int a = 0; a < 4; a++)
#pragma unroll
    for (int b = 0; b < 4; b++)
#pragma unroll
      for (int c = 0; c < 4; c++) acc[a][b][c] = 0.f;

  const int m0 = blockIdx.y * 128;
  hmma_loop<2>(pi + (size_t)z * (CS * CS), vi + (size_t)z * (CHD * CS),
               PPLANE, KPLANE, CS, m0, 0, 0, 8, acc);

  const int t = threadIdx.x, l = t & 31, wid = t >> 5;
  const int wm = wid >> 2, wn = wid & 3;
  const int gid = l >> 2, q4 = l & 3;
  float* C = ob + (size_t)z * (CS * CHD);
#pragma unroll
  for (int mt = 0; mt < 4; mt++)
#pragma unroll
    for (int g = 0; g < 4; g++) {
      int mr = m0 + wm * 64 + mt * 16 + gid;
      int nc = wn * 32 + g * 8 + q4 * 2;
      const float* a = acc[mt][g];
#pragma unroll
      for (int h = 0; h < 2; h++) {
        int m = mr + h * 8;
        C[(size_t)m * CHD + nc]     = a[2 * h + 0];
        C[(size_t)m * CHD + nc + 1] = a[2 * h + 1];
      }
    }
}

// ---------------- small helper kernels ----------------
__global__ void k_fill(float* __restrict__ C, const float* __restrict__ b,
                       int ncols4, int total4) {
  int i = blockIdx.x * 256 + threadIdx.x;
  if (i < total4) ((float4*)C)[i] = ((const float4*)b)[i % ncols4];
}

__global__ void k_softmax(const float* __restrict__ sc, bf16* __restrict__ pi,
                          size_t plane) {
  const float* row = sc + (size_t)blockIdx.x * CS;
  int t = threadIdx.x;
  __shared__ float red[8];
  float v = row[t];
  float m = v;
#pragma unroll
  for (int o = 16; o > 0; o >>= 1) m = fmaxf(m, __shfl_xor_sync(~0u, m, o));
  if ((t & 31) == 0) red[t >> 5] = m;
  __syncthreads();
  float mx = red[0];
#pragma unroll
  for (int i = 1; i < 8; i++) mx = fmaxf(mx, red[i]);
  float e = expf(v - mx);
  __syncthreads();
  float s = e;
#pragma unroll
  for (int o = 16; o > 0; o >>= 1) s += __shfl_xor_sync(~0u, s, o);
  if ((t & 31) == 0) red[t >> 5] = s;
  __syncthreads();
  float tot = 0.f;
#pragma unroll
  for (int i = 0; i < 8; i++) tot += red[i];
  float p = e / tot;
  bf16 hi = __float2bfloat16(p);
  bf16 lo = __float2bfloat16(p - __bfloat162float(hi));
  size_t off = (size_t)blockIdx.x * CS + t;
  pi[off] = hi;
  pi[plane + off] = lo;
}

// combine with in-kernel layer-mix softmax; emits split image
__global__ void k_combine(const float* __restrict__ ob, const float* __restrict__ lw,
                          int n, bf16* __restrict__ out, size_t plane)
{
  float w[CL + 1];
  {
    float mx = -1e30f;
    for (int i = 0; i < n; i++) mx = fmaxf(mx, __ldg(lw + i));
    float ssum = 0.f;
    for (int i = 0; i < n; i++) { w[i] = expf(__ldg(lw + i) - mx); ssum += w[i]; }
    float inv = 1.f / ssum;
    for (int i = 0; i < n; i++) w[i] *= inv;
  }
  int idx = blockIdx.x * 256 + threadIdx.x;
  int r = idx >> 10, c = idx & 1023;
  int s = r >> 1, b = r & 1, h = c >> 7, hd = c & 127;
  float acc = 0.f;
  for (int slot = 0; slot < n; slot++)
    acc += w[slot] * ob[((size_t)(slot * 16 + b * 8 + h) * CS + s) * CHD + hd];
  bf16 hi = __float2bfloat16(acc);
  bf16 lo = __float2bfloat16(acc - __bfloat162float(hi));
  out[(size_t)r * CD + c] = hi;
  out[plane + (size_t)r * CD + c] = lo;
}

// residual add + LN; emits float out(s) and bf16 split image(s)
__global__ void k_addln(const float* __restrict__ x, const float* __restrict__ res,
                        const float* __restrict__ g, const float* __restrict__ be,
                        float* __restrict__ out0, float* __restrict__ out1,
                        bf16* __restrict__ img, size_t plane,
                        int rowOff0, int rowOff1)
{
  int r = blockIdx.x, t = threadIdx.x;
  const float4* xr = (const float4*)(x + (size_t)r * CD);
  const float4* rr = (const float4*)(res + (size_t)r * CD);
  float4 a = xr[t], b4 = rr[t];
  float v0 = a.x + b4.x, v1 = a.y + b4.y, v2 = a.z + b4.z, v3 = a.w + b4.w;

  __shared__ float red[8];
  float s = v0 + v1 + v2 + v3;
#pragma unroll
  for (int o = 16; o > 0; o >>= 1) s += __shfl_xor_sync(~0u, s, o);
  if ((t & 31) == 0) red[t >> 5] = s;
  __syncthreads();
  float tot = 0.f;
#pragma unroll
  for (int i = 0; i < 8; i++) tot += red[i];
  float mean = tot * (1.f / CD);

  float d0 = v0 - mean, d1 = v1 - mean, d2 = v2 - mean, d3 = v3 - mean;
  float sq = d0 * d0 + d1 * d1 + d2 * d2 + d3 * d3;
  __syncthreads();
#pragma unroll
  for (int o = 16; o > 0; o >>= 1) sq += __shfl_xor_sync(~0u, sq, o);
  if ((t & 31) == 0) red[t >> 5] = sq;
  __syncthreads();
  float vs = 0.f;
#pragma unroll
  for (int i = 0; i < 8; i++) vs += red[i];
  float rstd = rsqrtf(vs * (1.f / CD) + 1e-5f);

  float4 gg = ((const float4*)g)[t];
  float4 bb = ((const float4*)be)[t];
  float4 ov;
  ov.x = d0 * rstd * gg.x + bb.x;
  ov.y = d1 * rstd * gg.y + bb.y;
  ov.z = d2 * rstd * gg.z + bb.z;
  ov.w = d3 * rstd * gg.w + bb.w;
  ((float4*)(out0 + (size_t)r * CD))[t] = ov;
  if (out1) ((float4*)(out1 + (size_t)r * CD))[t] = ov;

  if (img) {
    float r0, r1, d0x, d1x;
    uint32_t hp0 = pkbf(ov.x, ov.y, r0, r1);
    uint32_t lp0 = pkbf(r0, r1, d0x, d1x);
    uint32_t hp1 = pkbf(ov.z, ov.w, r0, r1);
    uint32_t lp1 = pkbf(r0, r1, d0x, d1x);
    size_t off = (size_t)(rowOff0 + r) * CD + t * 4;
    *(uint32_t*)(img + off) = hp0;
    *(uint32_t*)(img + off + 2) = hp1;
    *(uint32_t*)(img + plane + off) = lp0;
    *(uint32_t*)(img + plane + off + 2) = lp1;
    if (rowOff1 >= 0) {
      size_t off1 = (size_t)(rowOff1 + r) * CD + t * 4;
      *(uint32_t*)(img + off1) = hp0;
      *(uint32_t*)(img + off1 + 2) = hp1;
      *(uint32_t*)(img + plane + off1) = lp0;
      *(uint32_t*)(img + plane + off1 + 2) = lp1;
    }
  }
}

__global__ void k_embed(const int* __restrict__ src, const float* __restrict__ emb,
                        float* __restrict__ x)
{
  int r = blockIdx.x, t = threadIdx.x;
  int s = r >> 1, b = r & 1;
  int tok = src[b * CS + s];
  const float* er = emb + (size_t)tok * CD;
  float* xr = x + (size_t)r * CD;
  const float SQ = 32.0f;
  const float cexp = -9.210340371976184f / (float)CD;
#pragma unroll
  for (int i = 0; i < 4; i++) {
    int d = t * 4 + i;
    int pair = d >> 1;
    float ang = (float)s * expf((float)(2 * pair) * cexp);
    float pe = (d & 1) ? cosf(ang) : sinf(ang);
    xr[d] = er[d] * SQ + pe;
  }
}

// SNN scan: emits spike split image directly (hi = spike, lo = 0)
__global__ void k_snn(const float* __restrict__ cur, bf16* __restrict__ spimg,
                      size_t plane) {
  int b = blockIdx.x, t = threadIdx.x;
  __shared__ float red[32];
  __shared__ float ssum;
  const bf16 z16 = __float2bfloat16(0.f);
  float mem = 0.f, thr = 1.0f;
  for (int s = 0; s < CS; s++) {
    float v = mem;
#pragma unroll
    for (int o = 16; o > 0; o >>= 1) v += __shfl_xor_sync(~0u, v, o);
    if ((t & 31) == 0) red[t >> 5] = v;
    __syncthreads();
    if (t < 32) {
      float w = red[t];
#pragma unroll
      for (int o = 16; o > 0; o >>= 1) w += __shfl_xor_sync(~0u, w, o);
      if (t == 0) ssum = w;
    }
    __syncthreads();
    float c = cur[(size_t)(s * CB + b) * CD + t] - 0.1f * ssum;
    mem = 0.9f * mem + c;
    float spk = (mem >= thr) ? 1.f : 0.f;
    mem -= spk * thr;
    thr = 0.9f * thr + 0.1f * spk;
    size_t off = (size_t)(s * CB + b) * CD + t;
    spimg[off] = __float2bfloat16(spk);
    spimg[plane + off] = z16;
    __syncthreads();
  }
}

// =======================================================================
extern "C" void kernel_launch(void* const* d_in, const int* in_sizes, int n_in,
                              void* d_out, int out_size)
{
  (void)in_sizes; (void)n_in; (void)out_size;
  const int*   src     = (const int*)  d_in[0];
  const float* emb     = (const float*)d_in[1];
  const float* Wq      = (const float*)d_in[2];
  const float* bq      = (const float*)d_in[3];
  const float* Wk      = (const float*)d_in[4];
  const float* bk      = (const float*)d_in[5];
  const float* Wv      = (const float*)d_in[6];
  const float* bv      = (const float*)d_in[7];
  const float* Wo      = (const float*)d_in[8];
  const float* bo      = (const float*)d_in[9];
  const float* layer_w = (const float*)d_in[10];
  const float* Wsnn    = (const float*)d_in[11];
  const float* bsnn    = (const float*)d_in[12];
  const float* W1      = (const float*)d_in[13];
  const float* b1      = (const float*)d_in[14];
  const float* W2      = (const float*)d_in[15];
  const float* b2      = (const float*)d_in[16];
  const float* g1      = (const float*)d_in[17];
  const float* be1     = (const float*)d_in[18];
  const float* g2      = (const float*)d_in[19];
  const float* be2     = (const float*)d_in[20];
  const float* Wout    = (const float*)d_in[21];
  const float* bout    = (const float*)d_in[22];
  float* out = (float*)d_out;

  static bool s_init = false;
  static float *pLB, *pK, *pV, *pQ, *pSC, *pOB, *pATT, *pXA, *pCUR,
               *pFFH, *pFFO;
  static bf16 *pALB, *pATMP, *pQI, *pKI, *pVI, *pPI, *pWI;
  if (!s_init) {
    cudaGetSymbolAddress((void**)&pLB,   g_LB);
    cudaGetSymbolAddress((void**)&pK,    g_k);
    cudaGetSymbolAddress((void**)&pV,    g_v);
    cudaGetSymbolAddress((void**)&pQ,    g_q);
    cudaGetSymbolAddress((void**)&pSC,   g_sc);
    cudaGetSymbolAddress((void**)&pOB,   g_ob);
    cudaGetSymbolAddress((void**)&pATT,  g_att);
    cudaGetSymbolAddress((void**)&pXA,   g_xa);
    cudaGetSymbolAddress((void**)&pCUR,  g_cur);
    cudaGetSymbolAddress((void**)&pFFH,  g_ffh);
    cudaGetSymbolAddress((void**)&pFFO,  g_ffo);
    cudaGetSymbolAddress((void**)&pALB,  g_aLB);
    cudaGetSymbolAddress((void**)&pATMP, g_atmp);
    cudaGetSymbolAddress((void**)&pQI,   g_qi);
    cudaGetSymbolAddress((void**)&pKI,   g_ki);
    cudaGetSymbolAddress((void**)&pVI,   g_vi);
    cudaGetSymbolAddress((void**)&pPI,   g_pi);
    cudaGetSymbolAddress((void**)&pWI,   g_wimg);
    cudaFuncSetAttribute(k_hmma<2>,  cudaFuncAttributeMaxDynamicSharedMemorySize, HM_SMEM);
    cudaFuncSetAttribute(k_hmma<1>,  cudaFuncAttributeMaxDynamicSharedMemorySize, HM_SMEM);
    cudaFuncSetAttribute(k_hmma_sc,  cudaFuncAttributeMaxDynamicSharedMemorySize, HM_SMEM);
    cudaFuncSetAttribute(k_hmma_pv,  cudaFuncAttributeMaxDynamicSharedMemorySize, HM_SMEM);
    s_init = true;
  }

  // ---- pre-split all weights (batched over layers) ----
  k_splitB2b<<<dim3(CD / 128, CD / 64, CL), 256>>>(Wq, pWI + 0 * CL * W_CDCD,
      CD, CD, CD, (size_t)CD * CD, W_CDCD);
  k_splitB2b<<<dim3(CD / 128, CD / 64, CL), 256>>>(Wk, pWI + 1 * CL * W_CDCD,
      CD, CD, CD, (size_t)CD * CD, W_CDCD);
  k_splitB2b<<<dim3(CD / 128, CD / 64, CL), 256>>>(Wv, pWI + 2 * CL * W_CDCD,
      CD, CD, CD, (size_t)CD * CD, W_CDCD);
  k_splitB2b<<<dim3(CD / 128, CD / 64, CL), 256>>>(Wo, pWI + 3 * CL * W_CDCD,
      CD, CD, CD, (size_t)CD * CD, W_CDCD);
  k_splitB2b<<<dim3(CFF / 128, CD / 64, CL), 256>>>(W1, pWI + W_BASE1,
      CFF, CFF, CD, (size_t)CD * CFF, W_FFSZ);
  k_splitB2b<<<dim3(CD / 128, CFF / 64, CL), 256>>>(W2, pWI + W_BASE2,
      CD, CD, CFF, (size_t)CFF * CD, W_FFSZ);
  k_splitB2b<<<dim3(CVP / 128, CD / 64, 1), 256>>>(Wout, pWI + W_BASEO,
      CV, CVP, CD, 0, 0);
  k_splitB2b<<<dim3(CD / 128, CD / 64, CL), 256>>>(Wsnn, pWI + W_BASES,
      CD, CD, CD, (size_t)CD * CD, W_CDCD);

  auto hgemm = [&](const bf16* Aimg, int Mimg, const bf16* Wimg,
                   const float* bias, float* C,
                   int M, int Nact, int Npad, int K,
                   int ks, int relu, int perm, int aspl,
                   bf16* himg = nullptr, size_t hplane = 0) {
    int chunks = K >> 5;
    if (ks > 1) {
      int t4 = (M * Nact) >> 2;
      k_fill<<<(t4 + 255) / 256, 256>>>(C, bias, Nact >> 2, t4);
      if (aspl == 1)
        k_hmma<1><<<dim3(Npad / 128, M / 128, ks), 256, HM_SMEM>>>(
            Aimg, Wimg, nullptr, C, Mimg, Nact, Npad, K, chunks / ks, Nact, 0, 0, 1,
            nullptr, 0);
      else
        k_hmma<2><<<dim3(Npad / 128, M / 128, ks), 256, HM_SMEM>>>(
            Aimg, Wimg, nullptr, C, Mimg, Nact, Npad, K, chunks / ks, Nact, 0, 0, 1,
            nullptr, 0);
    } else {
      if (aspl == 1)
        k_hmma<1><<<dim3(Npad / 128, M / 128, 1), 256, HM_SMEM>>>(
            Aimg, Wimg, bias, C, Mimg, Nact, Npad, K, chunks, Nact, relu, perm, 0,
            himg, hplane);
      else
        k_hmma<2><<<dim3(Npad / 128, M / 128, 1), 256, HM_SMEM>>>(
            Aimg, Wimg, bias, C, Mimg, Nact, Npad, K, chunks, Nact, relu, perm, 0,
            himg, hplane);
    }
  };
  const int MIMG_LB = (CL + 1) * CT;

  k_embed<<<CT, 256>>>(src, emb, pLB);
  k_splitA2<<<(CT * CD / 2 + 255) / 256, 256>>>(pLB, pALB, CD, CT * CD / 2, 0, PLANE_LB);

  for (int l = 0; l < CL; l++) {
    int n = l + 1;

    hgemm(pALB, MIMG_LB, pWI + (0 * CL + l) * W_CDCD, bq + (size_t)l * CD, pQ,
          CT, CD, CD, CD, 8, 0, 0, 2);
    k_splitHead<<<(16 * 16384) / 256, 256>>>(pQ, pQI, QPLANE, 16 * 16384);

    if (n >= 8) {
      // K projection with fused head-layout split epilogue (ks=1)
      hgemm(pALB, MIMG_LB, pWI + (1 * CL + l) * W_CDCD, bk + (size_t)l * CD, pK,
            n * CT, CD, CD, CD, 1, 0, 0, 2, pKI, KPLANE);
    } else {
      int ksv = (n == 1) ? 8 : (n == 2) ? 4 : 2;
      hgemm(pALB, MIMG_LB, pWI + (1 * CL + l) * W_CDCD, bk + (size_t)l * CD, pK,
            n * CT, CD, CD, CD, ksv, 0, 0, 2);
      k_splitHead<<<(n * 16 * 16384) / 256, 256>>>(pK, pKI, KPLANE, n * 16 * 16384);
    }
    {
      int ksv = (n == 1) ? 8 : (n == 2) ? 4 : (n <= 7) ? 2 : 1;
      hgemm(pALB, MIMG_LB, pWI + (2 * CL + l) * W_CDCD, bv + (size_t)l * CD, pV,
            n * CT, CD, CD, CD, ksv, 0, 0, 2);
    }
    k_splitVT<<<dim3(n * 16, 4), 256>>>(pV, pVI, KPLANE);

    k_hmma_sc<<<dim3(2, 2, n * 16), 256, HM_SMEM>>>(pQI, pKI, pSC);
    k_softmax<<<n * 16 * CS, 256>>>(pSC, pPI, PPLANE);
    k_hmma_pv<<<dim3(1, 2, n * 16), 256, HM_SMEM>>>(pPI, pVI, pOB);
    k_combine<<<(CT * CD) / 256, 256>>>(pOB, layer_w + (size_t)l * (CL + 1), n,
                                        pATMP, PLANE_CD);

    hgemm(pATMP, 512, pWI + (3 * CL + l) * W_CDCD, bo + (size_t)l * CD, pATT,
          CT, CD, CD, CD, 8, 0, 0, 2);
    // LN1: xa float + xa split image (for SNN projection)
    k_addln<<<CT, 256>>>(pLB, pATT, g1 + (size_t)l * CD, be1 + (size_t)l * CD,
                         pXA, nullptr, pATMP, PLANE_CD, 0, -1);

    // SNN current projection via HMMA
    hgemm(pATMP, 512, pWI + W_BASES + (size_t)l * W_CDCD, bsnn + (size_t)l * CD, pCUR,
          CT, CD, CD, CD, 8, 0, 0, 2);
    k_snn<<<CB, 1024>>>(pCUR, pATMP, PLANE_CD);

    hgemm(pATMP, 512, pWI + W_BASE1 + (size_t)l * W_FFSZ, b1 + (size_t)l * CFF, pFFH,
          CT, CFF, CFF, CD, 4, 1, 0, 1);
    k_relusplit<<<(CT * CFF / 2 + 255) / 256, 256>>>(pFFH, pATMP, CFF, CT * CFF / 2,
                                                     PLANE_TMP);
    hgemm(pATMP, 512, pWI + W_BASE2 + (size_t)l * W_FFSZ, b2 + (size_t)l * CD, pFFO,
          CT, CD, CD, CFF, 8, 0, 0, 2);

    // LN2: x -> slot0 float + archive float + both split-image slots
    k_addln<<<CT, 256>>>(pXA, pFFO, g2 + (size_t)l * CD, be2 + (size_t)l * CD,
                         pLB, pLB + (size_t)(l + 1) * CT * CD,
                         pALB, PLANE_LB, 0, (l + 1) * CT);
  }

  // logits = x @ Wout + bout -> [B,S,V] (perm)
  hgemm(pALB, MIMG_LB, pWI + W_BASEO, bout, out, CT, CV, CVP, CD, 1, 0, 1, 2);
}

// round 17
// speedup vs baseline: 3.2913x; 1.1508x over previous
#include <cuda_runtime.h>
#include <cuda_bf16.h>
#include <math.h>
#include <stdint.h>
#include <stddef.h>

typedef unsigned long long ull;
typedef __nv_bfloat16 bf16;

// ---------------- problem constants ----------------
constexpr int CB  = 2;
constexpr int CS  = 256;
constexpr int CD  = 1024;
constexpr int CH  = 8;
constexpr int CHD = 128;
constexpr int CL  = 16;
constexpr int CFF = 2048;
constexpr int CV  = 50257;
constexpr int CVP = 50304;
constexpr int CT  = CS * CB;   // 512 tokens, row r = s*CB + b
constexpr float ATT_SCALE = 0.08838834764831845f;
constexpr int HM_SMEM = 2 * 40960;   // double-buffered A2+B2 tiles (80KB)

// weight-image layout (bf16 elements)
constexpr size_t W_CDCD   = (size_t)2 * CD * CD;
constexpr size_t W_BASE1  = (size_t)64 * W_CDCD;
constexpr size_t W_FFSZ   = (size_t)2 * CFF * CD;
constexpr size_t W_BASE2  = W_BASE1 + (size_t)CL * W_FFSZ;
constexpr size_t W_BASEO  = W_BASE2 + (size_t)CL * W_FFSZ;
constexpr size_t W_BASES  = W_BASEO + (size_t)2 * CVP * CD;   // Wsnn images
constexpr size_t W_BASEKV = W_BASES + (size_t)CL * W_CDCD;    // fused K|V images
constexpr size_t W_KVSZ   = (size_t)2 * 2048 * CD;            // per-layer KV image
constexpr size_t W_TOTAL  = W_BASEKV + (size_t)CL * W_KVSZ;

// activation image planes
constexpr size_t PLANE_LB  = (size_t)(CL + 1) * CT * CD;
constexpr size_t PLANE_TMP = (size_t)512 * 2048;
constexpr size_t PLANE_CD  = (size_t)512 * CD;
constexpr size_t QPLANE    = (size_t)16 * CS * CHD;
constexpr size_t KPLANE    = (size_t)CL * 16 * CS * CHD;
constexpr size_t PPLANE    = (size_t)CL * 16 * CS * CS;

// ---------------- static device scratch ----------------
__device__ __align__(16) float g_LB[(size_t)(CL + 1) * CT * CD];
__device__ __align__(16) float g_kv[(size_t)CL * CT * 2048];   // packed K|V float
__device__ __align__(16) float g_q [CT * CD];
__device__ __align__(16) float g_sc[(size_t)CL * 16 * CS * CS];
__device__ __align__(16) float g_ob[(size_t)CL * 16 * CS * CHD];
__device__ __align__(16) float g_att [CT * CD];
__device__ __align__(16) float g_xa  [CT * CD];
__device__ __align__(16) float g_cur [CT * CD];
__device__ __align__(16) float g_ffh [CT * CFF];
__device__ __align__(16) float g_ffo [CT * CD];
__device__ __align__(16) float g_bkv[CL * 2048];               // concat bk|bv
// bf16 hi/lo split images (16B-aligned for cp.async)
__device__ __align__(16) bf16 g_aLB [2 * PLANE_LB];
__device__ __align__(16) bf16 g_atmp[2 * PLANE_TMP];
__device__ __align__(16) bf16 g_qi  [2 * QPLANE];
__device__ __align__(16) bf16 g_ki  [2 * KPLANE];
__device__ __align__(16) bf16 g_vi  [2 * KPLANE];
__device__ __align__(16) bf16 g_pi  [2 * PPLANE];
__device__ __align__(16) bf16 g_wimg[W_TOTAL];

// ---------------- helpers ----------------
__device__ __forceinline__ uint32_t smem_u32(const void* p) {
  uint32_t a;
  asm("{ .reg .u64 t; cvta.to.shared.u64 t, %1; cvt.u32.u64 %0, t; }" : "=r"(a) : "l"(p));
  return a;
}
__device__ __forceinline__ uint32_t pkbf(float x0, float x1, float& r0, float& r1) {
  bf16 b0 = __float2bfloat16(x0), b1 = __float2bfloat16(x1);
  uint32_t pk;
  asm("mov.b32 %0,{%1,%2};" : "=r"(pk)
      : "h"(*(unsigned short*)&b0), "h"(*(unsigned short*)&b1));
  r0 = x0 - __bfloat162float(b0);
  r1 = x1 - __bfloat162float(b1);
  return pk;
}

#define LDMX4(r, a) \
  asm volatile("ldmatrix.sync.aligned.m8n8.x4.shared.b16 {%0,%1,%2,%3}, [%4];" \
    : "=r"((r)[0]), "=r"((r)[1]), "=r"((r)[2]), "=r"((r)[3]) : "r"(a))

__device__ __forceinline__ void mma16816(float* c, const uint32_t* a, const uint32_t* b) {
  asm volatile("mma.sync.aligned.m16n8k16.row.col.f32.bf16.bf16.f32 "
    "{%0,%1,%2,%3}, {%4,%5,%6,%7}, {%8,%9}, {%0,%1,%2,%3};"
    : "+f"(c[0]), "+f"(c[1]), "+f"(c[2]), "+f"(c[3])
    : "r"(a[0]), "r"(a[1]), "r"(a[2]), "r"(a[3]), "r"(b[0]), "r"(b[1]));
}

// =======================================================================
// split-image builders
// =======================================================================
__global__ void k_splitA2(const float* __restrict__ A, bf16* __restrict__ img,
                          int K, int pairs, int rowOff, size_t plane)
{
  int idx = blockIdx.x * 256 + threadIdx.x;
  if (idx >= pairs) return;
  int kh = K >> 1;
  int m = idx / kh, kp = idx - m * kh;
  int k = kp * 2;
  float2 v = *(const float2*)(A + (size_t)m * K + k);
  float r0, r1, d0, d1;
  uint32_t hp = pkbf(v.x, v.y, r0, r1);
  uint32_t lp = pkbf(r0, r1, d0, d1);
  size_t off = (size_t)(rowOff + m) * K + k;
  *(uint32_t*)(img + off) = hp;
  *(uint32_t*)(img + plane + off) = lp;
}

__global__ void k_relusplit(const float* __restrict__ A, bf16* __restrict__ img,
                            int K, int pairs, size_t plane)
{
  int idx = blockIdx.x * 256 + threadIdx.x;
  if (idx >= pairs) return;
  int kh = K >> 1;
  int m = idx / kh, kp = idx - m * kh;
  int k = kp * 2;
  float2 v = *(const float2*)(A + (size_t)m * K + k);
  v.x = fmaxf(v.x, 0.f); v.y = fmaxf(v.y, 0.f);
  float r0, r1, d0, d1;
  uint32_t hp = pkbf(v.x, v.y, r0, r1);
  uint32_t lp = pkbf(r0, r1, d0, d1);
  size_t off = (size_t)m * K + k;
  *(uint32_t*)(img + off) = hp;
  *(uint32_t*)(img + plane + off) = lp;
}

// W [K][N] row-major -> image [rowOff + n][k] per split plane, batched over z.
__global__ void k_splitB2b(const float* __restrict__ W0, bf16* __restrict__ img0,
                           int N, int Npad, int K, size_t wstride, size_t istride,
                           int rowOff)
{
  __shared__ float sT[64][129];
  const float* W = W0 + (size_t)blockIdx.z * wstride;
  bf16* img = img0 + (size_t)blockIdx.z * istride;
  int t = threadIdx.x;
  int n0 = blockIdx.x * 128, k0 = blockIdx.y * 64;
  size_t planeB = (size_t)Npad * K;
  for (int i = t; i < 64 * 128; i += 256) {
    int kk = i >> 7, nn = i & 127;
    int n = n0 + nn;
    sT[kk][nn] = (n < N) ? W[(size_t)(k0 + kk) * N + n] : 0.f;
  }
  __syncthreads();
  for (int i = t; i < 128 * 32; i += 256) {
    int r = i >> 5, kp = i & 31;
    float r0, r1, d0, d1;
    uint32_t hp = pkbf(sT[2 * kp][r], sT[2 * kp + 1][r], r0, r1);
    uint32_t lp = pkbf(r0, r1, d0, d1);
    size_t off = (size_t)(rowOff + n0 + r) * K + k0 + 2 * kp;
    *(uint32_t*)(img + off) = hp;
    *(uint32_t*)(img + planeB + off) = lp;
  }
}

// per-head reorder+split: in[(slot*CT)+(s*CB+b)][colOff + h*CHD+hd] -> out[z][s][hd]
__global__ void k_splitHead(const float* __restrict__ in, int ld, int colOff,
                            bf16* __restrict__ out, size_t plane, int total)
{
  int idx = blockIdx.x * 256 + threadIdx.x;
  if (idx >= total) return;
  int z2 = idx >> 14;
  int rem = idx & 16383;
  int s = rem >> 6, hd = (rem & 63) * 2;
  int slot = z2 >> 4, bh = z2 & 15, b = bh >> 3, h = bh & 7;
  float2 v = *(const float2*)(in + ((size_t)(slot * CT + s * CB + b)) * ld
                              + colOff + h * CHD + hd);
  float r0, r1, d0, d1;
  uint32_t hp = pkbf(v.x, v.y, r0, r1);
  uint32_t lp = pkbf(r0, r1, d0, d1);
  size_t off = (size_t)z2 * (CS * CHD) + (size_t)s * CHD + hd;
  *(uint32_t*)(out + off) = hp;
  *(uint32_t*)(out + plane + off) = lp;
}

// V transpose+split: -> out[z][hd][s]
__global__ void k_splitVT(const float* __restrict__ in, int ld, int colOff,
                          bf16* __restrict__ out, size_t plane)
{
  __shared__ float sT[64][129];
  int t = threadIdx.x;
  int z2 = blockIdx.x, s0 = blockIdx.y * 64;
  int slot = z2 >> 4, bh = z2 & 15, b = bh >> 3, h = bh & 7;
  for (int i = t; i < 64 * 128; i += 256) {
    int sl = i >> 7, hd = i & 127;
    sT[sl][hd] = in[((size_t)(slot * CT + (s0 + sl) * CB + b)) * ld
                    + colOff + h * CHD + hd];
  }
  __syncthreads();
  for (int i = t; i < 128 * 32; i += 256) {
    int hd = i >> 5, sp = i & 31, sl = sp * 2;
    float r0, r1, d0, d1;
    uint32_t hp = pkbf(sT[sl][hd], sT[sl + 1][hd], r0, r1);
    uint32_t lp = pkbf(r0, r1, d0, d1);
    size_t off = (size_t)z2 * (CHD * CS) + (size_t)hd * CS + s0 + sl;
    *(uint32_t*)(out + off) = hp;
    *(uint32_t*)(out + plane + off) = lp;
  }
}

// =======================================================================
// HMMA bf16-split mainloop (shared by all HMMA kernels).
// =======================================================================
template<int ASPL>
__device__ __forceinline__ void hmma_loop(
    const bf16* __restrict__ Aimg, const bf16* __restrict__ Bimg,
    size_t planeA, size_t planeB, int K,
    int m0, int n0, int ck0, int nck, float (&acc)[4][4][4])
{
  extern __shared__ char sm[];
  const int t = threadIdx.x, l = t & 31, wid = t >> 5;
  const int wm = wid >> 2, wn = wid & 3;
  uint32_t sbase = smem_u32(sm);

  auto load_chunk = [&](int buf, int ck) {
    int kc = ck * 32;
#pragma unroll
    for (int j = 0; j < 8; j++) {
      int cid = t + j * 256;
      int mat = cid >> 10;
      int s   = (cid >> 9) & 1;
      int row = (cid >> 2) & 127;
      int c16 = cid & 3;
      const bf16* src = (mat == 0)
        ? Aimg + (size_t)s * planeA + (size_t)(m0 + row) * K + kc + c16 * 8
        : Bimg + (size_t)s * planeB + (size_t)(n0 + row) * K + kc + c16 * 8;
      uint32_t dst = sbase + buf * 40960 + mat * 20480 + s * 10240 + row * 80 + c16 * 16;
      asm volatile("cp.async.cg.shared.global [%0], [%1], 16;" :: "r"(dst), "l"(src));
    }
    asm volatile("cp.async.commit_group;" ::: "memory");
  };

  load_chunk(0, ck0);
  const int krow = l & 15, khalf = l >> 4;

  for (int ic = 0; ic < nck; ic++) {
    int buf = ic & 1;
    if (ic + 1 < nck) {
      load_chunk(buf ^ 1, ck0 + ic + 1);
      asm volatile("cp.async.wait_group 1;" ::: "memory");
    } else {
      asm volatile("cp.async.wait_group 0;" ::: "memory");
    }
    __syncthreads();

    uint32_t abase = sbase + buf * 40960;
    uint32_t bbase = abase + 20480;
#pragma unroll
    for (int ks = 0; ks < 2; ks++) {
      uint32_t koff = (uint32_t)(ks * 16 + khalf * 8) * 2;
      uint32_t af[ASPL][4][4];
#pragma unroll
      for (int s = 0; s < ASPL; s++)
#pragma unroll
        for (int mt = 0; mt < 4; mt++) {
          uint32_t addr = abase + s * 10240 + (uint32_t)(wm * 64 + mt * 16 + krow) * 80 + koff;
          LDMX4(af[s][mt], addr);
        }
#pragma unroll
      for (int sb = 0; sb < 2; sb++) {
        uint32_t bfr[4][2];
#pragma unroll
        for (int nt = 0; nt < 2; nt++) {
          uint32_t r[4];
          uint32_t addr = bbase + sb * 10240 + (uint32_t)(wn * 32 + nt * 16 + krow) * 80 + koff;
          LDMX4(r, addr);
          bfr[2 * nt][0]     = r[0]; bfr[2 * nt][1]     = r[2];
          bfr[2 * nt + 1][0] = r[1]; bfr[2 * nt + 1][1] = r[3];
        }
#pragma unroll
        for (int sa = 0; sa < ASPL; sa++) {
          if (sa + sb > 1) continue;
#pragma unroll
          for (int mt = 0; mt < 4; mt++)
#pragma unroll
            for (int g = 0; g < 4; g++)
              mma16816(acc[mt][g], af[sa][mt], bfr[g]);
        }
      }
    }
    __syncthreads();
  }
}

// generic projection GEMM (bias/relu/perm/atomic epilogue)
template<int ASPL>
__global__ void __launch_bounds__(256, 2) k_hmma(
    const bf16* __restrict__ Aimg, const bf16* __restrict__ Bimg,
    const float* __restrict__ bias, float* __restrict__ C,
    int Mimg, int N, int Npad, int K, int nck, int ldc,
    int relu, int perm, int atomic)
{
  float acc[4][4][4];
#pragma unroll
  for (int a = 0; a < 4; a++)
#pragma unroll
    for (int b = 0; b < 4; b++)
#pragma unroll
      for (int c = 0; c < 4; c++) acc[a][b][c] = 0.f;

  const int m0 = blockIdx.y * 128, n0 = blockIdx.x * 128;
  hmma_loop<ASPL>(Aimg, Bimg, (size_t)Mimg * K, (size_t)Npad * K, K,
                  m0, n0, blockIdx.z * nck, nck, acc);

  const int t = threadIdx.x, l = t & 31, wid = t >> 5;
  const int wm = wid >> 2, wn = wid & 3;
  const int gid = l >> 2, q = l & 3;
#pragma unroll
  for (int mt = 0; mt < 4; mt++) {
#pragma unroll
    for (int g = 0; g < 4; g++) {
      int mr = m0 + wm * 64 + mt * 16 + gid;
      int nc = n0 + wn * 32 + g * 8 + q * 2;
      const float* a = acc[mt][g];
#pragma unroll
      for (int h = 0; h < 2; h++) {
        int m = mr + h * 8;
        float v0 = a[2 * h + 0], v1 = a[2 * h + 1];
        int crow = perm ? ((m & 1) * CS + (m >> 1)) : m;
        float* cp = C + (size_t)crow * ldc;
        if (atomic) {
          if (nc < N)     atomicAdd(cp + nc, v0);
          if (nc + 1 < N) atomicAdd(cp + nc + 1, v1);
        } else {
          if (nc < N)     { float x = v0 + bias[nc];     if (relu) x = fmaxf(x, 0.f); cp[nc] = x; }
          if (nc + 1 < N) { float x = v1 + bias[nc + 1]; if (relu) x = fmaxf(x, 0.f); cp[nc + 1] = x; }
        }
      }
    }
  }
}

// scores: C[z][q][k] = SCALE * sum_hd Q[bh][q][hd]*K[z][k][hd]
__global__ void __launch_bounds__(256, 2) k_hmma_sc(
    const bf16* __restrict__ qi, const bf16* __restrict__ ki, float* __restrict__ sc)
{
  int z = blockIdx.z, bh = z & 15;
  float acc[4][4][4];
#pragma unroll
  for (int a = 0; a < 4; a++)
#pragma unroll
    for (int b = 0; b < 4; b++)
#pragma unroll
      for (int c = 0; c < 4; c++) acc[a][b][c] = 0.f;

  const int m0 = blockIdx.y * 128, n0 = blockIdx.x * 128;
  hmma_loop<2>(qi + (size_t)bh * (CS * CHD), ki + (size_t)z * (CS * CHD),
               QPLANE, KPLANE, CHD, m0, n0, 0, 4, acc);

  const int t = threadIdx.x, l = t & 31, wid = t >> 5;
  const int wm = wid >> 2, wn = wid & 3;
  const int gid = l >> 2, q4 = l & 3;
  float* C = sc + (size_t)z * (CS * CS);
#pragma unroll
  for (int mt = 0; mt < 4; mt++)
#pragma unroll
    for (int g = 0; g < 4; g++) {
      int mr = m0 + wm * 64 + mt * 16 + gid;
      int nc = n0 + wn * 32 + g * 8 + q4 * 2;
      const float* a = acc[mt][g];
#pragma unroll
      for (int h = 0; h < 2; h++) {
        int m = mr + h * 8;
        C[(size_t)m * CS + nc]     = a[2 * h + 0] * ATT_SCALE;
        C[(size_t)m * CS + nc + 1] = a[2 * h + 1] * ATT_SCALE;
      }
    }
}

// PV: ob[z][q][hd] = sum_k P[z][q][k]*V[z][k][hd]   (vi is [z][hd][k])
__global__ void __launch_bounds__(256, 2) k_hmma_pv(
    const bf16* __restrict__ pi, const bf16* __restrict__ vi, float* __restrict__ ob)
{
  int z = blockIdx.z;
  float acc[4][4][4];
#pragma unroll
  for (int a = 0; a < 4; a++)
#pragma unroll
    for (int b = 0; b < 4; b++)
#pragma unroll
      for (int c = 0; c < 4; c++) acc[a][b][c] = 0.f;

  const int m0 = blockIdx.y * 128;
  hmma_loop<2>(pi + (size_t)z * (CS * CS), vi + (size_t)z * (CHD * CS),
               PPLANE, KPLANE, CS, m0, 0, 0, 8, acc);

  const int t = threadIdx.x, l = t & 31, wid = t >> 5;
  const int wm = wid >> 2, wn = wid & 3;
  const int gid = l >> 2, q4 = l & 3;
  float* C = ob + (size_t)z * (CS * CHD);
#pragma unroll
  for (int mt = 0; mt < 4; mt++)
#pragma unroll
    for (int g = 0; g < 4; g++) {
      int mr = m0 + wm * 64 + mt * 16 + gid;
      int nc = wn * 32 + g * 8 + q4 * 2;
      const float* a = acc[mt][g];
#pragma unroll
      for (int h = 0; h < 2; h++) {
        int m = mr + h * 8;
        C[(size_t)m * CHD + nc]     = a[2 * h + 0];
        C[(size_t)m * CHD + nc + 1] = a[2 * h + 1];
      }
    }
}

// ---------------- small helper kernels ----------------
struct FillSeg { float* dst; const float* bias; int n4; int ncols4; };
struct Fill6 { FillSeg s[6]; };
__global__ void k_fillmulti(Fill6 f) {
  int i = blockIdx.x * 256 + threadIdx.x;
#pragma unroll
  for (int j = 0; j < 6; j++) {
    int n4 = f.s[j].n4;
    if (i < n4) {
      ((float4*)f.s[j].dst)[i] = ((const float4*)f.s[j].bias)[i % f.s[j].ncols4];
      return;
    }
    i -= n4;
  }
}

__global__ void k_catbias(const float* __restrict__ bk, const float* __restrict__ bv,
                          float* __restrict__ bkv) {
  int l = blockIdx.x;
  for (int c = threadIdx.x; c < 2048; c += 256)
    bkv[l * 2048 + c] = (c < 1024) ? bk[l * 1024 + c] : bv[l * 1024 + c - 1024];
}

// warp-per-row softmax (8 rows / 256-thread block); emits split P image
__global__ void k_softmax8(const float* __restrict__ sc, bf16* __restrict__ pi,
                           size_t plane) {
  int wid = threadIdx.x >> 5, lane = threadIdx.x & 31;
  size_t row = (size_t)blockIdx.x * 8 + wid;
  const float* r = sc + row * CS;
  float4 a = ((const float4*)r)[lane];
  float4 b = ((const float4*)r)[lane + 32];
  float m = fmaxf(fmaxf(fmaxf(a.x, a.y), fmaxf(a.z, a.w)),
                  fmaxf(fmaxf(b.x, b.y), fmaxf(b.z, b.w)));
#pragma unroll
  for (int o = 16; o > 0; o >>= 1) m = fmaxf(m, __shfl_xor_sync(~0u, m, o));
  a.x = expf(a.x - m); a.y = expf(a.y - m); a.z = expf(a.z - m); a.w = expf(a.w - m);
  b.x = expf(b.x - m); b.y = expf(b.y - m); b.z = expf(b.z - m); b.w = expf(b.w - m);
  float s = a.x + a.y + a.z + a.w + b.x + b.y + b.z + b.w;
#pragma unroll
  for (int o = 16; o > 0; o >>= 1) s += __shfl_xor_sync(~0u, s, o);
  float inv = 1.f / s;
  a.x *= inv; a.y *= inv; a.z *= inv; a.w *= inv;
  b.x *= inv; b.y *= inv; b.z *= inv; b.w *= inv;
  float r0, r1, d0, d1;
  size_t off = row * CS + lane * 4;
  uint32_t h0 = pkbf(a.x, a.y, r0, r1);
  uint32_t l0 = pkbf(r0, r1, d0, d1);
  uint32_t h1 = pkbf(a.z, a.w, r0, r1);
  uint32_t l1 = pkbf(r0, r1, d0, d1);
  *(uint32_t*)(pi + off) = h0;
  *(uint32_t*)(pi + off + 2) = h1;
  *(uint32_t*)(pi + plane + off) = l0;
  *(uint32_t*)(pi + plane + off + 2) = l1;
  off += 128;
  h0 = pkbf(b.x, b.y, r0, r1);
  l0 = pkbf(r0, r1, d0, d1);
  h1 = pkbf(b.z, b.w, r0, r1);
  l1 = pkbf(r0, r1, d0, d1);
  *(uint32_t*)(pi + off) = h0;
  *(uint32_t*)(pi + off + 2) = h1;
  *(uint32_t*)(pi + plane + off) = l0;
  *(uint32_t*)(pi + plane + off + 2) = l1;
}

// combine with in-kernel layer-mix softmax; emits split image
__global__ void k_combine(const float* __restrict__ ob, const float* __restrict__ lw,
                          int n, bf16* __restrict__ out, size_t plane)
{
  float w[CL + 1];
  {
    float mx = -1e30f;
    for (int i = 0; i < n; i++) mx = fmaxf(mx, __ldg(lw + i));
    float ssum = 0.f;
    for (int i = 0; i < n; i++) { w[i] = expf(__ldg(lw + i) - mx); ssum += w[i]; }
    float inv = 1.f / ssum;
    for (int i = 0; i < n; i++) w[i] *= inv;
  }
  int idx = blockIdx.x * 256 + threadIdx.x;
  int r = idx >> 10, c = idx & 1023;
  int s = r >> 1, b = r & 1, h = c >> 7, hd = c & 127;
  float acc = 0.f;
  for (int slot = 0; slot < n; slot++)
    acc += w[slot] * ob[((size_t)(slot * 16 + b * 8 + h) * CS + s) * CHD + hd];
  bf16 hi = __float2bfloat16(acc);
  bf16 lo = __float2bfloat16(acc - __bfloat162float(hi));
  out[(size_t)r * CD + c] = hi;
  out[plane + (size_t)r * CD + c] = lo;
}

// residual add + LN; emits float out(s) and bf16 split image(s)
__global__ void k_addln(const float* __restrict__ x, const float* __restrict__ res,
                        const float* __restrict__ g, const float* __restrict__ be,
                        float* __restrict__ out0, float* __restrict__ out1,
                        bf16* __restrict__ img, size_t plane,
                        int rowOff0, int rowOff1)
{
  int r = blockIdx.x, t = threadIdx.x;
  const float4* xr = (const float4*)(x + (size_t)r * CD);
  const float4* rr = (const float4*)(res + (size_t)r * CD);
  float4 a = xr[t], b4 = rr[t];
  float v0 = a.x + b4.x, v1 = a.y + b4.y, v2 = a.z + b4.z, v3 = a.w + b4.w;

  __shared__ float red[8];
  float s = v0 + v1 + v2 + v3;
#pragma unroll
  for (int o = 16; o > 0; o >>= 1) s += __shfl_xor_sync(~0u, s, o);
  if ((t & 31) == 0) red[t >> 5] = s;
  __syncthreads();
  float tot = 0.f;
#pragma unroll
  for (int i = 0; i < 8; i++) tot += red[i];
  float mean = tot * (1.f / CD);

  float d0 = v0 - mean, d1 = v1 - mean, d2 = v2 - mean, d3 = v3 - mean;
  float sq = d0 * d0 + d1 * d1 + d2 * d2 + d3 * d3;
  __syncthreads();
#pragma unroll
  for (int o = 16; o > 0; o >>= 1) sq += __shfl_xor_sync(~0u, sq, o);
  if ((t & 31) == 0) red[t >> 5] = sq;
  __syncthreads();
  float vs = 0.f;
#pragma unroll
  for (int i = 0; i < 8; i++) vs += red[i];
  float rstd = rsqrtf(vs * (1.f / CD) + 1e-5f);

  float4 gg = ((const float4*)g)[t];
  float4 bb = ((const float4*)be)[t];
  float4 ov;
  ov.x = d0 * rstd * gg.x + bb.x;
  ov.y = d1 * rstd * gg.y + bb.y;
  ov.z = d2 * rstd * gg.z + bb.z;
  ov.w = d3 * rstd * gg.w + bb.w;
  ((float4*)(out0 + (size_t)r * CD))[t] = ov;
  if (out1) ((float4*)(out1 + (size_t)r * CD))[t] = ov;

  if (img) {
    float r0, r1, d0x, d1x;
    uint32_t hp0 = pkbf(ov.x, ov.y, r0, r1);
    uint32_t lp0 = pkbf(r0, r1, d0x, d1x);
    uint32_t hp1 = pkbf(ov.z, ov.w, r0, r1);
    uint32_t lp1 = pkbf(r0, r1, d0x, d1x);
    size_t off = (size_t)(rowOff0 + r) * CD + t * 4;
    *(uint32_t*)(img + off) = hp0;
    *(uint32_t*)(img + off + 2) = hp1;
    *(uint32_t*)(img + plane + off) = lp0;
    *(uint32_t*)(img + plane + off + 2) = lp1;
    if (rowOff1 >= 0) {
      size_t off1 = (size_t)(rowOff1 + r) * CD + t * 4;
      *(uint32_t*)(img + off1) = hp0;
      *(uint32_t*)(img + off1 + 2) = hp1;
      *(uint32_t*)(img + plane + off1) = lp0;
      *(uint32_t*)(img + plane + off1 + 2) = lp1;
    }
  }
}

__global__ void k_embed(const int* __restrict__ src, const float* __restrict__ emb,
                        float* __restrict__ x)
{
  int r = blockIdx.x, t = threadIdx.x;
  int s = r >> 1, b = r & 1;
  int tok = src[b * CS + s];
  const float* er = emb + (size_t)tok * CD;
  float* xr = x + (size_t)r * CD;
  const float SQ = 32.0f;
  const float cexp = -9.210340371976184f / (float)CD;
#pragma unroll
  for (int i = 0; i < 4; i++) {
    int d = t * 4 + i;
    int pair = d >> 1;
    float ang = (float)s * expf((float)(2 * pair) * cexp);
    float pe = (d & 1) ? cosf(ang) : sinf(ang);
    xr[d] = er[d] * SQ + pe;
  }
}

// SNN scan: one barrier/step via double-buffered warp partials; emits split image
__global__ void k_snn(const float* __restrict__ cur, bf16* __restrict__ spimg,
                      size_t plane) {
  int b = blockIdx.x, t = threadIdx.x, wid = t >> 5, lane = t & 31;
  __shared__ float red[2][32];
  const bf16 z16 = __float2bfloat16(0.f);
  float mem = 0.f, thr = 1.0f;
  for (int s = 0; s < CS; s++) {
    int buf = s & 1;
    float v = mem;
#pragma unroll
    for (int o = 16; o > 0; o >>= 1) v += __shfl_xor_sync(~0u, v, o);
    if (lane == 0) red[buf][wid] = v;
    __syncthreads();
    float w = red[buf][lane];
#pragma unroll
    for (int o = 16; o > 0; o >>= 1) w += __shfl_xor_sync(~0u, w, o);
    float c = cur[(size_t)(s * CB + b) * CD + t] - 0.1f * w;
    mem = 0.9f * mem + c;
    float spk = (mem >= thr) ? 1.f : 0.f;
    mem -= spk * thr;
    thr = 0.9f * thr + 0.1f * spk;
    size_t off = (size_t)(s * CB + b) * CD + t;
    spimg[off] = __float2bfloat16(spk);
    spimg[plane + off] = z16;
  }
}

// =======================================================================
extern "C" void kernel_launch(void* const* d_in, const int* in_sizes, int n_in,
                              void* d_out, int out_size)
{
  (void)in_sizes; (void)n_in; (void)out_size;
  const int*   src     = (const int*)  d_in[0];
  const float* emb     = (const float*)d_in[1];
  const float* Wq      = (const float*)d_in[2];
  const float* bq      = (const float*)d_in[3];
  const float* Wk      = (const float*)d_in[4];
  const float* bk      = (const float*)d_in[5];
  const float* Wv      = (const float*)d_in[6];
  const float* bv      = (const float*)d_in[7];
  const float* Wo      = (const float*)d_in[8];
  const float* bo      = (const float*)d_in[9];
  const float* layer_w = (const float*)d_in[10];
  const float* Wsnn    = (const float*)d_in[11];
  const float* bsnn    = (const float*)d_in[12];
  const float* W1      = (const float*)d_in[13];
  const float* b1      = (const float*)d_in[14];
  const float* W2      = (const float*)d_in[15];
  const float* b2      = (const float*)d_in[16];
  const float* g1      = (const float*)d_in[17];
  const float* be1     = (const float*)d_in[18];
  const float* g2      = (const float*)d_in[19];
  const float* be2     = (const float*)d_in[20];
  const float* Wout    = (const float*)d_in[21];
  const float* bout    = (const float*)d_in[22];
  float* out = (float*)d_out;

  static bool s_init = false;
  static float *pLB, *pKV, *pQ, *pSC, *pOB, *pATT, *pXA, *pCUR, *pFFH, *pFFO, *pBKV;
  static bf16 *pALB, *pATMP, *pQI, *pKI, *pVI, *pPI, *pWI;
  if (!s_init) {
    cudaGetSymbolAddress((void**)&pLB,   g_LB);
    cudaGetSymbolAddress((void**)&pKV,   g_kv);
    cudaGetSymbolAddress((void**)&pQ,    g_q);
    cudaGetSymbolAddress((void**)&pSC,   g_sc);
    cudaGetSymbolAddress((void**)&pOB,   g_ob);
    cudaGetSymbolAddress((void**)&pATT,  g_att);
    cudaGetSymbolAddress((void**)&pXA,   g_xa);
    cudaGetSymbolAddress((void**)&pCUR,  g_cur);
    cudaGetSymbolAddress((void**)&pFFH,  g_ffh);
    cudaGetSymbolAddress((void**)&pFFO,  g_ffo);
    cudaGetSymbolAddress((void**)&pBKV,  g_bkv);
    cudaGetSymbolAddress((void**)&pALB,  g_aLB);
    cudaGetSymbolAddress((void**)&pATMP, g_atmp);
    cudaGetSymbolAddress((void**)&pQI,   g_qi);
    cudaGetSymbolAddress((void**)&pKI,   g_ki);
    cudaGetSymbolAddress((void**)&pVI,   g_vi);
    cudaGetSymbolAddress((void**)&pPI,   g_pi);
    cudaGetSymbolAddress((void**)&pWI,   g_wimg);
    cudaFuncSetAttribute(k_hmma<2>,  cudaFuncAttributeMaxDynamicSharedMemorySize, HM_SMEM);
    cudaFuncSetAttribute(k_hmma<1>,  cudaFuncAttributeMaxDynamicSharedMemorySize, HM_SMEM);
    cudaFuncSetAttribute(k_hmma_sc,  cudaFuncAttributeMaxDynamicSharedMemorySize, HM_SMEM);
    cudaFuncSetAttribute(k_hmma_pv,  cudaFuncAttributeMaxDynamicSharedMemorySize, HM_SMEM);
    s_init = true;
  }

  // ---- pre-split all weights (batched over layers) ----
  k_splitB2b<<<dim3(CD / 128, CD / 64, CL), 256>>>(Wq, pWI + 0 * CL * W_CDCD,
      CD, CD, CD, (size_t)CD * CD, W_CDCD, 0);
  k_splitB2b<<<dim3(CD / 128, CD / 64, CL), 256>>>(Wo, pWI + 3 * CL * W_CDCD,
      CD, CD, CD, (size_t)CD * CD, W_CDCD, 0);
  k_splitB2b<<<dim3(CFF / 128, CD / 64, CL), 256>>>(W1, pWI + W_BASE1,
      CFF, CFF, CD, (size_t)CD * CFF, W_FFSZ, 0);
  k_splitB2b<<<dim3(CD / 128, CFF / 64, CL), 256>>>(W2, pWI + W_BASE2,
      CD, CD, CFF, (size_t)CFF * CD, W_FFSZ, 0);
  k_splitB2b<<<dim3(CVP / 128, CD / 64, 1), 256>>>(Wout, pWI + W_BASEO,
      CV, CVP, CD, 0, 0, 0);
  k_splitB2b<<<dim3(CD / 128, CD / 64, CL), 256>>>(Wsnn, pWI + W_BASES,
      CD, CD, CD, (size_t)CD * CD, W_CDCD, 0);
  // fused KV images: rows 0-1023 = Wk, rows 1024-2047 = Wv (Npad 2048)
  k_splitB2b<<<dim3(CD / 128, CD / 64, CL), 256>>>(Wk, pWI + W_BASEKV,
      CD, 2048, CD, (size_t)CD * CD, W_KVSZ, 0);
  k_splitB2b<<<dim3(CD / 128, CD / 64, CL), 256>>>(Wv, pWI + W_BASEKV,
      CD, 2048, CD, (size_t)CD * CD, W_KVSZ, 1024);
  k_catbias<<<CL, 256>>>(bk, bv, pBKV);

  auto hgemm = [&](const bf16* Aimg, int Mimg, const bf16* Wimg,
                   const float* bias, float* C,
                   int M, int Nact, int Npad, int K,
                   int ks, int relu, int perm, int aspl) {
    int chunks = K >> 5;
    if (aspl == 1)
      k_hmma<1><<<dim3(Npad / 128, M / 128, ks), 256, HM_SMEM>>>(
          Aimg, Wimg, bias, C, Mimg, Nact, Npad, K, chunks / ks, Nact,
          relu, perm, ks > 1);
    else
      k_hmma<2><<<dim3(Npad / 128, M / 128, ks), 256, HM_SMEM>>>(
          Aimg, Wimg, bias, C, Mimg, Nact, Npad, K, chunks / ks, Nact,
          relu, perm, ks > 1);
  };
  const int MIMG_LB = (CL + 1) * CT;

  k_embed<<<CT, 256>>>(src, emb, pLB);
  k_splitA2<<<(CT * CD / 2 + 255) / 256, 256>>>(pLB, pALB, CD, CT * CD / 2, 0, PLANE_LB);

  for (int l = 0; l < CL; l++) {
    int n = l + 1;
    int ksv = (n == 1) ? 4 : (n <= 3) ? 2 : 1;

    // one prefill launch for all split-K outputs of this layer
    {
      Fill6 f;
      f.s[0] = { pQ,   bq + (size_t)l * CD,   131072, 256 };
      f.s[1] = { pKV,  pBKV + l * 2048, (ksv > 1) ? n * 262144 : 0, 512 };
      f.s[2] = { pATT, bo + (size_t)l * CD,   131072, 256 };
      f.s[3] = { pCUR, bsnn + (size_t)l * CD, 131072, 256 };
      f.s[4] = { pFFH, b1 + (size_t)l * CFF,  262144, 512 };
      f.s[5] = { pFFO, b2 + (size_t)l * CD,   131072, 256 };
      int tot = 0;
      for (int j = 0; j < 6; j++) tot += f.s[j].n4;
      k_fillmulti<<<(tot + 255) / 256, 256>>>(f);
    }

    hgemm(pALB, MIMG_LB, pWI + (0 * CL + l) * W_CDCD, nullptr, pQ,
          CT, CD, CD, CD, 8, 0, 0, 2);
    k_splitHead<<<(16 * 16384) / 256, 256>>>(pQ, CD, 0, pQI, QPLANE, 16 * 16384);

    // fused K|V projection
    hgemm(pALB, MIMG_LB, pWI + W_BASEKV + (size_t)l * W_KVSZ,
          (ksv > 1) ? nullptr : (pBKV + l * 2048), pKV,
          n * CT, 2048, 2048, CD, ksv, 0, 0, 2);
    k_splitHead<<<(n * 16 * 16384) / 256, 256>>>(pKV, 2048, 0, pKI, KPLANE,
                                                 n * 16 * 16384);
    k_splitVT<<<dim3(n * 16, 4), 256>>>(pKV, 2048, 1024, pVI, KPLANE);

    k_hmma_sc<<<dim3(2, 2, n * 16), 256, HM_SMEM>>>(pQI, pKI, pSC);
    k_softmax8<<<n * 512, 256>>>(pSC, pPI, PPLANE);
    k_hmma_pv<<<dim3(1, 2, n * 16), 256, HM_SMEM>>>(pPI, pVI, pOB);
    k_combine<<<(CT * CD) / 256, 256>>>(pOB, layer_w + (size_t)l * (CL + 1), n,
                                        pATMP, PLANE_CD);

    hgemm(pATMP, 512, pWI + (3 * CL + l) * W_CDCD, nullptr, pATT,
          CT, CD, CD, CD, 8, 0, 0, 2);
    k_addln<<<CT, 256>>>(pLB, pATT, g1 + (size_t)l * CD, be1 + (size_t)l * CD,
                         pXA, nullptr, pATMP, PLANE_CD, 0, -1);

    hgemm(pATMP, 512, pWI + W_BASES + (size_t)l * W_CDCD, nullptr, pCUR,
          CT, CD, CD, CD, 8, 0, 0, 2);
    k_snn<<<CB, 1024>>>(pCUR, pATMP, PLANE_CD);

    hgemm(pATMP, 512, pWI + W_BASE1 + (size_t)l * W_FFSZ, nullptr, pFFH,
          CT, CFF, CFF, CD, 4, 0, 0, 1);
    k_relusplit<<<(CT * CFF / 2 + 255) / 256, 256>>>(pFFH, pATMP, CFF, CT * CFF / 2,
                                                     PLANE_TMP);
    hgemm(pATMP, 512, pWI + W_BASE2 + (size_t)l * W_FFSZ, nullptr, pFFO,
          CT, CD, CD, CFF, 8, 0, 0, 2);

    k_addln<<<CT, 256>>>(pXA, pFFO, g2 + (size_t)l * CD, be2 + (size_t)l * CD,
                         pLB, pLB + (size_t)(l + 1) * CT * CD,
                         pALB, PLANE_LB, 0, (l + 1) * CT);
  }

  // logits = x @ Wout + bout -> [B,S,V] (perm)
  hgemm(pALB, MIMG_LB, pWI + W_BASEO, bout, out, CT, CV, CVP, CD, 1, 0, 1, 2);
}